// round 10
// baseline (speedup 1.0000x reference)
#include <cuda_runtime.h>
#include <cuda_bf16.h>
#include <cstdint>

#define DD   48
#define HW   2304
#define DHW  110592
#define NK   512
#define LOG2E 1.4426950408889634f
#define NT   13824            // 24^3 Winograd tiles
#define NMU  64

// ---------------- device scratch ----------------
__device__ float d_xp[50 * 50 * 50 * 128];                          // padded input, voxel-major
__device__ __align__(16) __nv_bfloat16 d_wA[(size_t)NMU * NT * 256]; // transformed input [mu][tile][hi128|lo128]
__device__ __align__(16) __nv_bfloat16 d_wu[NMU * 128 * 384];        // transformed weights [mu][co][bhi|bhi|blo]
__device__ float d_V[(size_t)32 * NT * 128];                         // x-folded GEMM out [mzmy*2+xs][tile][co]
__device__ float d_y2[(size_t)DHW * 128];                            // conv out voxel-major [voxel][c]
__device__ __align__(16) __nv_bfloat16 d_fkb[16 * 12288];            // keypoint feats, pre-swizzled
__device__ float d_sp[432 * 256];
__device__ float d_mean[128];
__device__ float d_rstd[128];
__device__ float d_nn[NK];

__device__ __forceinline__ float exp2a(float x) {
    float r; asm("ex2.approx.ftz.f32 %0, %1;" : "=f"(r) : "f"(x)); return r;
}
__device__ __forceinline__ uint32_t smem_u32(const void* p) {
    uint32_t a;
    asm("{ .reg .u64 t; cvta.to.shared.u64 t, %1; cvt.u32.u64 %0, t; }" : "=r"(a) : "l"(p));
    return a;
}
__device__ __forceinline__ void cp16(uint32_t dst, const void* src) {
    asm volatile("cp.async.cg.shared.global [%0], [%1], 16;" :: "r"(dst), "l"(src));
}
__device__ __forceinline__ void cp_commit() { asm volatile("cp.async.commit_group;"); }
__device__ __forceinline__ void ldsm4(uint32_t addr, uint32_t& r0, uint32_t& r1, uint32_t& r2, uint32_t& r3) {
    asm volatile("ldmatrix.sync.aligned.m8n8.x4.shared.b16 {%0,%1,%2,%3}, [%4];"
                 : "=r"(r0), "=r"(r1), "=r"(r2), "=r"(r3) : "r"(addr));
}
__device__ __forceinline__ void mma16816(float* c, const uint32_t* a, uint32_t b0, uint32_t b1) {
    asm volatile("mma.sync.aligned.m16n8k16.row.col.f32.bf16.bf16.f32 "
                 "{%0,%1,%2,%3}, {%4,%5,%6,%7}, {%8,%9}, {%0,%1,%2,%3};"
                 : "+f"(c[0]), "+f"(c[1]), "+f"(c[2]), "+f"(c[3])
                 : "r"(a[0]), "r"(a[1]), "r"(a[2]), "r"(a[3]), "r"(b0), "r"(b1));
}

// ---------------- pad input to [zp50][yp50][xp50][c128] fp32, voxel-major ----------------
__global__ void __launch_bounds__(256) pad_kernel(const float* __restrict__ feats) {
    __shared__ float tb[50][129];
    const int r = blockIdx.x;               // 2500 (zp,yp) rows
    const int zp = r / 50, yp = r % 50;
    const int zi = zp - 1, yi = yp - 1;
    const int tid = threadIdx.x;
    const int x = tid & 63, cq = tid >> 6;
    const int xi = x - 1;
    const bool rowok = (zi >= 0 && zi < 48 && yi >= 0 && yi < 48);
    const bool xok = rowok && (xi >= 0 && xi < 48);
#pragma unroll 4
    for (int i = 0; i < 32; ++i) {
        int c = cq * 32 + i;
        float v = 0.f;
        if (xok) {
            if (c < 125)       v = feats[(size_t)c * DHW + zi * HW + yi * 48 + xi];
            else if (c == 125) v = (2.0f / 47.0f) * (float)xi - 1.0f;
            else if (c == 126) v = (2.0f / 47.0f) * (float)yi - 1.0f;
            else               v = (2.0f / 47.0f) * (float)zi - 1.0f;
        }
        if (x < 50) tb[x][c] = v;
    }
    __syncthreads();
    float* dst = d_xp + (size_t)r * 50 * 128;
    for (int i = tid; i < 1600; i += 256) {
        int xr = i >> 5, c4 = (i & 31) * 4;
        float4 val = make_float4(tb[xr][c4], tb[xr][c4 + 1], tb[xr][c4 + 2], tb[xr][c4 + 3]);
        *(float4*)(dst + xr * 128 + c4) = val;
    }
}

// ---------------- Winograd weight transform ----------------
__device__ __forceinline__ void grow(int m, float* g) {
    if (m == 0)      { g[0] = 1.f;  g[1] = 0.f;   g[2] = 0.f; }
    else if (m == 1) { g[0] = 0.5f; g[1] = 0.5f;  g[2] = 0.5f; }
    else if (m == 2) { g[0] = 0.5f; g[1] = -0.5f; g[2] = 0.5f; }
    else             { g[0] = 0.f;  g[1] = 0.f;   g[2] = 1.f; }
}
__global__ void __launch_bounds__(128) wino_w_kernel(const float* __restrict__ W0) {
    const int mu = blockIdx.x >> 7, co = blockIdx.x & 127, ci = threadIdx.x;
    const int mz = mu >> 4, my = (mu >> 2) & 3, mx = mu & 3;
    float gz[3], gy[3], gx[3];
    grow(mz, gz); grow(my, gy); grow(mx, gx);
    const float* w = W0 + (size_t)(co * 128 + ci) * 27;
    float u = 0.f;
#pragma unroll
    for (int dz = 0; dz < 3; ++dz)
#pragma unroll
        for (int dy = 0; dy < 3; ++dy)
#pragma unroll
            for (int dx = 0; dx < 3; ++dx)
                u = fmaf(gz[dz] * gy[dy] * gx[dx], __ldg(w + dz * 9 + dy * 3 + dx), u);
    __nv_bfloat16 hi = __float2bfloat16(u);
    __nv_bfloat16 lo = __float2bfloat16(u - __bfloat162float(hi));
    __nv_bfloat16* rrow = d_wu + ((size_t)mu * 128 + co) * 384;
    rrow[ci] = hi; rrow[128 + ci] = hi; rrow[256 + ci] = lo;
}

// ---------------- Winograd input transform: 4 x-tiles per block, sliding window ----------------
__global__ void __launch_bounds__(128) wino_in_kernel() {
    __shared__ __nv_bfloat16 s[NMU * 256];   // 32 KB staging
    const int blk = blockIdx.x;              // 3456 = 24*24*6
    const int c = threadIdx.x;
    const int xg = blk % 6, yt = (blk / 6) % 24, zt = blk / 144;
    const int xt0 = xg * 4;
    const float* base = d_xp + ((size_t)((zt * 2) * 50 + yt * 2) * 50 + xt0 * 2) * 128 + c;

    float w[4][4][4];
#pragma unroll
    for (int z = 0; z < 4; ++z)
#pragma unroll
        for (int y = 0; y < 4; ++y)
#pragma unroll
            for (int x = 0; x < 4; ++x)
                w[z][y][x] = __ldg(base + ((z * 50 + y) * 50 + x) * 128);

    for (int t = 0; t < 4; ++t) {
        float d[4][4][4];
#pragma unroll
        for (int z = 0; z < 4; ++z)
#pragma unroll
            for (int y = 0; y < 4; ++y)
#pragma unroll
                for (int x = 0; x < 4; ++x) d[z][y][x] = w[z][y][x];
        // x-pass
#pragma unroll
        for (int z = 0; z < 4; ++z)
#pragma unroll
            for (int y = 0; y < 4; ++y) {
                float a0 = d[z][y][0], a1 = d[z][y][1], a2 = d[z][y][2], a3 = d[z][y][3];
                d[z][y][0] = a0 - a2; d[z][y][1] = a1 + a2; d[z][y][2] = a2 - a1; d[z][y][3] = a1 - a3;
            }
        // y-pass
#pragma unroll
        for (int z = 0; z < 4; ++z)
#pragma unroll
            for (int x = 0; x < 4; ++x) {
                float a0 = d[z][0][x], a1 = d[z][1][x], a2 = d[z][2][x], a3 = d[z][3][x];
                d[z][0][x] = a0 - a2; d[z][1][x] = a1 + a2; d[z][2][x] = a2 - a1; d[z][3][x] = a1 - a3;
            }
        // z-pass
#pragma unroll
        for (int y = 0; y < 4; ++y)
#pragma unroll
            for (int x = 0; x < 4; ++x) {
                float a0 = d[0][y][x], a1 = d[1][y][x], a2 = d[2][y][x], a3 = d[3][y][x];
                d[0][y][x] = a0 - a2; d[1][y][x] = a1 + a2; d[2][y][x] = a2 - a1; d[3][y][x] = a1 - a3;
            }
        // split to smem
#pragma unroll
        for (int mz = 0; mz < 4; ++mz)
#pragma unroll
            for (int my = 0; my < 4; ++my)
#pragma unroll
                for (int mx = 0; mx < 4; ++mx) {
                    int mu = mz * 16 + my * 4 + mx;
                    float v = d[mz][my][mx];
                    __nv_bfloat16 hi = __float2bfloat16(v);
                    s[mu * 256 + c] = hi;
                    s[mu * 256 + 128 + c] = __float2bfloat16(v - __bfloat162float(hi));
                }
        __syncthreads();
        {
            const int tile = zt * 576 + yt * 24 + xt0 + t;
            const float4* s4 = (const float4*)s;
            float4* dstA = (float4*)d_wA;
#pragma unroll
            for (int i = 0; i < 16; ++i) {
                int idx = i * 128 + c;
                int mu = idx >> 5, ch = idx & 31;
                dstA[((size_t)mu * NT + tile) * 32 + ch] = s4[idx];
            }
        }
        __syncthreads();
        if (t < 3) {
#pragma unroll
            for (int z = 0; z < 4; ++z)
#pragma unroll
                for (int y = 0; y < 4; ++y) {
                    w[z][y][0] = w[z][y][2];
                    w[z][y][1] = w[z][y][3];
                    w[z][y][2] = __ldg(base + ((z * 50 + y) * 50 + 2 * t + 4) * 128);
                    w[z][y][3] = __ldg(base + ((z * 50 + y) * 50 + 2 * t + 5) * 128);
                }
        }
    }
}

// ---------------- Winograd GEMM + x-direction output fold ----------------
// CTA: 256 thr, M=64 tiles, N=128 co, fixed (mz,my), loops mx=0..3 as 24 pipeline steps.
// Stage: A 8KB + B 16KB, 3 stages = 72 KB.
#define STG 24576
#define CONV_SMEM (3 * STG)

__global__ void __launch_bounds__(256, 2) wino_gemm_kernel() {
    extern __shared__ char smem[];
    const uint32_t sb = smem_u32(smem);
    const int tid = threadIdx.x;
    const int tile0 = blockIdx.x * 64;     // 216 blocks
    const int mzmy = blockIdx.y;           // 16
    const int mu0 = mzmy * 4;

    auto load_stage = [&](int s) {
        const int mx = s / 6, sub = s % 6;
        const int subm = (sub < 4) ? sub : sub - 4;
        const int koA = subm << 6;
        const uint32_t ab = sb + (s % 3) * STG;
        const __nv_bfloat16* Abase = d_wA + ((size_t)(mu0 + mx) * NT + tile0) * 256;
        const __nv_bfloat16* Bbase = d_wu + (size_t)(mu0 + mx) * 49152;
#pragma unroll
        for (int i = 0; i < 2; ++i) {
            const int idx = i * 256 + tid;
            const int row = idx >> 3, u = idx & 7;
            cp16(ab + row * 128 + ((u ^ (row & 7)) << 4),
                 Abase + (size_t)row * 256 + koA + u * 8);
        }
#pragma unroll
        for (int i = 0; i < 4; ++i) {
            const int idx = i * 256 + tid;
            const int row = idx >> 3, u = idx & 7;
            cp16(ab + 8192 + row * 128 + ((u ^ (row & 7)) << 4),
                 Bbase + (size_t)row * 384 + sub * 64 + u * 8);
        }
        cp_commit();
    };

    load_stage(0);
    load_stage(1);

    const int wid = tid >> 5, lane = tid & 31;
    const int wm = wid >> 2, wn = wid & 3;       // 2m x 4n, warp tile 32x32
    const int rA = wm * 32 + (lane & 15);
    const int uA = lane >> 4;
    const int rB = wn * 32 + ((lane >> 4) << 3) + (lane & 7);
    const int uB = (lane >> 3) & 1;

    float acc[2][4][4], out0[2][4][4], out1[2][4][4];
#pragma unroll
    for (int i = 0; i < 2; ++i)
#pragma unroll
        for (int j = 0; j < 4; ++j)
#pragma unroll
            for (int k = 0; k < 4; ++k) { acc[i][j][k] = 0.f; out0[i][j][k] = 0.f; out1[i][j][k] = 0.f; }

    for (int step = 0; step < 24; ++step) {
        if (step < 23) asm volatile("cp.async.wait_group 1;");
        else           asm volatile("cp.async.wait_group 0;");
        __syncthreads();
        if (step + 2 < 24) load_stage(step + 2);

        const uint32_t As = sb + (step % 3) * STG;
        const uint32_t Bs = As + 8192;
#pragma unroll
        for (int k16 = 0; k16 < 4; ++k16) {
            uint32_t a[2][4], b4[2][4];
#pragma unroll
            for (int mt = 0; mt < 2; ++mt) {
                const int row = rA + mt * 16;
                ldsm4(As + row * 128 + (((k16 * 2 + uA) ^ (row & 7)) << 4),
                      a[mt][0], a[mt][1], a[mt][2], a[mt][3]);
            }
#pragma unroll
            for (int bt = 0; bt < 2; ++bt) {
                const int row = rB + bt * 16;
                ldsm4(Bs + row * 128 + (((k16 * 2 + uB) ^ (row & 7)) << 4),
                      b4[bt][0], b4[bt][1], b4[bt][2], b4[bt][3]);
            }
#pragma unroll
            for (int mt = 0; mt < 2; ++mt)
#pragma unroll
                for (int nt = 0; nt < 4; ++nt)
                    mma16816(acc[mt][nt], a[mt], b4[nt >> 1][(nt & 1) * 2], b4[nt >> 1][(nt & 1) * 2 + 1]);
        }

        if ((step % 6) == 5) {
            const int mx = step / 6;
            // c0 = {1,1,1,0}, c1 = {0,1,-1,-1}
#pragma unroll
            for (int i = 0; i < 2; ++i)
#pragma unroll
                for (int j = 0; j < 4; ++j)
#pragma unroll
                    for (int k = 0; k < 4; ++k) {
                        float v = acc[i][j][k];
                        if (mx < 3) out0[i][j][k] += v;
                        if (mx == 1) out1[i][j][k] += v;
                        else if (mx >= 2) out1[i][j][k] -= v;
                        acc[i][j][k] = 0.f;
                    }
        }
    }

    // write out0 -> xs=0, out1 -> xs=1
#pragma unroll
    for (int mt = 0; mt < 2; ++mt) {
#pragma unroll
        for (int half = 0; half < 2; ++half) {
            const int r = wm * 32 + mt * 16 + (lane >> 2) + half * 8;
            float* dst0 = d_V + ((size_t)(mzmy * 2 + 0) * NT + tile0 + r) * 128;
            float* dst1 = d_V + ((size_t)(mzmy * 2 + 1) * NT + tile0 + r) * 128;
#pragma unroll
            for (int nt = 0; nt < 4; ++nt) {
                const int n0 = wn * 32 + nt * 8 + (lane & 3) * 2;
                *(float2*)(dst0 + n0) = make_float2(out0[mt][nt][half * 2 + 0], out0[mt][nt][half * 2 + 1]);
                *(float2*)(dst1 + n0) = make_float2(out1[mt][nt][half * 2 + 0], out1[mt][nt][half * 2 + 1]);
            }
        }
    }
}

// ---------------- Winograd y,z output transform + bias + relu -> d_y2 ----------------
__global__ void __launch_bounds__(128) wino_out_kernel(const float* __restrict__ b0) {
    const int t = blockIdx.x;
    const int c = threadIdx.x;
    const int zt = t / 576, yt = (t / 24) % 24, xt = t % 24;
    const float* src = d_V + (size_t)t * 128 + c;
    float v[4][4][2];     // [mz][my][xs]
#pragma unroll
    for (int mz = 0; mz < 4; ++mz)
#pragma unroll
        for (int my = 0; my < 4; ++my)
#pragma unroll
            for (int xs = 0; xs < 2; ++xs)
                v[mz][my][xs] = __ldg(src + (size_t)((mz * 4 + my) * 2 + xs) * NT * 128);
    // y-pass
    float w[4][2][2];     // [mz][py][xs]
#pragma unroll
    for (int mz = 0; mz < 4; ++mz)
#pragma unroll
        for (int xs = 0; xs < 2; ++xs) {
            w[mz][0][xs] = v[mz][0][xs] + v[mz][1][xs] + v[mz][2][xs];
            w[mz][1][xs] = v[mz][1][xs] - v[mz][2][xs] - v[mz][3][xs];
        }
    // z-pass + write
    const float bias = __ldg(b0 + c);
#pragma unroll
    for (int py = 0; py < 2; ++py)
#pragma unroll
        for (int xs = 0; xs < 2; ++xs) {
            float o0 = w[0][py][xs] + w[1][py][xs] + w[2][py][xs];
            float o1 = w[1][py][xs] - w[2][py][xs] - w[3][py][xs];
            const int vz0 = (zt * 2) * HW + (yt * 2 + py) * 48 + xt * 2 + xs;
            d_y2[(size_t)vz0 * 128 + c] = fmaxf(o0 + bias, 0.f);
            d_y2[(size_t)(vz0 + HW) * 128 + c] = fmaxf(o1 + bias, 0.f);
        }
}

// ---------------- InstanceNorm stats (voxel-major) ----------------
__global__ void __launch_bounds__(128) stats_part_kernel() {
    const int blk = blockIdx.x;       // 432
    const int c = threadIdx.x;
    const float* p = d_y2 + (size_t)blk * 256 * 128 + c;
    float s = 0.f, s2 = 0.f;
#pragma unroll 4
    for (int i = 0; i < 256; ++i) {
        float v = p[(size_t)i * 128];
        s += v; s2 += v * v;
    }
    d_sp[blk * 256 + c] = s;
    d_sp[blk * 256 + 128 + c] = s2;
}
__global__ void __launch_bounds__(128) stats_fin_kernel() {
    const int c = threadIdx.x;
    float S = 0.f, S2 = 0.f;
    for (int b = 0; b < 432; ++b) {
        S  += d_sp[b * 256 + c];
        S2 += d_sp[b * 256 + 128 + c];
    }
    float mean = S * (1.0f / (float)DHW);
    float var  = S2 * (1.0f / (float)DHW) - mean * mean;
    d_mean[c] = mean;
    d_rstd[c] = rsqrtf(var + 1e-5f);
}

// ---------------- keypoint sampling: pre-swizzled split-bf16 B + norms ----------------
__global__ void __launch_bounds__(128) sample_kernel(const float* __restrict__ kpts) {
    const int n = blockIdx.x;
    const int c = threadIdx.x;
    __shared__ float pt[3];
    if (c < 3) pt[c] = kpts[n * 3 + c];
    __syncthreads();
    const float ix = (pt[0] + 1.0f) * 0.5f * 47.0f;
    const float iy = (pt[1] + 1.0f) * 0.5f * 47.0f;
    const float iz = (pt[2] + 1.0f) * 0.5f * 47.0f;
    const float x0f = floorf(ix), y0f = floorf(iy), z0f = floorf(iz);
    const float wx = ix - x0f, wy = iy - y0f, wz = iz - z0f;
    int x0 = min(max((int)x0f, 0), 47);
    int y0 = min(max((int)y0f, 0), 47);
    int z0 = min(max((int)z0f, 0), 47);
    int x1 = min(x0 + 1, 47), y1 = min(y0 + 1, 47), z1 = min(z0 + 1, 47);
    const float* vol = d_y2 + c;
    float c000 = vol[(size_t)(z0*HW + y0*48 + x0) * 128], c001 = vol[(size_t)(z0*HW + y0*48 + x1) * 128];
    float c010 = vol[(size_t)(z0*HW + y1*48 + x0) * 128], c011 = vol[(size_t)(z0*HW + y1*48 + x1) * 128];
    float c100 = vol[(size_t)(z1*HW + y0*48 + x0) * 128], c101 = vol[(size_t)(z1*HW + y0*48 + x1) * 128];
    float c110 = vol[(size_t)(z1*HW + y1*48 + x0) * 128], c111 = vol[(size_t)(z1*HW + y1*48 + x1) * 128];
    float v = c000*((1-wz)*(1-wy)*(1-wx)) + c001*((1-wz)*(1-wy)*wx)
            + c010*((1-wz)*wy*(1-wx))     + c011*((1-wz)*wy*wx)
            + c100*(wz*(1-wy)*(1-wx))     + c101*(wz*(1-wy)*wx)
            + c110*(wz*wy*(1-wx))         + c111*(wz*wy*wx);
    float f = (v - d_mean[c]) * d_rstd[c];

    float b = 2.0f * LOG2E * f;
    __nv_bfloat16 bh = __float2bfloat16(b);
    __nv_bfloat16 bl = __float2bfloat16(b - __bfloat162float(bh));
    const int chunk = n >> 5, row = n & 31;
    const int u = (c & 63) >> 3, j = c & 7, ph = c >> 6;
    char* fb = (char*)d_fkb;
    size_t base = (size_t)chunk * 24576 + (size_t)row * 128 + ((u ^ (row & 7)) << 4) + j * 2;
    *(__nv_bfloat16*)(fb + base + (0 + ph) * 4096) = bh;
    *(__nv_bfloat16*)(fb + base + (2 + ph) * 4096) = bh;
    *(__nv_bfloat16*)(fb + base + (4 + ph) * 4096) = bl;

    __shared__ float red[128];
    red[c] = f * f;
    __syncthreads();
    for (int o = 64; o > 0; o >>= 1) {
        if (c < o) red[c] += red[c + o];
        __syncthreads();
    }
    if (c == 0) d_nn[n] = LOG2E * red[0];
}

// ---------------- softmax interpolation via mma.sync ----------------
#define SMX_A    0
#define SMX_B    49152
#define SMX_NN   98304
#define SMX_DSM  100352
#define SMX_MEAN 108544
#define SMX_RSTD 109056
#define SMX_TOTAL 109568

__global__ void __launch_bounds__(128, 2) softmax_mma_kernel(const float* __restrict__ disp,
                                                             float* __restrict__ out) {
    extern __shared__ char sm[];
    const uint32_t sb = smem_u32(sm);
    const int tid = threadIdx.x;
    const int g0 = blockIdx.x * 64;

    float* nns = (float*)(sm + SMX_NN);
    float4* dsm4 = (float4*)(sm + SMX_DSM);
    for (int i = tid; i < NK; i += 128) {
        nns[i] = d_nn[i];
        float4 dv;
        dv.x = disp[i * 3]; dv.y = disp[i * 3 + 1]; dv.z = disp[i * 3 + 2]; dv.w = 0.f;
        dsm4[i] = dv;
    }
    ((float*)(sm + SMX_MEAN))[tid & 127] = d_mean[tid & 127];
    ((float*)(sm + SMX_RSTD))[tid & 127] = d_rstd[tid & 127];

    {
        const char* src = (const char*)d_fkb;
        for (int i = tid; i < 1536; i += 128) cp16(sb + SMX_B + i * 16, src + (size_t)i * 16);
        cp_commit();
    }
    __syncthreads();

    {
        const float* mean = (const float*)(sm + SMX_MEAN);
        const float* rstd = (const float*)(sm + SMX_RSTD);
        const int g = tid & 63, half = tid >> 6;
#pragma unroll
        for (int oct = 0; oct < 8; ++oct) {
            const int c0 = half * 64 + oct * 8;
            const float* srcp = d_y2 + (size_t)(g0 + g) * 128 + c0;
            float4 fa = *(const float4*)srcp;
            float4 fb4 = *(const float4*)(srcp + 4);
            float vv[8] = {fa.x, fa.y, fa.z, fa.w, fb4.x, fb4.y, fb4.z, fb4.w};
            union { __nv_bfloat16 h[8]; float4 v; } H, L;
#pragma unroll
            for (int j = 0; j < 8; ++j) {
                float a = (vv[j] - mean[c0 + j]) * rstd[c0 + j];
                __nv_bfloat16 hh = __float2bfloat16(a);
                H.h[j] = hh;
                L.h[j] = __float2bfloat16(a - __bfloat162float(hh));
            }
            const uint32_t sw = (uint32_t)((oct ^ (g & 7)) << 4);
            char* basep = sm + SMX_A + g * 128 + sw;
            *(float4*)(basep + (0 + half) * 8192) = H.v;
            *(float4*)(basep + (4 + half) * 8192) = H.v;
            *(float4*)(basep + (2 + half) * 8192) = L.v;
        }
    }
    __syncthreads();

    const int wid = tid >> 5, lane = tid & 31;
    const int rA = wid * 16 + (lane & 15);
    const int uA = lane >> 4;
    const int rB0 = ((lane >> 4) << 3) + (lane & 7);
    const int uBb = (lane >> 3) & 1;

    float mlo = -1e30f, mhi = -1e30f;
    float Slo = 0.f, Shi = 0.f;
    float Wlo0 = 0.f, Wlo1 = 0.f, Wlo2 = 0.f;
    float Whi0 = 0.f, Whi1 = 0.f, Whi2 = 0.f;

    for (int ci = 0; ci < 16; ++ci) {
        asm volatile("cp.async.wait_group 0;");
        __syncthreads();
        if (ci < 15) {
            const char* src = (const char*)d_fkb + (size_t)(ci + 1) * 24576;
            const uint32_t dst = sb + SMX_B + ((ci + 1) & 1) * 24576;
            for (int i = tid; i < 1536; i += 128) cp16(dst + i * 16, src + (size_t)i * 16);
            cp_commit();
        }
        const uint32_t Bb = sb + SMX_B + (ci & 1) * 24576;
        const int nbase = ci * 32;

        float acc[4][4];
#pragma unroll
        for (int nt = 0; nt < 4; ++nt) {
            float i0 = -nns[nbase + nt * 8 + (lane & 3) * 2];
            float i1 = -nns[nbase + nt * 8 + (lane & 3) * 2 + 1];
            acc[nt][0] = i0; acc[nt][1] = i1; acc[nt][2] = i0; acc[nt][3] = i1;
        }
#pragma unroll
        for (int s = 0; s < 24; ++s) {
            const int pan = s >> 2, inner = s & 3;
            uint32_t a[4];
            ldsm4(sb + SMX_A + pan * 8192 + rA * 128 + (((inner * 2 + uA) ^ (rA & 7)) << 4),
                  a[0], a[1], a[2], a[3]);
            uint32_t b4[2][4];
#pragma unroll
            for (int bt = 0; bt < 2; ++bt) {
                const int row = bt * 16 + rB0;
                ldsm4(Bb + pan * 4096 + row * 128 + (((inner * 2 + uBb) ^ (row & 7)) << 4),
                      b4[bt][0], b4[bt][1], b4[bt][2], b4[bt][3]);
            }
#pragma unroll
            for (int nt = 0; nt < 4; ++nt)
                mma16816(acc[nt], a, b4[nt >> 1][(nt & 1) * 2], b4[nt >> 1][(nt & 1) * 2 + 1]);
        }

        float cmlo = fmaxf(fmaxf(fmaxf(acc[0][0], acc[0][1]), fmaxf(acc[1][0], acc[1][1])),
                           fmaxf(fmaxf(acc[2][0], acc[2][1]), fmaxf(acc[3][0], acc[3][1])));
        float cmhi = fmaxf(fmaxf(fmaxf(acc[0][2], acc[0][3]), fmaxf(acc[1][2], acc[1][3])),
                           fmaxf(fmaxf(acc[2][2], acc[2][3]), fmaxf(acc[3][2], acc[3][3])));
        cmlo = fmaxf(cmlo, __shfl_xor_sync(0xffffffffu, cmlo, 1));
        cmlo = fmaxf(cmlo, __shfl_xor_sync(0xffffffffu, cmlo, 2));
        cmhi = fmaxf(cmhi, __shfl_xor_sync(0xffffffffu, cmhi, 1));
        cmhi = fmaxf(cmhi, __shfl_xor_sync(0xffffffffu, cmhi, 2));
        if (cmlo > mlo) {
            float cs = exp2a(mlo - cmlo);
            Slo *= cs; Wlo0 *= cs; Wlo1 *= cs; Wlo2 *= cs;
            mlo = cmlo;
        }
        if (cmhi > mhi) {
            float cs = exp2a(mhi - cmhi);
            Shi *= cs; Whi0 *= cs; Whi1 *= cs; Whi2 *= cs;
            mhi = cmhi;
        }
#pragma unroll
        for (int nt = 0; nt < 4; ++nt) {
#pragma unroll
            for (int j = 0; j < 2; ++j) {
                const float4 dv = dsm4[nbase + nt * 8 + (lane & 3) * 2 + j];
                float elo = exp2a(acc[nt][j] - mlo);
                float ehi = exp2a(acc[nt][2 + j] - mhi);
                Slo += elo; Shi += ehi;
                Wlo0 = fmaf(elo, dv.x, Wlo0); Wlo1 = fmaf(elo, dv.y, Wlo1); Wlo2 = fmaf(elo, dv.z, Wlo2);
                Whi0 = fmaf(ehi, dv.x, Whi0); Whi1 = fmaf(ehi, dv.y, Whi1); Whi2 = fmaf(ehi, dv.z, Whi2);
            }
        }
    }

#pragma unroll
    for (int d = 1; d <= 2; d <<= 1) {
        Slo += __shfl_xor_sync(0xffffffffu, Slo, d);
        Shi += __shfl_xor_sync(0xffffffffu, Shi, d);
        Wlo0 += __shfl_xor_sync(0xffffffffu, Wlo0, d);
        Wlo1 += __shfl_xor_sync(0xffffffffu, Wlo1, d);
        Wlo2 += __shfl_xor_sync(0xffffffffu, Wlo2, d);
        Whi0 += __shfl_xor_sync(0xffffffffu, Whi0, d);
        Whi1 += __shfl_xor_sync(0xffffffffu, Whi1, d);
        Whi2 += __shfl_xor_sync(0xffffffffu, Whi2, d);
    }
    if ((lane & 3) == 0) {
        const int rlo = g0 + wid * 16 + (lane >> 2);
        const int rhi = rlo + 8;
        const float ilo = 1.0f / Slo, ihi = 1.0f / Shi;
        out[0 * DHW + rlo] = Wlo0 * ilo;
        out[1 * DHW + rlo] = Wlo1 * ilo;
        out[2 * DHW + rlo] = Wlo2 * ilo;
        out[0 * DHW + rhi] = Whi0 * ihi;
        out[1 * DHW + rhi] = Whi1 * ihi;
        out[2 * DHW + rhi] = Whi2 * ihi;
    }
}

// ---------------- launch ----------------
extern "C" void kernel_launch(void* const* d_in, const int* in_sizes, int n_in,
                              void* d_out, int out_size) {
    const float* kpts  = (const float*)d_in[0];
    const float* disp  = (const float*)d_in[1];
    const float* feats = (const float*)d_in[2];
    const float* W0    = (const float*)d_in[3];
    const float* b0    = (const float*)d_in[4];
    float* out = (float*)d_out;

    static int attr_done = 0;
    if (!attr_done) {
        cudaFuncSetAttribute(wino_gemm_kernel, cudaFuncAttributeMaxDynamicSharedMemorySize, CONV_SMEM);
        cudaFuncSetAttribute(softmax_mma_kernel, cudaFuncAttributeMaxDynamicSharedMemorySize, SMX_TOTAL);
        attr_done = 1;
    }

    pad_kernel<<<2500, 256>>>(feats);
    wino_w_kernel<<<8192, 128>>>(W0);
    wino_in_kernel<<<3456, 128>>>();
    wino_gemm_kernel<<<dim3(216, 16), 256, CONV_SMEM>>>();
    wino_out_kernel<<<NT, 128>>>(b0);
    stats_part_kernel<<<432, 128>>>();
    stats_fin_kernel<<<1, 128>>>();
    sample_kernel<<<NK, 128>>>(kpts);
    softmax_mma_kernel<<<DHW / 64, 128, SMX_TOTAL>>>(disp, out);
}

// round 11
// speedup vs baseline: 1.0555x; 1.0555x over previous
#include <cuda_runtime.h>
#include <cuda_bf16.h>
#include <cstdint>

#define DD   48
#define HW   2304
#define DHW  110592
#define NK   512
#define LOG2E 1.4426950408889634f
#define NT   13824            // 24^3 Winograd tiles
#define NMU  64

// ---------------- device scratch ----------------
__device__ float d_xp[50 * 50 * 50 * 128];                          // padded input, voxel-major
__device__ __align__(16) __nv_bfloat16 d_wA[(size_t)NMU * NT * 256]; // transformed input [mu][tile][hi128|lo128]
__device__ __align__(16) __nv_bfloat16 d_wu[NMU * 128 * 384];        // transformed weights [mu][co][bhi|bhi|blo]
__device__ float d_V[(size_t)32 * NT * 128];                         // x-folded GEMM out [mzmy*2+xs][tile][co]
__device__ float d_y2[(size_t)DHW * 128];                            // conv out voxel-major [voxel][c]
__device__ __align__(16) __nv_bfloat16 d_fkb[16 * 12288];            // keypoint feats, pre-swizzled
__device__ float d_sp[432 * 256];
__device__ float d_mean[128];
__device__ float d_rstd[128];
__device__ float d_nn[NK];

__device__ __forceinline__ float exp2a(float x) {
    float r; asm("ex2.approx.ftz.f32 %0, %1;" : "=f"(r) : "f"(x)); return r;
}
__device__ __forceinline__ uint32_t smem_u32(const void* p) {
    uint32_t a;
    asm("{ .reg .u64 t; cvta.to.shared.u64 t, %1; cvt.u32.u64 %0, t; }" : "=r"(a) : "l"(p));
    return a;
}
__device__ __forceinline__ void cp16(uint32_t dst, const void* src) {
    asm volatile("cp.async.cg.shared.global [%0], [%1], 16;" :: "r"(dst), "l"(src));
}
__device__ __forceinline__ void cp_commit() { asm volatile("cp.async.commit_group;"); }
__device__ __forceinline__ void ldsm4(uint32_t addr, uint32_t& r0, uint32_t& r1, uint32_t& r2, uint32_t& r3) {
    asm volatile("ldmatrix.sync.aligned.m8n8.x4.shared.b16 {%0,%1,%2,%3}, [%4];"
                 : "=r"(r0), "=r"(r1), "=r"(r2), "=r"(r3) : "r"(addr));
}
__device__ __forceinline__ void mma16816(float* c, const uint32_t* a, uint32_t b0, uint32_t b1) {
    asm volatile("mma.sync.aligned.m16n8k16.row.col.f32.bf16.bf16.f32 "
                 "{%0,%1,%2,%3}, {%4,%5,%6,%7}, {%8,%9}, {%0,%1,%2,%3};"
                 : "+f"(c[0]), "+f"(c[1]), "+f"(c[2]), "+f"(c[3])
                 : "r"(a[0]), "r"(a[1]), "r"(a[2]), "r"(a[3]), "r"(b0), "r"(b1));
}

// ---------------- pad input to [zp50][yp50][xp50][c128] fp32, voxel-major ----------------
__global__ void __launch_bounds__(256) pad_kernel(const float* __restrict__ feats) {
    __shared__ float tb[50][129];
    const int r = blockIdx.x;               // 2500 (zp,yp) rows
    const int zp = r / 50, yp = r % 50;
    const int zi = zp - 1, yi = yp - 1;
    const int tid = threadIdx.x;
    const int x = tid & 63, cq = tid >> 6;
    const int xi = x - 1;
    const bool rowok = (zi >= 0 && zi < 48 && yi >= 0 && yi < 48);
    const bool xok = rowok && (xi >= 0 && xi < 48);
#pragma unroll 4
    for (int i = 0; i < 32; ++i) {
        int c = cq * 32 + i;
        float v = 0.f;
        if (xok) {
            if (c < 125)       v = feats[(size_t)c * DHW + zi * HW + yi * 48 + xi];
            else if (c == 125) v = (2.0f / 47.0f) * (float)xi - 1.0f;
            else if (c == 126) v = (2.0f / 47.0f) * (float)yi - 1.0f;
            else               v = (2.0f / 47.0f) * (float)zi - 1.0f;
        }
        if (x < 50) tb[x][c] = v;
    }
    __syncthreads();
    float* dst = d_xp + (size_t)r * 50 * 128;
    for (int i = tid; i < 1600; i += 256) {
        int xr = i >> 5, c4 = (i & 31) * 4;
        float4 val = make_float4(tb[xr][c4], tb[xr][c4 + 1], tb[xr][c4 + 2], tb[xr][c4 + 3]);
        *(float4*)(dst + xr * 128 + c4) = val;
    }
}

// ---------------- Winograd weight transform ----------------
__device__ __forceinline__ void grow(int m, float* g) {
    if (m == 0)      { g[0] = 1.f;  g[1] = 0.f;   g[2] = 0.f; }
    else if (m == 1) { g[0] = 0.5f; g[1] = 0.5f;  g[2] = 0.5f; }
    else if (m == 2) { g[0] = 0.5f; g[1] = -0.5f; g[2] = 0.5f; }
    else             { g[0] = 0.f;  g[1] = 0.f;   g[2] = 1.f; }
}
__global__ void __launch_bounds__(128) wino_w_kernel(const float* __restrict__ W0) {
    const int mu = blockIdx.x >> 7, co = blockIdx.x & 127, ci = threadIdx.x;
    const int mz = mu >> 4, my = (mu >> 2) & 3, mx = mu & 3;
    float gz[3], gy[3], gx[3];
    grow(mz, gz); grow(my, gy); grow(mx, gx);
    const float* w = W0 + (size_t)(co * 128 + ci) * 27;
    float u = 0.f;
#pragma unroll
    for (int dz = 0; dz < 3; ++dz)
#pragma unroll
        for (int dy = 0; dy < 3; ++dy)
#pragma unroll
            for (int dx = 0; dx < 3; ++dx)
                u = fmaf(gz[dz] * gy[dy] * gx[dx], __ldg(w + dz * 9 + dy * 3 + dx), u);
    __nv_bfloat16 hi = __float2bfloat16(u);
    __nv_bfloat16 lo = __float2bfloat16(u - __bfloat162float(hi));
    __nv_bfloat16* rrow = d_wu + ((size_t)mu * 128 + co) * 384;
    rrow[ci] = hi; rrow[128 + ci] = hi; rrow[256 + ci] = lo;
}

// ---------------- Winograd input transform: 4 x-tiles per block, sliding window ----------------
__global__ void __launch_bounds__(128) wino_in_kernel() {
    __shared__ __nv_bfloat16 s[NMU * 256];   // 32 KB staging
    const int blk = blockIdx.x;              // 3456 = 24*24*6
    const int c = threadIdx.x;
    const int xg = blk % 6, yt = (blk / 6) % 24, zt = blk / 144;
    const int xt0 = xg * 4;
    const float* base = d_xp + ((size_t)((zt * 2) * 50 + yt * 2) * 50 + xt0 * 2) * 128 + c;

    float w[4][4][4];
#pragma unroll
    for (int z = 0; z < 4; ++z)
#pragma unroll
        for (int y = 0; y < 4; ++y)
#pragma unroll
            for (int x = 0; x < 4; ++x)
                w[z][y][x] = __ldg(base + ((z * 50 + y) * 50 + x) * 128);

    for (int t = 0; t < 4; ++t) {
        float d[4][4][4];
#pragma unroll
        for (int z = 0; z < 4; ++z)
#pragma unroll
            for (int y = 0; y < 4; ++y)
#pragma unroll
                for (int x = 0; x < 4; ++x) d[z][y][x] = w[z][y][x];
        // x-pass
#pragma unroll
        for (int z = 0; z < 4; ++z)
#pragma unroll
            for (int y = 0; y < 4; ++y) {
                float a0 = d[z][y][0], a1 = d[z][y][1], a2 = d[z][y][2], a3 = d[z][y][3];
                d[z][y][0] = a0 - a2; d[z][y][1] = a1 + a2; d[z][y][2] = a2 - a1; d[z][y][3] = a1 - a3;
            }
        // y-pass
#pragma unroll
        for (int z = 0; z < 4; ++z)
#pragma unroll
            for (int x = 0; x < 4; ++x) {
                float a0 = d[z][0][x], a1 = d[z][1][x], a2 = d[z][2][x], a3 = d[z][3][x];
                d[z][0][x] = a0 - a2; d[z][1][x] = a1 + a2; d[z][2][x] = a2 - a1; d[z][3][x] = a1 - a3;
            }
        // z-pass
#pragma unroll
        for (int y = 0; y < 4; ++y)
#pragma unroll
            for (int x = 0; x < 4; ++x) {
                float a0 = d[0][y][x], a1 = d[1][y][x], a2 = d[2][y][x], a3 = d[3][y][x];
                d[0][y][x] = a0 - a2; d[1][y][x] = a1 + a2; d[2][y][x] = a2 - a1; d[3][y][x] = a1 - a3;
            }
        // split to smem
#pragma unroll
        for (int mz = 0; mz < 4; ++mz)
#pragma unroll
            for (int my = 0; my < 4; ++my)
#pragma unroll
                for (int mx = 0; mx < 4; ++mx) {
                    int mu = mz * 16 + my * 4 + mx;
                    float v = d[mz][my][mx];
                    __nv_bfloat16 hi = __float2bfloat16(v);
                    s[mu * 256 + c] = hi;
                    s[mu * 256 + 128 + c] = __float2bfloat16(v - __bfloat162float(hi));
                }
        __syncthreads();
        {
            const int tile = zt * 576 + yt * 24 + xt0 + t;
            const float4* s4 = (const float4*)s;
            float4* dstA = (float4*)d_wA;
#pragma unroll
            for (int i = 0; i < 16; ++i) {
                int idx = i * 128 + c;
                int mu = idx >> 5, ch = idx & 31;
                dstA[((size_t)mu * NT + tile) * 32 + ch] = s4[idx];
            }
        }
        __syncthreads();
        if (t < 3) {
#pragma unroll
            for (int z = 0; z < 4; ++z)
#pragma unroll
                for (int y = 0; y < 4; ++y) {
                    w[z][y][0] = w[z][y][2];
                    w[z][y][1] = w[z][y][3];
                    w[z][y][2] = __ldg(base + ((z * 50 + y) * 50 + 2 * t + 4) * 128);
                    w[z][y][3] = __ldg(base + ((z * 50 + y) * 50 + 2 * t + 5) * 128);
                }
        }
    }
}

// ---------------- Winograd GEMM + x-direction output fold ----------------
// CTA: 128 thr, M=64 tiles, N=128 co, warp tile 32x64 (2m x 2n), fixed (mz,my),
// loops mx=0..3 as 24 pipeline steps. Stage: A 8KB + B 16KB, 3 stages = 72 KB.
#define STG 24576
#define CONV_SMEM (3 * STG)

__global__ void __launch_bounds__(128, 2) wino_gemm_kernel() {
    extern __shared__ char smem[];
    const uint32_t sb = smem_u32(smem);
    const int tid = threadIdx.x;
    const int tile0 = blockIdx.x * 64;     // 216 blocks
    const int mzmy = blockIdx.y;           // 16
    const int mu0 = mzmy * 4;

    auto load_stage = [&](int s) {
        const int mx = s / 6, sub = s % 6;
        const int subm = (sub < 4) ? sub : sub - 4;
        const int koA = subm << 6;
        const uint32_t ab = sb + (s % 3) * STG;
        const __nv_bfloat16* Abase = d_wA + ((size_t)(mu0 + mx) * NT + tile0) * 256;
        const __nv_bfloat16* Bbase = d_wu + (size_t)(mu0 + mx) * 49152;
#pragma unroll
        for (int i = 0; i < 4; ++i) {
            const int idx = i * 128 + tid;
            const int row = idx >> 3, u = idx & 7;
            cp16(ab + row * 128 + ((u ^ (row & 7)) << 4),
                 Abase + (size_t)row * 256 + koA + u * 8);
        }
#pragma unroll
        for (int i = 0; i < 8; ++i) {
            const int idx = i * 128 + tid;
            const int row = idx >> 3, u = idx & 7;
            cp16(ab + 8192 + row * 128 + ((u ^ (row & 7)) << 4),
                 Bbase + (size_t)row * 384 + sub * 64 + u * 8);
        }
        cp_commit();
    };

    load_stage(0);
    load_stage(1);

    const int wid = tid >> 5, lane = tid & 31;
    const int wm = wid >> 1, wn = wid & 1;       // 2m x 2n, warp tile 32x64
    const int rA = wm * 32 + (lane & 15);
    const int uA = lane >> 4;
    const int rB = wn * 64 + ((lane >> 4) << 3) + (lane & 7);
    const int uB = (lane >> 3) & 1;

    float acc[2][8][4], out0[2][8][4], out1[2][8][4];
#pragma unroll
    for (int i = 0; i < 2; ++i)
#pragma unroll
        for (int j = 0; j < 8; ++j)
#pragma unroll
            for (int k = 0; k < 4; ++k) { acc[i][j][k] = 0.f; out0[i][j][k] = 0.f; out1[i][j][k] = 0.f; }

    for (int step = 0; step < 24; ++step) {
        if (step < 23) asm volatile("cp.async.wait_group 1;");
        else           asm volatile("cp.async.wait_group 0;");
        __syncthreads();
        if (step + 2 < 24) load_stage(step + 2);

        const uint32_t As = sb + (step % 3) * STG;
        const uint32_t Bs = As + 8192;
#pragma unroll
        for (int k16 = 0; k16 < 4; ++k16) {
            uint32_t a[2][4], b4[4][4];
#pragma unroll
            for (int mt = 0; mt < 2; ++mt) {
                const int row = rA + mt * 16;
                ldsm4(As + row * 128 + (((k16 * 2 + uA) ^ (row & 7)) << 4),
                      a[mt][0], a[mt][1], a[mt][2], a[mt][3]);
            }
#pragma unroll
            for (int bt = 0; bt < 4; ++bt) {
                const int row = rB + bt * 16;
                ldsm4(Bs + row * 128 + (((k16 * 2 + uB) ^ (row & 7)) << 4),
                      b4[bt][0], b4[bt][1], b4[bt][2], b4[bt][3]);
            }
#pragma unroll
            for (int mt = 0; mt < 2; ++mt)
#pragma unroll
                for (int nt = 0; nt < 8; ++nt)
                    mma16816(acc[mt][nt], a[mt], b4[nt >> 1][(nt & 1) * 2], b4[nt >> 1][(nt & 1) * 2 + 1]);
        }

        if ((step % 6) == 5) {
            const int mx = step / 6;
            // c0 = {1,1,1,0}, c1 = {0,1,-1,-1}
#pragma unroll
            for (int i = 0; i < 2; ++i)
#pragma unroll
                for (int j = 0; j < 8; ++j)
#pragma unroll
                    for (int k = 0; k < 4; ++k) {
                        float v = acc[i][j][k];
                        if (mx < 3) out0[i][j][k] += v;
                        if (mx == 1) out1[i][j][k] += v;
                        else if (mx >= 2) out1[i][j][k] -= v;
                        acc[i][j][k] = 0.f;
                    }
        }
    }

    // write out0 -> xs=0, out1 -> xs=1
#pragma unroll
    for (int mt = 0; mt < 2; ++mt) {
#pragma unroll
        for (int half = 0; half < 2; ++half) {
            const int r = wm * 32 + mt * 16 + (lane >> 2) + half * 8;
            float* dst0 = d_V + ((size_t)(mzmy * 2 + 0) * NT + tile0 + r) * 128;
            float* dst1 = d_V + ((size_t)(mzmy * 2 + 1) * NT + tile0 + r) * 128;
#pragma unroll
            for (int nt = 0; nt < 8; ++nt) {
                const int n0 = wn * 64 + nt * 8 + (lane & 3) * 2;
                *(float2*)(dst0 + n0) = make_float2(out0[mt][nt][half * 2 + 0], out0[mt][nt][half * 2 + 1]);
                *(float2*)(dst1 + n0) = make_float2(out1[mt][nt][half * 2 + 0], out1[mt][nt][half * 2 + 1]);
            }
        }
    }
}

// ---------------- Winograd y,z output transform + bias + relu -> d_y2 ----------------
__global__ void __launch_bounds__(128) wino_out_kernel(const float* __restrict__ b0) {
    const int t = blockIdx.x;
    const int c = threadIdx.x;
    const int zt = t / 576, yt = (t / 24) % 24, xt = t % 24;
    const float* src = d_V + (size_t)t * 128 + c;
    float v[4][4][2];     // [mz][my][xs]
#pragma unroll
    for (int mz = 0; mz < 4; ++mz)
#pragma unroll
        for (int my = 0; my < 4; ++my)
#pragma unroll
            for (int xs = 0; xs < 2; ++xs)
                v[mz][my][xs] = __ldg(src + (size_t)((mz * 4 + my) * 2 + xs) * NT * 128);
    // y-pass
    float w[4][2][2];     // [mz][py][xs]
#pragma unroll
    for (int mz = 0; mz < 4; ++mz)
#pragma unroll
        for (int xs = 0; xs < 2; ++xs) {
            w[mz][0][xs] = v[mz][0][xs] + v[mz][1][xs] + v[mz][2][xs];
            w[mz][1][xs] = v[mz][1][xs] - v[mz][2][xs] - v[mz][3][xs];
        }
    // z-pass + write
    const float bias = __ldg(b0 + c);
#pragma unroll
    for (int py = 0; py < 2; ++py)
#pragma unroll
        for (int xs = 0; xs < 2; ++xs) {
            float o0 = w[0][py][xs] + w[1][py][xs] + w[2][py][xs];
            float o1 = w[1][py][xs] - w[2][py][xs] - w[3][py][xs];
            const int vz0 = (zt * 2) * HW + (yt * 2 + py) * 48 + xt * 2 + xs;
            d_y2[(size_t)vz0 * 128 + c] = fmaxf(o0 + bias, 0.f);
            d_y2[(size_t)(vz0 + HW) * 128 + c] = fmaxf(o1 + bias, 0.f);
        }
}

// ---------------- InstanceNorm stats (voxel-major) ----------------
__global__ void __launch_bounds__(128) stats_part_kernel() {
    const int blk = blockIdx.x;       // 432
    const int c = threadIdx.x;
    const float* p = d_y2 + (size_t)blk * 256 * 128 + c;
    float s = 0.f, s2 = 0.f;
#pragma unroll 4
    for (int i = 0; i < 256; ++i) {
        float v = p[(size_t)i * 128];
        s += v; s2 += v * v;
    }
    d_sp[blk * 256 + c] = s;
    d_sp[blk * 256 + 128 + c] = s2;
}
__global__ void __launch_bounds__(128) stats_fin_kernel() {
    const int c = threadIdx.x;
    float S = 0.f, S2 = 0.f;
    for (int b = 0; b < 432; ++b) {
        S  += d_sp[b * 256 + c];
        S2 += d_sp[b * 256 + 128 + c];
    }
    float mean = S * (1.0f / (float)DHW);
    float var  = S2 * (1.0f / (float)DHW) - mean * mean;
    d_mean[c] = mean;
    d_rstd[c] = rsqrtf(var + 1e-5f);
}

// ---------------- keypoint sampling: pre-swizzled split-bf16 B + norms ----------------
__global__ void __launch_bounds__(128) sample_kernel(const float* __restrict__ kpts) {
    const int n = blockIdx.x;
    const int c = threadIdx.x;
    __shared__ float pt[3];
    if (c < 3) pt[c] = kpts[n * 3 + c];
    __syncthreads();
    const float ix = (pt[0] + 1.0f) * 0.5f * 47.0f;
    const float iy = (pt[1] + 1.0f) * 0.5f * 47.0f;
    const float iz = (pt[2] + 1.0f) * 0.5f * 47.0f;
    const float x0f = floorf(ix), y0f = floorf(iy), z0f = floorf(iz);
    const float wx = ix - x0f, wy = iy - y0f, wz = iz - z0f;
    int x0 = min(max((int)x0f, 0), 47);
    int y0 = min(max((int)y0f, 0), 47);
    int z0 = min(max((int)z0f, 0), 47);
    int x1 = min(x0 + 1, 47), y1 = min(y0 + 1, 47), z1 = min(z0 + 1, 47);
    const float* vol = d_y2 + c;
    float c000 = vol[(size_t)(z0*HW + y0*48 + x0) * 128], c001 = vol[(size_t)(z0*HW + y0*48 + x1) * 128];
    float c010 = vol[(size_t)(z0*HW + y1*48 + x0) * 128], c011 = vol[(size_t)(z0*HW + y1*48 + x1) * 128];
    float c100 = vol[(size_t)(z1*HW + y0*48 + x0) * 128], c101 = vol[(size_t)(z1*HW + y0*48 + x1) * 128];
    float c110 = vol[(size_t)(z1*HW + y1*48 + x0) * 128], c111 = vol[(size_t)(z1*HW + y1*48 + x1) * 128];
    float v = c000*((1-wz)*(1-wy)*(1-wx)) + c001*((1-wz)*(1-wy)*wx)
            + c010*((1-wz)*wy*(1-wx))     + c011*((1-wz)*wy*wx)
            + c100*(wz*(1-wy)*(1-wx))     + c101*(wz*(1-wy)*wx)
            + c110*(wz*wy*(1-wx))         + c111*(wz*wy*wx);
    float f = (v - d_mean[c]) * d_rstd[c];

    float b = 2.0f * LOG2E * f;
    __nv_bfloat16 bh = __float2bfloat16(b);
    __nv_bfloat16 bl = __float2bfloat16(b - __bfloat162float(bh));
    const int chunk = n >> 5, row = n & 31;
    const int u = (c & 63) >> 3, j = c & 7, ph = c >> 6;
    char* fb = (char*)d_fkb;
    size_t base = (size_t)chunk * 24576 + (size_t)row * 128 + ((u ^ (row & 7)) << 4) + j * 2;
    *(__nv_bfloat16*)(fb + base + (0 + ph) * 4096) = bh;
    *(__nv_bfloat16*)(fb + base + (2 + ph) * 4096) = bh;
    *(__nv_bfloat16*)(fb + base + (4 + ph) * 4096) = bl;

    __shared__ float red[128];
    red[c] = f * f;
    __syncthreads();
    for (int o = 64; o > 0; o >>= 1) {
        if (c < o) red[c] += red[c + o];
        __syncthreads();
    }
    if (c == 0) d_nn[n] = LOG2E * red[0];
}

// ---------------- softmax interpolation via mma.sync ----------------
#define SMX_A    0
#define SMX_B    49152
#define SMX_NN   98304
#define SMX_DSM  100352
#define SMX_MEAN 108544
#define SMX_RSTD 109056
#define SMX_TOTAL 109568

__global__ void __launch_bounds__(128, 2) softmax_mma_kernel(const float* __restrict__ disp,
                                                             float* __restrict__ out) {
    extern __shared__ char sm[];
    const uint32_t sb = smem_u32(sm);
    const int tid = threadIdx.x;
    const int g0 = blockIdx.x * 64;

    float* nns = (float*)(sm + SMX_NN);
    float4* dsm4 = (float4*)(sm + SMX_DSM);
    for (int i = tid; i < NK; i += 128) {
        nns[i] = d_nn[i];
        float4 dv;
        dv.x = disp[i * 3]; dv.y = disp[i * 3 + 1]; dv.z = disp[i * 3 + 2]; dv.w = 0.f;
        dsm4[i] = dv;
    }
    ((float*)(sm + SMX_MEAN))[tid & 127] = d_mean[tid & 127];
    ((float*)(sm + SMX_RSTD))[tid & 127] = d_rstd[tid & 127];

    {
        const char* src = (const char*)d_fkb;
        for (int i = tid; i < 1536; i += 128) cp16(sb + SMX_B + i * 16, src + (size_t)i * 16);
        cp_commit();
    }
    __syncthreads();

    {
        const float* mean = (const float*)(sm + SMX_MEAN);
        const float* rstd = (const float*)(sm + SMX_RSTD);
        const int g = tid & 63, half = tid >> 6;
#pragma unroll
        for (int oct = 0; oct < 8; ++oct) {
            const int c0 = half * 64 + oct * 8;
            const float* srcp = d_y2 + (size_t)(g0 + g) * 128 + c0;
            float4 fa = *(const float4*)srcp;
            float4 fb4 = *(const float4*)(srcp + 4);
            float vv[8] = {fa.x, fa.y, fa.z, fa.w, fb4.x, fb4.y, fb4.z, fb4.w};
            union { __nv_bfloat16 h[8]; float4 v; } H, L;
#pragma unroll
            for (int j = 0; j < 8; ++j) {
                float a = (vv[j] - mean[c0 + j]) * rstd[c0 + j];
                __nv_bfloat16 hh = __float2bfloat16(a);
                H.h[j] = hh;
                L.h[j] = __float2bfloat16(a - __bfloat162float(hh));
            }
            const uint32_t sw = (uint32_t)((oct ^ (g & 7)) << 4);
            char* basep = sm + SMX_A + g * 128 + sw;
            *(float4*)(basep + (0 + half) * 8192) = H.v;
            *(float4*)(basep + (4 + half) * 8192) = H.v;
            *(float4*)(basep + (2 + half) * 8192) = L.v;
        }
    }
    __syncthreads();

    const int wid = tid >> 5, lane = tid & 31;
    const int rA = wid * 16 + (lane & 15);
    const int uA = lane >> 4;
    const int rB0 = ((lane >> 4) << 3) + (lane & 7);
    const int uBb = (lane >> 3) & 1;

    float mlo = -1e30f, mhi = -1e30f;
    float Slo = 0.f, Shi = 0.f;
    float Wlo0 = 0.f, Wlo1 = 0.f, Wlo2 = 0.f;
    float Whi0 = 0.f, Whi1 = 0.f, Whi2 = 0.f;

    for (int ci = 0; ci < 16; ++ci) {
        asm volatile("cp.async.wait_group 0;");
        __syncthreads();
        if (ci < 15) {
            const char* src = (const char*)d_fkb + (size_t)(ci + 1) * 24576;
            const uint32_t dst = sb + SMX_B + ((ci + 1) & 1) * 24576;
            for (int i = tid; i < 1536; i += 128) cp16(dst + i * 16, src + (size_t)i * 16);
            cp_commit();
        }
        const uint32_t Bb = sb + SMX_B + (ci & 1) * 24576;
        const int nbase = ci * 32;

        float acc[4][4];
#pragma unroll
        for (int nt = 0; nt < 4; ++nt) {
            float i0 = -nns[nbase + nt * 8 + (lane & 3) * 2];
            float i1 = -nns[nbase + nt * 8 + (lane & 3) * 2 + 1];
            acc[nt][0] = i0; acc[nt][1] = i1; acc[nt][2] = i0; acc[nt][3] = i1;
        }
#pragma unroll
        for (int s = 0; s < 24; ++s) {
            const int pan = s >> 2, inner = s & 3;
            uint32_t a[4];
            ldsm4(sb + SMX_A + pan * 8192 + rA * 128 + (((inner * 2 + uA) ^ (rA & 7)) << 4),
                  a[0], a[1], a[2], a[3]);
            uint32_t b4[2][4];
#pragma unroll
            for (int bt = 0; bt < 2; ++bt) {
                const int row = bt * 16 + rB0;
                ldsm4(Bb + pan * 4096 + row * 128 + (((inner * 2 + uBb) ^ (row & 7)) << 4),
                      b4[bt][0], b4[bt][1], b4[bt][2], b4[bt][3]);
            }
#pragma unroll
            for (int nt = 0; nt < 4; ++nt)
                mma16816(acc[nt], a, b4[nt >> 1][(nt & 1) * 2], b4[nt >> 1][(nt & 1) * 2 + 1]);
        }

        float cmlo = fmaxf(fmaxf(fmaxf(acc[0][0], acc[0][1]), fmaxf(acc[1][0], acc[1][1])),
                           fmaxf(fmaxf(acc[2][0], acc[2][1]), fmaxf(acc[3][0], acc[3][1])));
        float cmhi = fmaxf(fmaxf(fmaxf(acc[0][2], acc[0][3]), fmaxf(acc[1][2], acc[1][3])),
                           fmaxf(fmaxf(acc[2][2], acc[2][3]), fmaxf(acc[3][2], acc[3][3])));
        cmlo = fmaxf(cmlo, __shfl_xor_sync(0xffffffffu, cmlo, 1));
        cmlo = fmaxf(cmlo, __shfl_xor_sync(0xffffffffu, cmlo, 2));
        cmhi = fmaxf(cmhi, __shfl_xor_sync(0xffffffffu, cmhi, 1));
        cmhi = fmaxf(cmhi, __shfl_xor_sync(0xffffffffu, cmhi, 2));
        if (cmlo > mlo) {
            float cs = exp2a(mlo - cmlo);
            Slo *= cs; Wlo0 *= cs; Wlo1 *= cs; Wlo2 *= cs;
            mlo = cmlo;
        }
        if (cmhi > mhi) {
            float cs = exp2a(mhi - cmhi);
            Shi *= cs; Whi0 *= cs; Whi1 *= cs; Whi2 *= cs;
            mhi = cmhi;
        }
#pragma unroll
        for (int nt = 0; nt < 4; ++nt) {
#pragma unroll
            for (int j = 0; j < 2; ++j) {
                const float4 dv = dsm4[nbase + nt * 8 + (lane & 3) * 2 + j];
                float elo = exp2a(acc[nt][j] - mlo);
                float ehi = exp2a(acc[nt][2 + j] - mhi);
                Slo += elo; Shi += ehi;
                Wlo0 = fmaf(elo, dv.x, Wlo0); Wlo1 = fmaf(elo, dv.y, Wlo1); Wlo2 = fmaf(elo, dv.z, Wlo2);
                Whi0 = fmaf(ehi, dv.x, Whi0); Whi1 = fmaf(ehi, dv.y, Whi1); Whi2 = fmaf(ehi, dv.z, Whi2);
            }
        }
    }

#pragma unroll
    for (int d = 1; d <= 2; d <<= 1) {
        Slo += __shfl_xor_sync(0xffffffffu, Slo, d);
        Shi += __shfl_xor_sync(0xffffffffu, Shi, d);
        Wlo0 += __shfl_xor_sync(0xffffffffu, Wlo0, d);
        Wlo1 += __shfl_xor_sync(0xffffffffu, Wlo1, d);
        Wlo2 += __shfl_xor_sync(0xffffffffu, Wlo2, d);
        Whi0 += __shfl_xor_sync(0xffffffffu, Whi0, d);
        Whi1 += __shfl_xor_sync(0xffffffffu, Whi1, d);
        Whi2 += __shfl_xor_sync(0xffffffffu, Whi2, d);
    }
    if ((lane & 3) == 0) {
        const int rlo = g0 + wid * 16 + (lane >> 2);
        const int rhi = rlo + 8;
        const float ilo = 1.0f / Slo, ihi = 1.0f / Shi;
        out[0 * DHW + rlo] = Wlo0 * ilo;
        out[1 * DHW + rlo] = Wlo1 * ilo;
        out[2 * DHW + rlo] = Wlo2 * ilo;
        out[0 * DHW + rhi] = Whi0 * ihi;
        out[1 * DHW + rhi] = Whi1 * ihi;
        out[2 * DHW + rhi] = Whi2 * ihi;
    }
}

// ---------------- launch ----------------
extern "C" void kernel_launch(void* const* d_in, const int* in_sizes, int n_in,
                              void* d_out, int out_size) {
    const float* kpts  = (const float*)d_in[0];
    const float* disp  = (const float*)d_in[1];
    const float* feats = (const float*)d_in[2];
    const float* W0    = (const float*)d_in[3];
    const float* b0    = (const float*)d_in[4];
    float* out = (float*)d_out;

    static int attr_done = 0;
    if (!attr_done) {
        cudaFuncSetAttribute(wino_gemm_kernel, cudaFuncAttributeMaxDynamicSharedMemorySize, CONV_SMEM);
        cudaFuncSetAttribute(softmax_mma_kernel, cudaFuncAttributeMaxDynamicSharedMemorySize, SMX_TOTAL);
        attr_done = 1;
    }

    pad_kernel<<<2500, 256>>>(feats);
    wino_w_kernel<<<8192, 128>>>(W0);
    wino_in_kernel<<<3456, 128>>>();
    wino_gemm_kernel<<<dim3(216, 16), 128, CONV_SMEM>>>();
    wino_out_kernel<<<NT, 128>>>(b0);
    stats_part_kernel<<<432, 128>>>();
    stats_fin_kernel<<<1, 128>>>();
    sample_kernel<<<NK, 128>>>(kpts);
    softmax_mma_kernel<<<DHW / 64, 128, SMX_TOTAL>>>(disp, out);
}

// round 12
// speedup vs baseline: 1.0685x; 1.0123x over previous
#include <cuda_runtime.h>
#include <cuda_bf16.h>
#include <cstdint>

#define DD   48
#define HW   2304
#define DHW  110592
#define NK   512
#define LOG2E 1.4426950408889634f
#define NT   13824            // 24^3 Winograd tiles
#define NMU  64

// ---------------- device scratch ----------------
__device__ float d_xp[50 * 50 * 50 * 128];                          // padded input, voxel-major
__device__ __align__(16) __nv_bfloat16 d_wA[(size_t)NMU * NT * 256]; // transformed input [mu][tile][hi128|lo128]
__device__ __align__(16) __nv_bfloat16 d_wu[NMU * 128 * 384];        // transformed weights [mu][co][bhi|bhi|blo]
__device__ float d_V[(size_t)32 * NT * 128];                         // x-folded GEMM out [mzmy*2+xs][tile][co]
__device__ float d_y2[(size_t)DHW * 128];                            // conv out voxel-major [voxel][c]
__device__ __align__(16) __nv_bfloat16 d_fkb[16 * 12288];            // keypoint feats, pre-swizzled
__device__ float d_sp[432 * 256];
__device__ float d_mean[128];
__device__ float d_rstd[128];
__device__ float d_nn[NK];

__device__ __forceinline__ float exp2a(float x) {
    float r; asm("ex2.approx.ftz.f32 %0, %1;" : "=f"(r) : "f"(x)); return r;
}
__device__ __forceinline__ uint32_t smem_u32(const void* p) {
    uint32_t a;
    asm("{ .reg .u64 t; cvta.to.shared.u64 t, %1; cvt.u32.u64 %0, t; }" : "=r"(a) : "l"(p));
    return a;
}
__device__ __forceinline__ void cp16(uint32_t dst, const void* src) {
    asm volatile("cp.async.cg.shared.global [%0], [%1], 16;" :: "r"(dst), "l"(src));
}
__device__ __forceinline__ void cp_commit() { asm volatile("cp.async.commit_group;"); }
__device__ __forceinline__ void ldsm4(uint32_t addr, uint32_t& r0, uint32_t& r1, uint32_t& r2, uint32_t& r3) {
    asm volatile("ldmatrix.sync.aligned.m8n8.x4.shared.b16 {%0,%1,%2,%3}, [%4];"
                 : "=r"(r0), "=r"(r1), "=r"(r2), "=r"(r3) : "r"(addr));
}
__device__ __forceinline__ void mma16816(float* c, const uint32_t* a, uint32_t b0, uint32_t b1) {
    asm volatile("mma.sync.aligned.m16n8k16.row.col.f32.bf16.bf16.f32 "
                 "{%0,%1,%2,%3}, {%4,%5,%6,%7}, {%8,%9}, {%0,%1,%2,%3};"
                 : "+f"(c[0]), "+f"(c[1]), "+f"(c[2]), "+f"(c[3])
                 : "r"(a[0]), "r"(a[1]), "r"(a[2]), "r"(a[3]), "r"(b0), "r"(b1));
}

// ---------------- pad input to [zp50][yp50][xp50][c128] fp32, voxel-major ----------------
__global__ void __launch_bounds__(256) pad_kernel(const float* __restrict__ feats) {
    __shared__ float tb[50][129];
    const int r = blockIdx.x;               // 2500 (zp,yp) rows
    const int zp = r / 50, yp = r % 50;
    const int zi = zp - 1, yi = yp - 1;
    const int tid = threadIdx.x;
    const int x = tid & 63, cq = tid >> 6;
    const int xi = x - 1;
    const bool rowok = (zi >= 0 && zi < 48 && yi >= 0 && yi < 48);
    const bool xok = rowok && (xi >= 0 && xi < 48);
#pragma unroll 4
    for (int i = 0; i < 32; ++i) {
        int c = cq * 32 + i;
        float v = 0.f;
        if (xok) {
            if (c < 125)       v = feats[(size_t)c * DHW + zi * HW + yi * 48 + xi];
            else if (c == 125) v = (2.0f / 47.0f) * (float)xi - 1.0f;
            else if (c == 126) v = (2.0f / 47.0f) * (float)yi - 1.0f;
            else               v = (2.0f / 47.0f) * (float)zi - 1.0f;
        }
        if (x < 50) tb[x][c] = v;
    }
    __syncthreads();
    float* dst = d_xp + (size_t)r * 50 * 128;
    for (int i = tid; i < 1600; i += 256) {
        int xr = i >> 5, c4 = (i & 31) * 4;
        float4 val = make_float4(tb[xr][c4], tb[xr][c4 + 1], tb[xr][c4 + 2], tb[xr][c4 + 3]);
        *(float4*)(dst + xr * 128 + c4) = val;
    }
}

// ---------------- Winograd weight transform ----------------
__device__ __forceinline__ void grow(int m, float* g) {
    if (m == 0)      { g[0] = 1.f;  g[1] = 0.f;   g[2] = 0.f; }
    else if (m == 1) { g[0] = 0.5f; g[1] = 0.5f;  g[2] = 0.5f; }
    else if (m == 2) { g[0] = 0.5f; g[1] = -0.5f; g[2] = 0.5f; }
    else             { g[0] = 0.f;  g[1] = 0.f;   g[2] = 1.f; }
}
__global__ void __launch_bounds__(128) wino_w_kernel(const float* __restrict__ W0) {
    const int mu = blockIdx.x >> 7, co = blockIdx.x & 127, ci = threadIdx.x;
    const int mz = mu >> 4, my = (mu >> 2) & 3, mx = mu & 3;
    float gz[3], gy[3], gx[3];
    grow(mz, gz); grow(my, gy); grow(mx, gx);
    const float* w = W0 + (size_t)(co * 128 + ci) * 27;
    float u = 0.f;
#pragma unroll
    for (int dz = 0; dz < 3; ++dz)
#pragma unroll
        for (int dy = 0; dy < 3; ++dy)
#pragma unroll
            for (int dx = 0; dx < 3; ++dx)
                u = fmaf(gz[dz] * gy[dy] * gx[dx], __ldg(w + dz * 9 + dy * 3 + dx), u);
    __nv_bfloat16 hi = __float2bfloat16(u);
    __nv_bfloat16 lo = __float2bfloat16(u - __bfloat162float(hi));
    __nv_bfloat16* rrow = d_wu + ((size_t)mu * 128 + co) * 384;
    rrow[ci] = hi; rrow[128 + ci] = hi; rrow[256 + ci] = lo;
}

// ---------------- Winograd input transform: 4 x-tiles per block, sliding window ----------------
__global__ void __launch_bounds__(128) wino_in_kernel() {
    __shared__ __nv_bfloat16 s[NMU * 256];   // 32 KB staging
    const int blk = blockIdx.x;              // 3456 = 24*24*6
    const int c = threadIdx.x;
    const int xg = blk % 6, yt = (blk / 6) % 24, zt = blk / 144;
    const int xt0 = xg * 4;
    const float* base = d_xp + ((size_t)((zt * 2) * 50 + yt * 2) * 50 + xt0 * 2) * 128 + c;

    float w[4][4][4];
#pragma unroll
    for (int z = 0; z < 4; ++z)
#pragma unroll
        for (int y = 0; y < 4; ++y)
#pragma unroll
            for (int x = 0; x < 4; ++x)
                w[z][y][x] = __ldg(base + ((z * 50 + y) * 50 + x) * 128);

    for (int t = 0; t < 4; ++t) {
        float d[4][4][4];
#pragma unroll
        for (int z = 0; z < 4; ++z)
#pragma unroll
            for (int y = 0; y < 4; ++y)
#pragma unroll
                for (int x = 0; x < 4; ++x) d[z][y][x] = w[z][y][x];
        // x-pass
#pragma unroll
        for (int z = 0; z < 4; ++z)
#pragma unroll
            for (int y = 0; y < 4; ++y) {
                float a0 = d[z][y][0], a1 = d[z][y][1], a2 = d[z][y][2], a3 = d[z][y][3];
                d[z][y][0] = a0 - a2; d[z][y][1] = a1 + a2; d[z][y][2] = a2 - a1; d[z][y][3] = a1 - a3;
            }
        // y-pass
#pragma unroll
        for (int z = 0; z < 4; ++z)
#pragma unroll
            for (int x = 0; x < 4; ++x) {
                float a0 = d[z][0][x], a1 = d[z][1][x], a2 = d[z][2][x], a3 = d[z][3][x];
                d[z][0][x] = a0 - a2; d[z][1][x] = a1 + a2; d[z][2][x] = a2 - a1; d[z][3][x] = a1 - a3;
            }
        // z-pass
#pragma unroll
        for (int y = 0; y < 4; ++y)
#pragma unroll
            for (int x = 0; x < 4; ++x) {
                float a0 = d[0][y][x], a1 = d[1][y][x], a2 = d[2][y][x], a3 = d[3][y][x];
                d[0][y][x] = a0 - a2; d[1][y][x] = a1 + a2; d[2][y][x] = a2 - a1; d[3][y][x] = a1 - a3;
            }
        // split to smem
#pragma unroll
        for (int mz = 0; mz < 4; ++mz)
#pragma unroll
            for (int my = 0; my < 4; ++my)
#pragma unroll
                for (int mx = 0; mx < 4; ++mx) {
                    int mu = mz * 16 + my * 4 + mx;
                    float v = d[mz][my][mx];
                    __nv_bfloat16 hi = __float2bfloat16(v);
                    s[mu * 256 + c] = hi;
                    s[mu * 256 + 128 + c] = __float2bfloat16(v - __bfloat162float(hi));
                }
        __syncthreads();
        {
            const int tile = zt * 576 + yt * 24 + xt0 + t;
            const float4* s4 = (const float4*)s;
            float4* dstA = (float4*)d_wA;
#pragma unroll
            for (int i = 0; i < 16; ++i) {
                int idx = i * 128 + c;
                int mu = idx >> 5, ch = idx & 31;
                dstA[((size_t)mu * NT + tile) * 32 + ch] = s4[idx];
            }
        }
        __syncthreads();
        if (t < 3) {
#pragma unroll
            for (int z = 0; z < 4; ++z)
#pragma unroll
                for (int y = 0; y < 4; ++y) {
                    w[z][y][0] = w[z][y][2];
                    w[z][y][1] = w[z][y][3];
                    w[z][y][2] = __ldg(base + ((z * 50 + y) * 50 + 2 * t + 4) * 128);
                    w[z][y][3] = __ldg(base + ((z * 50 + y) * 50 + 2 * t + 5) * 128);
                }
        }
    }
}

// ---------------- Winograd GEMM + x-direction output fold ----------------
// CTA: 128 thr, M=64 tiles, N=128 co, warp tile 32x64 (2m x 2n), fixed (mz,my).
// mx loop UNROLLED (compile-time fold signs); 6-step inner loop; 4-stage pipeline.
#define STG 24576
#define CONV_SMEM (4 * STG)     // 96 KB

__global__ void __launch_bounds__(128, 2) wino_gemm_kernel() {
    extern __shared__ char smem[];
    const uint32_t sb = smem_u32(smem);
    const int tid = threadIdx.x;
    const int tile0 = blockIdx.x * 64;     // 216 blocks
    const int mzmy = blockIdx.y;           // 16
    const int mu0 = mzmy * 4;

    auto load_stage = [&](int s) {
        const int mx = s / 6, sub = s - mx * 6;
        const int subm = (sub < 4) ? sub : sub - 4;
        const int koA = subm << 6;
        const uint32_t ab = sb + (s & 3) * STG;
        const __nv_bfloat16* Abase = d_wA + ((size_t)(mu0 + mx) * NT + tile0) * 256;
        const __nv_bfloat16* Bbase = d_wu + (size_t)(mu0 + mx) * 49152;
#pragma unroll
        for (int i = 0; i < 4; ++i) {
            const int idx = i * 128 + tid;
            const int row = idx >> 3, u = idx & 7;
            cp16(ab + row * 128 + ((u ^ (row & 7)) << 4),
                 Abase + (size_t)row * 256 + koA + u * 8);
        }
#pragma unroll
        for (int i = 0; i < 8; ++i) {
            const int idx = i * 128 + tid;
            const int row = idx >> 3, u = idx & 7;
            cp16(ab + 8192 + row * 128 + ((u ^ (row & 7)) << 4),
                 Bbase + (size_t)row * 384 + sub * 64 + u * 8);
        }
        cp_commit();
    };

    load_stage(0);
    load_stage(1);
    load_stage(2);

    const int wid = tid >> 5, lane = tid & 31;
    const int wm = wid >> 1, wn = wid & 1;       // 2m x 2n, warp tile 32x64
    const int rA = wm * 32 + (lane & 15);
    const int uA = lane >> 4;
    const int rB = wn * 64 + ((lane >> 4) << 3) + (lane & 7);
    const int uB = (lane >> 3) & 1;

    float acc[2][8][4], out0[2][8][4], out1[2][8][4];
#pragma unroll
    for (int i = 0; i < 2; ++i)
#pragma unroll
        for (int j = 0; j < 8; ++j)
#pragma unroll
            for (int k = 0; k < 4; ++k) { out0[i][j][k] = 0.f; out1[i][j][k] = 0.f; }

    auto compute = [&](float (&tgt)[2][8][4], int s) {
        const uint32_t As = sb + (s & 3) * STG;
        const uint32_t Bs = As + 8192;
#pragma unroll
        for (int k16 = 0; k16 < 4; ++k16) {
            uint32_t a[2][4], b4[4][4];
#pragma unroll
            for (int mt = 0; mt < 2; ++mt) {
                const int row = rA + mt * 16;
                ldsm4(As + row * 128 + (((k16 * 2 + uA) ^ (row & 7)) << 4),
                      a[mt][0], a[mt][1], a[mt][2], a[mt][3]);
            }
#pragma unroll
            for (int bt = 0; bt < 4; ++bt) {
                const int row = rB + bt * 16;
                ldsm4(Bs + row * 128 + (((k16 * 2 + uB) ^ (row & 7)) << 4),
                      b4[bt][0], b4[bt][1], b4[bt][2], b4[bt][3]);
            }
#pragma unroll
            for (int mt = 0; mt < 2; ++mt)
#pragma unroll
                for (int nt = 0; nt < 8; ++nt)
                    mma16816(tgt[mt][nt], a[mt], b4[nt >> 1][(nt & 1) * 2], b4[nt >> 1][(nt & 1) * 2 + 1]);
        }
    };

    auto pipe_step = [&](int s) {
        if (s <= 21)      asm volatile("cp.async.wait_group 2;");
        else if (s == 22) asm volatile("cp.async.wait_group 1;");
        else              asm volatile("cp.async.wait_group 0;");
        __syncthreads();
        if (s + 3 < 24) load_stage(s + 3);
    };

#pragma unroll
    for (int mx = 0; mx < 4; ++mx) {
        if (mx > 0) {
#pragma unroll
            for (int i = 0; i < 2; ++i)
#pragma unroll
                for (int j = 0; j < 8; ++j)
#pragma unroll
                    for (int k = 0; k < 4; ++k) acc[i][j][k] = 0.f;
        }
        for (int sub = 0; sub < 6; ++sub) {
            const int s = mx * 6 + sub;
            pipe_step(s);
            if (mx == 0) compute(out0, s);
            else         compute(acc, s);
        }
        // fold (compile-time signs): c0 = {1,1,1,0}, c1 = {0,1,-1,-1}
        if (mx == 1) {
#pragma unroll
            for (int i = 0; i < 2; ++i)
#pragma unroll
                for (int j = 0; j < 8; ++j)
#pragma unroll
                    for (int k = 0; k < 4; ++k) { out0[i][j][k] += acc[i][j][k]; out1[i][j][k] += acc[i][j][k]; }
        } else if (mx == 2) {
#pragma unroll
            for (int i = 0; i < 2; ++i)
#pragma unroll
                for (int j = 0; j < 8; ++j)
#pragma unroll
                    for (int k = 0; k < 4; ++k) { out0[i][j][k] += acc[i][j][k]; out1[i][j][k] -= acc[i][j][k]; }
        } else if (mx == 3) {
#pragma unroll
            for (int i = 0; i < 2; ++i)
#pragma unroll
                for (int j = 0; j < 8; ++j)
#pragma unroll
                    for (int k = 0; k < 4; ++k) { out1[i][j][k] -= acc[i][j][k]; }
        }
    }

    // write out0 -> xs=0, out1 -> xs=1
#pragma unroll
    for (int mt = 0; mt < 2; ++mt) {
#pragma unroll
        for (int half = 0; half < 2; ++half) {
            const int r = wm * 32 + mt * 16 + (lane >> 2) + half * 8;
            float* dst0 = d_V + ((size_t)(mzmy * 2 + 0) * NT + tile0 + r) * 128;
            float* dst1 = d_V + ((size_t)(mzmy * 2 + 1) * NT + tile0 + r) * 128;
#pragma unroll
            for (int nt = 0; nt < 8; ++nt) {
                const int n0 = wn * 64 + nt * 8 + (lane & 3) * 2;
                *(float2*)(dst0 + n0) = make_float2(out0[mt][nt][half * 2 + 0], out0[mt][nt][half * 2 + 1]);
                *(float2*)(dst1 + n0) = make_float2(out1[mt][nt][half * 2 + 0], out1[mt][nt][half * 2 + 1]);
            }
        }
    }
}

// ---------------- Winograd y,z output transform + bias + relu -> d_y2 ----------------
__global__ void __launch_bounds__(128) wino_out_kernel(const float* __restrict__ b0) {
    const int t = blockIdx.x;
    const int c = threadIdx.x;
    const int zt = t / 576, yt = (t / 24) % 24, xt = t % 24;
    const float* src = d_V + (size_t)t * 128 + c;
    float v[4][4][2];     // [mz][my][xs]
#pragma unroll
    for (int mz = 0; mz < 4; ++mz)
#pragma unroll
        for (int my = 0; my < 4; ++my)
#pragma unroll
            for (int xs = 0; xs < 2; ++xs)
                v[mz][my][xs] = __ldg(src + (size_t)((mz * 4 + my) * 2 + xs) * NT * 128);
    // y-pass
    float w[4][2][2];     // [mz][py][xs]
#pragma unroll
    for (int mz = 0; mz < 4; ++mz)
#pragma unroll
        for (int xs = 0; xs < 2; ++xs) {
            w[mz][0][xs] = v[mz][0][xs] + v[mz][1][xs] + v[mz][2][xs];
            w[mz][1][xs] = v[mz][1][xs] - v[mz][2][xs] - v[mz][3][xs];
        }
    // z-pass + write
    const float bias = __ldg(b0 + c);
#pragma unroll
    for (int py = 0; py < 2; ++py)
#pragma unroll
        for (int xs = 0; xs < 2; ++xs) {
            float o0 = w[0][py][xs] + w[1][py][xs] + w[2][py][xs];
            float o1 = w[1][py][xs] - w[2][py][xs] - w[3][py][xs];
            const int vz0 = (zt * 2) * HW + (yt * 2 + py) * 48 + xt * 2 + xs;
            d_y2[(size_t)vz0 * 128 + c] = fmaxf(o0 + bias, 0.f);
            d_y2[(size_t)(vz0 + HW) * 128 + c] = fmaxf(o1 + bias, 0.f);
        }
}

// ---------------- InstanceNorm stats (voxel-major) ----------------
__global__ void __launch_bounds__(128) stats_part_kernel() {
    const int blk = blockIdx.x;       // 432
    const int c = threadIdx.x;
    const float* p = d_y2 + (size_t)blk * 256 * 128 + c;
    float s = 0.f, s2 = 0.f;
#pragma unroll 4
    for (int i = 0; i < 256; ++i) {
        float v = p[(size_t)i * 128];
        s += v; s2 += v * v;
    }
    d_sp[blk * 256 + c] = s;
    d_sp[blk * 256 + 128 + c] = s2;
}
__global__ void __launch_bounds__(128) stats_fin_kernel() {
    const int c = threadIdx.x;
    float S = 0.f, S2 = 0.f;
    for (int b = 0; b < 432; ++b) {
        S  += d_sp[b * 256 + c];
        S2 += d_sp[b * 256 + 128 + c];
    }
    float mean = S * (1.0f / (float)DHW);
    float var  = S2 * (1.0f / (float)DHW) - mean * mean;
    d_mean[c] = mean;
    d_rstd[c] = rsqrtf(var + 1e-5f);
}

// ---------------- keypoint sampling: pre-swizzled split-bf16 B + norms ----------------
__global__ void __launch_bounds__(128) sample_kernel(const float* __restrict__ kpts) {
    const int n = blockIdx.x;
    const int c = threadIdx.x;
    __shared__ float pt[3];
    if (c < 3) pt[c] = kpts[n * 3 + c];
    __syncthreads();
    const float ix = (pt[0] + 1.0f) * 0.5f * 47.0f;
    const float iy = (pt[1] + 1.0f) * 0.5f * 47.0f;
    const float iz = (pt[2] + 1.0f) * 0.5f * 47.0f;
    const float x0f = floorf(ix), y0f = floorf(iy), z0f = floorf(iz);
    const float wx = ix - x0f, wy = iy - y0f, wz = iz - z0f;
    int x0 = min(max((int)x0f, 0), 47);
    int y0 = min(max((int)y0f, 0), 47);
    int z0 = min(max((int)z0f, 0), 47);
    int x1 = min(x0 + 1, 47), y1 = min(y0 + 1, 47), z1 = min(z0 + 1, 47);
    const float* vol = d_y2 + c;
    float c000 = vol[(size_t)(z0*HW + y0*48 + x0) * 128], c001 = vol[(size_t)(z0*HW + y0*48 + x1) * 128];
    float c010 = vol[(size_t)(z0*HW + y1*48 + x0) * 128], c011 = vol[(size_t)(z0*HW + y1*48 + x1) * 128];
    float c100 = vol[(size_t)(z1*HW + y0*48 + x0) * 128], c101 = vol[(size_t)(z1*HW + y0*48 + x1) * 128];
    float c110 = vol[(size_t)(z1*HW + y1*48 + x0) * 128], c111 = vol[(size_t)(z1*HW + y1*48 + x1) * 128];
    float v = c000*((1-wz)*(1-wy)*(1-wx)) + c001*((1-wz)*(1-wy)*wx)
            + c010*((1-wz)*wy*(1-wx))     + c011*((1-wz)*wy*wx)
            + c100*(wz*(1-wy)*(1-wx))     + c101*(wz*(1-wy)*wx)
            + c110*(wz*wy*(1-wx))         + c111*(wz*wy*wx);
    float f = (v - d_mean[c]) * d_rstd[c];

    float b = 2.0f * LOG2E * f;
    __nv_bfloat16 bh = __float2bfloat16(b);
    __nv_bfloat16 bl = __float2bfloat16(b - __bfloat162float(bh));
    const int chunk = n >> 5, row = n & 31;
    const int u = (c & 63) >> 3, j = c & 7, ph = c >> 6;
    char* fb = (char*)d_fkb;
    size_t base = (size_t)chunk * 24576 + (size_t)row * 128 + ((u ^ (row & 7)) << 4) + j * 2;
    *(__nv_bfloat16*)(fb + base + (0 + ph) * 4096) = bh;
    *(__nv_bfloat16*)(fb + base + (2 + ph) * 4096) = bh;
    *(__nv_bfloat16*)(fb + base + (4 + ph) * 4096) = bl;

    __shared__ float red[128];
    red[c] = f * f;
    __syncthreads();
    for (int o = 64; o > 0; o >>= 1) {
        if (c < o) red[c] += red[c + o];
        __syncthreads();
    }
    if (c == 0) d_nn[n] = LOG2E * red[0];
}

// ---------------- softmax interpolation via mma.sync ----------------
#define SMX_A    0
#define SMX_B    49152
#define SMX_NN   98304
#define SMX_DSM  100352
#define SMX_MEAN 108544
#define SMX_RSTD 109056
#define SMX_TOTAL 109568

__global__ void __launch_bounds__(128, 2) softmax_mma_kernel(const float* __restrict__ disp,
                                                             float* __restrict__ out) {
    extern __shared__ char sm[];
    const uint32_t sb = smem_u32(sm);
    const int tid = threadIdx.x;
    const int g0 = blockIdx.x * 64;

    float* nns = (float*)(sm + SMX_NN);
    float4* dsm4 = (float4*)(sm + SMX_DSM);
    for (int i = tid; i < NK; i += 128) {
        nns[i] = d_nn[i];
        float4 dv;
        dv.x = disp[i * 3]; dv.y = disp[i * 3 + 1]; dv.z = disp[i * 3 + 2]; dv.w = 0.f;
        dsm4[i] = dv;
    }
    ((float*)(sm + SMX_MEAN))[tid & 127] = d_mean[tid & 127];
    ((float*)(sm + SMX_RSTD))[tid & 127] = d_rstd[tid & 127];

    {
        const char* src = (const char*)d_fkb;
        for (int i = tid; i < 1536; i += 128) cp16(sb + SMX_B + i * 16, src + (size_t)i * 16);
        cp_commit();
    }
    __syncthreads();

    {
        const float* mean = (const float*)(sm + SMX_MEAN);
        const float* rstd = (const float*)(sm + SMX_RSTD);
        const int g = tid & 63, half = tid >> 6;
#pragma unroll
        for (int oct = 0; oct < 8; ++oct) {
            const int c0 = half * 64 + oct * 8;
            const float* srcp = d_y2 + (size_t)(g0 + g) * 128 + c0;
            float4 fa = *(const float4*)srcp;
            float4 fb4 = *(const float4*)(srcp + 4);
            float vv[8] = {fa.x, fa.y, fa.z, fa.w, fb4.x, fb4.y, fb4.z, fb4.w};
            union { __nv_bfloat16 h[8]; float4 v; } H, L;
#pragma unroll
            for (int j = 0; j < 8; ++j) {
                float a = (vv[j] - mean[c0 + j]) * rstd[c0 + j];
                __nv_bfloat16 hh = __float2bfloat16(a);
                H.h[j] = hh;
                L.h[j] = __float2bfloat16(a - __bfloat162float(hh));
            }
            const uint32_t sw = (uint32_t)((oct ^ (g & 7)) << 4);
            char* basep = sm + SMX_A + g * 128 + sw;
            *(float4*)(basep + (0 + half) * 8192) = H.v;
            *(float4*)(basep + (4 + half) * 8192) = H.v;
            *(float4*)(basep + (2 + half) * 8192) = L.v;
        }
    }
    __syncthreads();

    const int wid = tid >> 5, lane = tid & 31;
    const int rA = wid * 16 + (lane & 15);
    const int uA = lane >> 4;
    const int rB0 = ((lane >> 4) << 3) + (lane & 7);
    const int uBb = (lane >> 3) & 1;

    float mlo = -1e30f, mhi = -1e30f;
    float Slo = 0.f, Shi = 0.f;
    float Wlo0 = 0.f, Wlo1 = 0.f, Wlo2 = 0.f;
    float Whi0 = 0.f, Whi1 = 0.f, Whi2 = 0.f;

    for (int ci = 0; ci < 16; ++ci) {
        asm volatile("cp.async.wait_group 0;");
        __syncthreads();
        if (ci < 15) {
            const char* src = (const char*)d_fkb + (size_t)(ci + 1) * 24576;
            const uint32_t dst = sb + SMX_B + ((ci + 1) & 1) * 24576;
            for (int i = tid; i < 1536; i += 128) cp16(dst + i * 16, src + (size_t)i * 16);
            cp_commit();
        }
        const uint32_t Bb = sb + SMX_B + (ci & 1) * 24576;
        const int nbase = ci * 32;

        float acc[4][4];
#pragma unroll
        for (int nt = 0; nt < 4; ++nt) {
            float i0 = -nns[nbase + nt * 8 + (lane & 3) * 2];
            float i1 = -nns[nbase + nt * 8 + (lane & 3) * 2 + 1];
            acc[nt][0] = i0; acc[nt][1] = i1; acc[nt][2] = i0; acc[nt][3] = i1;
        }
#pragma unroll
        for (int s = 0; s < 24; ++s) {
            const int pan = s >> 2, inner = s & 3;
            uint32_t a[4];
            ldsm4(sb + SMX_A + pan * 8192 + rA * 128 + (((inner * 2 + uA) ^ (rA & 7)) << 4),
                  a[0], a[1], a[2], a[3]);
            uint32_t b4[2][4];
#pragma unroll
            for (int bt = 0; bt < 2; ++bt) {
                const int row = bt * 16 + rB0;
                ldsm4(Bb + pan * 4096 + row * 128 + (((inner * 2 + uBb) ^ (row & 7)) << 4),
                      b4[bt][0], b4[bt][1], b4[bt][2], b4[bt][3]);
            }
#pragma unroll
            for (int nt = 0; nt < 4; ++nt)
                mma16816(acc[nt], a, b4[nt >> 1][(nt & 1) * 2], b4[nt >> 1][(nt & 1) * 2 + 1]);
        }

        float cmlo = fmaxf(fmaxf(fmaxf(acc[0][0], acc[0][1]), fmaxf(acc[1][0], acc[1][1])),
                           fmaxf(fmaxf(acc[2][0], acc[2][1]), fmaxf(acc[3][0], acc[3][1])));
        float cmhi = fmaxf(fmaxf(fmaxf(acc[0][2], acc[0][3]), fmaxf(acc[1][2], acc[1][3])),
                           fmaxf(fmaxf(acc[2][2], acc[2][3]), fmaxf(acc[3][2], acc[3][3])));
        cmlo = fmaxf(cmlo, __shfl_xor_sync(0xffffffffu, cmlo, 1));
        cmlo = fmaxf(cmlo, __shfl_xor_sync(0xffffffffu, cmlo, 2));
        cmhi = fmaxf(cmhi, __shfl_xor_sync(0xffffffffu, cmhi, 1));
        cmhi = fmaxf(cmhi, __shfl_xor_sync(0xffffffffu, cmhi, 2));
        if (cmlo > mlo) {
            float cs = exp2a(mlo - cmlo);
            Slo *= cs; Wlo0 *= cs; Wlo1 *= cs; Wlo2 *= cs;
            mlo = cmlo;
        }
        if (cmhi > mhi) {
            float cs = exp2a(mhi - cmhi);
            Shi *= cs; Whi0 *= cs; Whi1 *= cs; Whi2 *= cs;
            mhi = cmhi;
        }
#pragma unroll
        for (int nt = 0; nt < 4; ++nt) {
#pragma unroll
            for (int j = 0; j < 2; ++j) {
                const float4 dv = dsm4[nbase + nt * 8 + (lane & 3) * 2 + j];
                float elo = exp2a(acc[nt][j] - mlo);
                float ehi = exp2a(acc[nt][2 + j] - mhi);
                Slo += elo; Shi += ehi;
                Wlo0 = fmaf(elo, dv.x, Wlo0); Wlo1 = fmaf(elo, dv.y, Wlo1); Wlo2 = fmaf(elo, dv.z, Wlo2);
                Whi0 = fmaf(ehi, dv.x, Whi0); Whi1 = fmaf(ehi, dv.y, Whi1); Whi2 = fmaf(ehi, dv.z, Whi2);
            }
        }
    }

#pragma unroll
    for (int d = 1; d <= 2; d <<= 1) {
        Slo += __shfl_xor_sync(0xffffffffu, Slo, d);
        Shi += __shfl_xor_sync(0xffffffffu, Shi, d);
        Wlo0 += __shfl_xor_sync(0xffffffffu, Wlo0, d);
        Wlo1 += __shfl_xor_sync(0xffffffffu, Wlo1, d);
        Wlo2 += __shfl_xor_sync(0xffffffffu, Wlo2, d);
        Whi0 += __shfl_xor_sync(0xffffffffu, Whi0, d);
        Whi1 += __shfl_xor_sync(0xffffffffu, Whi1, d);
        Whi2 += __shfl_xor_sync(0xffffffffu, Whi2, d);
    }
    if ((lane & 3) == 0) {
        const int rlo = g0 + wid * 16 + (lane >> 2);
        const int rhi = rlo + 8;
        const float ilo = 1.0f / Slo, ihi = 1.0f / Shi;
        out[0 * DHW + rlo] = Wlo0 * ilo;
        out[1 * DHW + rlo] = Wlo1 * ilo;
        out[2 * DHW + rlo] = Wlo2 * ilo;
        out[0 * DHW + rhi] = Whi0 * ihi;
        out[1 * DHW + rhi] = Whi1 * ihi;
        out[2 * DHW + rhi] = Whi2 * ihi;
    }
}

// ---------------- launch ----------------
extern "C" void kernel_launch(void* const* d_in, const int* in_sizes, int n_in,
                              void* d_out, int out_size) {
    const float* kpts  = (const float*)d_in[0];
    const float* disp  = (const float*)d_in[1];
    const float* feats = (const float*)d_in[2];
    const float* W0    = (const float*)d_in[3];
    const float* b0    = (const float*)d_in[4];
    float* out = (float*)d_out;

    static int attr_done = 0;
    if (!attr_done) {
        cudaFuncSetAttribute(wino_gemm_kernel, cudaFuncAttributeMaxDynamicSharedMemorySize, CONV_SMEM);
        cudaFuncSetAttribute(softmax_mma_kernel, cudaFuncAttributeMaxDynamicSharedMemorySize, SMX_TOTAL);
        attr_done = 1;
    }

    pad_kernel<<<2500, 256>>>(feats);
    wino_w_kernel<<<8192, 128>>>(W0);
    wino_in_kernel<<<3456, 128>>>();
    wino_gemm_kernel<<<dim3(216, 16), 128, CONV_SMEM>>>();
    wino_out_kernel<<<NT, 128>>>(b0);
    stats_part_kernel<<<432, 128>>>();
    stats_fin_kernel<<<1, 128>>>();
    sample_kernel<<<NK, 128>>>(kpts);
    softmax_mma_kernel<<<DHW / 64, 128, SMX_TOTAL>>>(disp, out);
}

// round 13
// speedup vs baseline: 1.1106x; 1.0394x over previous
#include <cuda_runtime.h>
#include <cuda_bf16.h>
#include <cstdint>

#define DD   48
#define HW   2304
#define DHW  110592
#define NK   512
#define LOG2E 1.4426950408889634f
#define NT   13824            // 24^3 Winograd tiles
#define NMU  64

// ---------------- device scratch ----------------
__device__ float d_xp[50 * 50 * 50 * 128];                          // padded input, voxel-major
__device__ __align__(16) __nv_bfloat16 d_wA[(size_t)NMU * NT * 256]; // transformed input [mu][tile][hi128|lo128]
__device__ __align__(16) __nv_bfloat16 d_wu[NMU * 128 * 256];        // transformed weights [mu][co][bhi128|blo128]
__device__ float d_V[(size_t)32 * NT * 128];                         // x-folded GEMM out [mzmy*2+xs][tile][co]
__device__ float d_y2[(size_t)DHW * 128];                            // conv out voxel-major [voxel][c]
__device__ __align__(16) __nv_bfloat16 d_fkb[16 * 12288];            // keypoint feats, pre-swizzled
__device__ float d_sp[432 * 256];
__device__ float d_mean[128];
__device__ float d_rstd[128];
__device__ float d_nn[NK];

__device__ __forceinline__ float exp2a(float x) {
    float r; asm("ex2.approx.ftz.f32 %0, %1;" : "=f"(r) : "f"(x)); return r;
}
__device__ __forceinline__ uint32_t smem_u32(const void* p) {
    uint32_t a;
    asm("{ .reg .u64 t; cvta.to.shared.u64 t, %1; cvt.u32.u64 %0, t; }" : "=r"(a) : "l"(p));
    return a;
}
__device__ __forceinline__ void cp16(uint32_t dst, const void* src) {
    asm volatile("cp.async.cg.shared.global [%0], [%1], 16;" :: "r"(dst), "l"(src));
}
__device__ __forceinline__ void cp_commit() { asm volatile("cp.async.commit_group;"); }
__device__ __forceinline__ void ldsm4(uint32_t addr, uint32_t& r0, uint32_t& r1, uint32_t& r2, uint32_t& r3) {
    asm volatile("ldmatrix.sync.aligned.m8n8.x4.shared.b16 {%0,%1,%2,%3}, [%4];"
                 : "=r"(r0), "=r"(r1), "=r"(r2), "=r"(r3) : "r"(addr));
}
__device__ __forceinline__ void mma16816(float* c, const uint32_t* a, uint32_t b0, uint32_t b1) {
    asm volatile("mma.sync.aligned.m16n8k16.row.col.f32.bf16.bf16.f32 "
                 "{%0,%1,%2,%3}, {%4,%5,%6,%7}, {%8,%9}, {%0,%1,%2,%3};"
                 : "+f"(c[0]), "+f"(c[1]), "+f"(c[2]), "+f"(c[3])
                 : "r"(a[0]), "r"(a[1]), "r"(a[2]), "r"(a[3]), "r"(b0), "r"(b1));
}

// ---------------- pad input to [zp50][yp50][xp50][c128] fp32, voxel-major ----------------
__global__ void __launch_bounds__(256) pad_kernel(const float* __restrict__ feats) {
    __shared__ float tb[50][129];
    const int r = blockIdx.x;               // 2500 (zp,yp) rows
    const int zp = r / 50, yp = r % 50;
    const int zi = zp - 1, yi = yp - 1;
    const int tid = threadIdx.x;
    const int x = tid & 63, cq = tid >> 6;
    const int xi = x - 1;
    const bool rowok = (zi >= 0 && zi < 48 && yi >= 0 && yi < 48);
    const bool xok = rowok && (xi >= 0 && xi < 48);
#pragma unroll 4
    for (int i = 0; i < 32; ++i) {
        int c = cq * 32 + i;
        float v = 0.f;
        if (xok) {
            if (c < 125)       v = feats[(size_t)c * DHW + zi * HW + yi * 48 + xi];
            else if (c == 125) v = (2.0f / 47.0f) * (float)xi - 1.0f;
            else if (c == 126) v = (2.0f / 47.0f) * (float)yi - 1.0f;
            else               v = (2.0f / 47.0f) * (float)zi - 1.0f;
        }
        if (x < 50) tb[x][c] = v;
    }
    __syncthreads();
    float* dst = d_xp + (size_t)r * 50 * 128;
    for (int i = tid; i < 1600; i += 256) {
        int xr = i >> 5, c4 = (i & 31) * 4;
        float4 val = make_float4(tb[xr][c4], tb[xr][c4 + 1], tb[xr][c4 + 2], tb[xr][c4 + 3]);
        *(float4*)(dst + xr * 128 + c4) = val;
    }
}

// ---------------- Winograd weight transform -> [mu][co][bhi128|blo128] ----------------
__device__ __forceinline__ void grow(int m, float* g) {
    if (m == 0)      { g[0] = 1.f;  g[1] = 0.f;   g[2] = 0.f; }
    else if (m == 1) { g[0] = 0.5f; g[1] = 0.5f;  g[2] = 0.5f; }
    else if (m == 2) { g[0] = 0.5f; g[1] = -0.5f; g[2] = 0.5f; }
    else             { g[0] = 0.f;  g[1] = 0.f;   g[2] = 1.f; }
}
__global__ void __launch_bounds__(128) wino_w_kernel(const float* __restrict__ W0) {
    const int mu = blockIdx.x >> 7, co = blockIdx.x & 127, ci = threadIdx.x;
    const int mz = mu >> 4, my = (mu >> 2) & 3, mx = mu & 3;
    float gz[3], gy[3], gx[3];
    grow(mz, gz); grow(my, gy); grow(mx, gx);
    const float* w = W0 + (size_t)(co * 128 + ci) * 27;
    float u = 0.f;
#pragma unroll
    for (int dz = 0; dz < 3; ++dz)
#pragma unroll
        for (int dy = 0; dy < 3; ++dy)
#pragma unroll
            for (int dx = 0; dx < 3; ++dx)
                u = fmaf(gz[dz] * gy[dy] * gx[dx], __ldg(w + dz * 9 + dy * 3 + dx), u);
    __nv_bfloat16 hi = __float2bfloat16(u);
    __nv_bfloat16 lo = __float2bfloat16(u - __bfloat162float(hi));
    __nv_bfloat16* rrow = d_wu + ((size_t)mu * 128 + co) * 256;
    rrow[ci] = hi; rrow[128 + ci] = lo;
}

// ---------------- Winograd input transform: 4 x-tiles per block, sliding window ----------------
__global__ void __launch_bounds__(128) wino_in_kernel() {
    __shared__ __nv_bfloat16 s[NMU * 256];   // 32 KB staging
    const int blk = blockIdx.x;              // 3456 = 24*24*6
    const int c = threadIdx.x;
    const int xg = blk % 6, yt = (blk / 6) % 24, zt = blk / 144;
    const int xt0 = xg * 4;
    const float* base = d_xp + ((size_t)((zt * 2) * 50 + yt * 2) * 50 + xt0 * 2) * 128 + c;

    float w[4][4][4];
#pragma unroll
    for (int z = 0; z < 4; ++z)
#pragma unroll
        for (int y = 0; y < 4; ++y)
#pragma unroll
            for (int x = 0; x < 4; ++x)
                w[z][y][x] = __ldg(base + ((z * 50 + y) * 50 + x) * 128);

    for (int t = 0; t < 4; ++t) {
        float d[4][4][4];
#pragma unroll
        for (int z = 0; z < 4; ++z)
#pragma unroll
            for (int y = 0; y < 4; ++y)
#pragma unroll
                for (int x = 0; x < 4; ++x) d[z][y][x] = w[z][y][x];
        // x-pass
#pragma unroll
        for (int z = 0; z < 4; ++z)
#pragma unroll
            for (int y = 0; y < 4; ++y) {
                float a0 = d[z][y][0], a1 = d[z][y][1], a2 = d[z][y][2], a3 = d[z][y][3];
                d[z][y][0] = a0 - a2; d[z][y][1] = a1 + a2; d[z][y][2] = a2 - a1; d[z][y][3] = a1 - a3;
            }
        // y-pass
#pragma unroll
        for (int z = 0; z < 4; ++z)
#pragma unroll
            for (int x = 0; x < 4; ++x) {
                float a0 = d[z][0][x], a1 = d[z][1][x], a2 = d[z][2][x], a3 = d[z][3][x];
                d[z][0][x] = a0 - a2; d[z][1][x] = a1 + a2; d[z][2][x] = a2 - a1; d[z][3][x] = a1 - a3;
            }
        // z-pass
#pragma unroll
        for (int y = 0; y < 4; ++y)
#pragma unroll
            for (int x = 0; x < 4; ++x) {
                float a0 = d[0][y][x], a1 = d[1][y][x], a2 = d[2][y][x], a3 = d[3][y][x];
                d[0][y][x] = a0 - a2; d[1][y][x] = a1 + a2; d[2][y][x] = a2 - a1; d[3][y][x] = a1 - a3;
            }
        // split to smem
#pragma unroll
        for (int mz = 0; mz < 4; ++mz)
#pragma unroll
            for (int my = 0; my < 4; ++my)
#pragma unroll
                for (int mx = 0; mx < 4; ++mx) {
                    int mu = mz * 16 + my * 4 + mx;
                    float v = d[mz][my][mx];
                    __nv_bfloat16 hi = __float2bfloat16(v);
                    s[mu * 256 + c] = hi;
                    s[mu * 256 + 128 + c] = __float2bfloat16(v - __bfloat162float(hi));
                }
        __syncthreads();
        {
            const int tile = zt * 576 + yt * 24 + xt0 + t;
            const float4* s4 = (const float4*)s;
            float4* dstA = (float4*)d_wA;
#pragma unroll
            for (int i = 0; i < 16; ++i) {
                int idx = i * 128 + c;
                int mu = idx >> 5, ch = idx & 31;
                dstA[((size_t)mu * NT + tile) * 32 + ch] = s4[idx];
            }
        }
        __syncthreads();
        if (t < 3) {
#pragma unroll
            for (int z = 0; z < 4; ++z)
#pragma unroll
                for (int y = 0; y < 4; ++y) {
                    w[z][y][0] = w[z][y][2];
                    w[z][y][1] = w[z][y][3];
                    w[z][y][2] = __ldg(base + ((z * 50 + y) * 50 + 2 * t + 4) * 128);
                    w[z][y][3] = __ldg(base + ((z * 50 + y) * 50 + 2 * t + 5) * 128);
                }
        }
    }
}

// ---------------- Winograd GEMM + x-direction output fold ----------------
// CTA: 128 thr, M=64 tiles, N=128 co, warp tile 32x64 (2m x 2n), fixed (mz,my).
// Half-mu stages: stage h = (mu = h>>1, p = h&1) holds {A_hi(p), A_lo(p), B_hi(p), B_lo(p)}.
// One pass computes hi*bh + lo*bh + hi*bl with frags resident. Ring depth 2.
#define STG 49152               // A 16KB + B 32KB
#define CONV_SMEM (2 * STG)     // 96 KB

__global__ void __launch_bounds__(128, 2) wino_gemm_kernel() {
    extern __shared__ char smem[];
    const uint32_t sb = smem_u32(smem);
    const int tid = threadIdx.x;
    const int tile0 = blockIdx.x * 64;     // 216 blocks
    const int mzmy = blockIdx.y;           // 16
    const int mu0 = mzmy * 4;

    auto load_stage = [&](int h) {
        const int mu = h >> 1, p = h & 1;
        const uint32_t ab = sb + (h & 1) * STG;
        const __nv_bfloat16* Abase = d_wA + ((size_t)(mu0 + mu) * NT + tile0) * 256;
        const __nv_bfloat16* Bbase = d_wu + (size_t)(mu0 + mu) * 32768;
        // A: chunks {p, p+2} (hi(p), lo(p)), 64 rows x 128B each
#pragma unroll
        for (int i = 0; i < 8; ++i) {
            const int idx = i * 128 + tid;            // 0..1023
            const int chunk = idx >> 9;
            const int row = (idx >> 3) & 63;
            const int u = idx & 7;
            cp16(ab + chunk * 8192 + row * 128 + ((u ^ (row & 7)) << 4),
                 Abase + (size_t)row * 256 + (p + 2 * chunk) * 64 + u * 8);
        }
        // B: slices {bhi(p), blo(p)}, each 128 rows x 128B
#pragma unroll
        for (int i = 0; i < 16; ++i) {
            const int idx = i * 128 + tid;            // 0..2047
            const int half = idx >> 10;
            const int row = (idx >> 3) & 127;
            const int u = idx & 7;
            cp16(ab + 16384 + half * 16384 + row * 128 + ((u ^ (row & 7)) << 4),
                 Bbase + (size_t)row * 256 + half * 128 + p * 64 + u * 8);
        }
        cp_commit();
    };

    load_stage(0);
    load_stage(1);

    const int wid = tid >> 5, lane = tid & 31;
    const int wm = wid >> 1, wn = wid & 1;       // 2m x 2n, warp tile 32x64
    const int rA = wm * 32 + (lane & 15);
    const int uA = lane >> 4;
    const int rB = wn * 64 + ((lane >> 4) << 3) + (lane & 7);
    const int uB = (lane >> 3) & 1;

    float acc[2][8][4], out0[2][8][4], out1[2][8][4];
#pragma unroll
    for (int i = 0; i < 2; ++i)
#pragma unroll
        for (int j = 0; j < 8; ++j)
#pragma unroll
            for (int k = 0; k < 4; ++k) { out0[i][j][k] = 0.f; out1[i][j][k] = 0.f; }

    auto compute = [&](float (&tgt)[2][8][4], int h) {
        const uint32_t Ahi = sb + (h & 1) * STG;
        const uint32_t Alo = Ahi + 8192;
        const uint32_t Bh  = Ahi + 16384;
        const uint32_t Bl  = Ahi + 32768;
#pragma unroll
        for (int k16 = 0; k16 < 4; ++k16) {
            uint32_t ah[2][4], al[2][4], bh[4][4], bl[4][4];
#pragma unroll
            for (int mt = 0; mt < 2; ++mt) {
                const int row = rA + mt * 16;
                const uint32_t off = row * 128 + (((k16 * 2 + uA) ^ (row & 7)) << 4);
                ldsm4(Ahi + off, ah[mt][0], ah[mt][1], ah[mt][2], ah[mt][3]);
                ldsm4(Alo + off, al[mt][0], al[mt][1], al[mt][2], al[mt][3]);
            }
#pragma unroll
            for (int bt = 0; bt < 4; ++bt) {
                const int row = rB + bt * 16;
                const uint32_t off = row * 128 + (((k16 * 2 + uB) ^ (row & 7)) << 4);
                ldsm4(Bh + off, bh[bt][0], bh[bt][1], bh[bt][2], bh[bt][3]);
                ldsm4(Bl + off, bl[bt][0], bl[bt][1], bl[bt][2], bl[bt][3]);
            }
#pragma unroll
            for (int mt = 0; mt < 2; ++mt)
#pragma unroll
                for (int nt = 0; nt < 8; ++nt) {
                    uint32_t h0 = bh[nt >> 1][(nt & 1) * 2], h1 = bh[nt >> 1][(nt & 1) * 2 + 1];
                    mma16816(tgt[mt][nt], ah[mt], h0, h1);
                    mma16816(tgt[mt][nt], al[mt], h0, h1);
                    mma16816(tgt[mt][nt], ah[mt], bl[nt >> 1][(nt & 1) * 2], bl[nt >> 1][(nt & 1) * 2 + 1]);
                }
        }
    };

#pragma unroll
    for (int mx = 0; mx < 4; ++mx) {
        if (mx > 0) {
#pragma unroll
            for (int i = 0; i < 2; ++i)
#pragma unroll
                for (int j = 0; j < 8; ++j)
#pragma unroll
                    for (int k = 0; k < 4; ++k) acc[i][j][k] = 0.f;
        }
#pragma unroll
        for (int ph = 0; ph < 2; ++ph) {
            const int h = mx * 2 + ph;
            if (h < 7) asm volatile("cp.async.wait_group 1;");
            else       asm volatile("cp.async.wait_group 0;");
            __syncthreads();
            if (mx == 0) compute(out0, h);
            else         compute(acc, h);
            __syncthreads();
            if (h + 2 < 8) load_stage(h + 2);
        }
        // fold (compile-time signs): c0 = {1,1,1,0}, c1 = {0,1,-1,-1}
        if (mx == 1) {
#pragma unroll
            for (int i = 0; i < 2; ++i)
#pragma unroll
                for (int j = 0; j < 8; ++j)
#pragma unroll
                    for (int k = 0; k < 4; ++k) { out0[i][j][k] += acc[i][j][k]; out1[i][j][k] += acc[i][j][k]; }
        } else if (mx == 2) {
#pragma unroll
            for (int i = 0; i < 2; ++i)
#pragma unroll
                for (int j = 0; j < 8; ++j)
#pragma unroll
                    for (int k = 0; k < 4; ++k) { out0[i][j][k] += acc[i][j][k]; out1[i][j][k] -= acc[i][j][k]; }
        } else if (mx == 3) {
#pragma unroll
            for (int i = 0; i < 2; ++i)
#pragma unroll
                for (int j = 0; j < 8; ++j)
#pragma unroll
                    for (int k = 0; k < 4; ++k) { out1[i][j][k] -= acc[i][j][k]; }
        }
    }

    // write out0 -> xs=0, out1 -> xs=1
#pragma unroll
    for (int mt = 0; mt < 2; ++mt) {
#pragma unroll
        for (int half = 0; half < 2; ++half) {
            const int r = wm * 32 + mt * 16 + (lane >> 2) + half * 8;
            float* dst0 = d_V + ((size_t)(mzmy * 2 + 0) * NT + tile0 + r) * 128;
            float* dst1 = d_V + ((size_t)(mzmy * 2 + 1) * NT + tile0 + r) * 128;
#pragma unroll
            for (int nt = 0; nt < 8; ++nt) {
                const int n0 = wn * 64 + nt * 8 + (lane & 3) * 2;
                *(float2*)(dst0 + n0) = make_float2(out0[mt][nt][half * 2 + 0], out0[mt][nt][half * 2 + 1]);
                *(float2*)(dst1 + n0) = make_float2(out1[mt][nt][half * 2 + 0], out1[mt][nt][half * 2 + 1]);
            }
        }
    }
}

// ---------------- Winograd y,z output transform + bias + relu -> d_y2 ----------------
__global__ void __launch_bounds__(128) wino_out_kernel(const float* __restrict__ b0) {
    const int t = blockIdx.x;
    const int c = threadIdx.x;
    const int zt = t / 576, yt = (t / 24) % 24, xt = t % 24;
    const float* src = d_V + (size_t)t * 128 + c;
    float v[4][4][2];     // [mz][my][xs]
#pragma unroll
    for (int mz = 0; mz < 4; ++mz)
#pragma unroll
        for (int my = 0; my < 4; ++my)
#pragma unroll
            for (int xs = 0; xs < 2; ++xs)
                v[mz][my][xs] = __ldg(src + (size_t)((mz * 4 + my) * 2 + xs) * NT * 128);
    // y-pass
    float w[4][2][2];     // [mz][py][xs]
#pragma unroll
    for (int mz = 0; mz < 4; ++mz)
#pragma unroll
        for (int xs = 0; xs < 2; ++xs) {
            w[mz][0][xs] = v[mz][0][xs] + v[mz][1][xs] + v[mz][2][xs];
            w[mz][1][xs] = v[mz][1][xs] - v[mz][2][xs] - v[mz][3][xs];
        }
    // z-pass + write
    const float bias = __ldg(b0 + c);
#pragma unroll
    for (int py = 0; py < 2; ++py)
#pragma unroll
        for (int xs = 0; xs < 2; ++xs) {
            float o0 = w[0][py][xs] + w[1][py][xs] + w[2][py][xs];
            float o1 = w[1][py][xs] - w[2][py][xs] - w[3][py][xs];
            const int vz0 = (zt * 2) * HW + (yt * 2 + py) * 48 + xt * 2 + xs;
            d_y2[(size_t)vz0 * 128 + c] = fmaxf(o0 + bias, 0.f);
            d_y2[(size_t)(vz0 + HW) * 128 + c] = fmaxf(o1 + bias, 0.f);
        }
}

// ---------------- InstanceNorm stats (voxel-major) ----------------
__global__ void __launch_bounds__(128) stats_part_kernel() {
    const int blk = blockIdx.x;       // 432
    const int c = threadIdx.x;
    const float* p = d_y2 + (size_t)blk * 256 * 128 + c;
    float s = 0.f, s2 = 0.f;
#pragma unroll 4
    for (int i = 0; i < 256; ++i) {
        float v = p[(size_t)i * 128];
        s += v; s2 += v * v;
    }
    d_sp[blk * 256 + c] = s;
    d_sp[blk * 256 + 128 + c] = s2;
}
__global__ void __launch_bounds__(128) stats_fin_kernel() {
    const int c = threadIdx.x;
    float S = 0.f, S2 = 0.f;
    for (int b = 0; b < 432; ++b) {
        S  += d_sp[b * 256 + c];
        S2 += d_sp[b * 256 + 128 + c];
    }
    float mean = S * (1.0f / (float)DHW);
    float var  = S2 * (1.0f / (float)DHW) - mean * mean;
    d_mean[c] = mean;
    d_rstd[c] = rsqrtf(var + 1e-5f);
}

// ---------------- keypoint sampling: pre-swizzled split-bf16 B + norms ----------------
__global__ void __launch_bounds__(128) sample_kernel(const float* __restrict__ kpts) {
    const int n = blockIdx.x;
    const int c = threadIdx.x;
    __shared__ float pt[3];
    if (c < 3) pt[c] = kpts[n * 3 + c];
    __syncthreads();
    const float ix = (pt[0] + 1.0f) * 0.5f * 47.0f;
    const float iy = (pt[1] + 1.0f) * 0.5f * 47.0f;
    const float iz = (pt[2] + 1.0f) * 0.5f * 47.0f;
    const float x0f = floorf(ix), y0f = floorf(iy), z0f = floorf(iz);
    const float wx = ix - x0f, wy = iy - y0f, wz = iz - z0f;
    int x0 = min(max((int)x0f, 0), 47);
    int y0 = min(max((int)y0f, 0), 47);
    int z0 = min(max((int)z0f, 0), 47);
    int x1 = min(x0 + 1, 47), y1 = min(y0 + 1, 47), z1 = min(z0 + 1, 47);
    const float* vol = d_y2 + c;
    float c000 = vol[(size_t)(z0*HW + y0*48 + x0) * 128], c001 = vol[(size_t)(z0*HW + y0*48 + x1) * 128];
    float c010 = vol[(size_t)(z0*HW + y1*48 + x0) * 128], c011 = vol[(size_t)(z0*HW + y1*48 + x1) * 128];
    float c100 = vol[(size_t)(z1*HW + y0*48 + x0) * 128], c101 = vol[(size_t)(z1*HW + y0*48 + x1) * 128];
    float c110 = vol[(size_t)(z1*HW + y1*48 + x0) * 128], c111 = vol[(size_t)(z1*HW + y1*48 + x1) * 128];
    float v = c000*((1-wz)*(1-wy)*(1-wx)) + c001*((1-wz)*(1-wy)*wx)
            + c010*((1-wz)*wy*(1-wx))     + c011*((1-wz)*wy*wx)
            + c100*(wz*(1-wy)*(1-wx))     + c101*(wz*(1-wy)*wx)
            + c110*(wz*wy*(1-wx))         + c111*(wz*wy*wx);
    float f = (v - d_mean[c]) * d_rstd[c];

    float b = 2.0f * LOG2E * f;
    __nv_bfloat16 bh = __float2bfloat16(b);
    __nv_bfloat16 bl = __float2bfloat16(b - __bfloat162float(bh));
    const int chunk = n >> 5, row = n & 31;
    const int u = (c & 63) >> 3, j = c & 7, ph = c >> 6;
    char* fb = (char*)d_fkb;
    size_t base = (size_t)chunk * 24576 + (size_t)row * 128 + ((u ^ (row & 7)) << 4) + j * 2;
    *(__nv_bfloat16*)(fb + base + (0 + ph) * 4096) = bh;
    *(__nv_bfloat16*)(fb + base + (2 + ph) * 4096) = bh;
    *(__nv_bfloat16*)(fb + base + (4 + ph) * 4096) = bl;

    __shared__ float red[128];
    red[c] = f * f;
    __syncthreads();
    for (int o = 64; o > 0; o >>= 1) {
        if (c < o) red[c] += red[c + o];
        __syncthreads();
    }
    if (c == 0) d_nn[n] = LOG2E * red[0];
}

// ---------------- softmax interpolation via mma.sync ----------------
#define SMX_A    0
#define SMX_B    49152
#define SMX_NN   98304
#define SMX_DSM  100352
#define SMX_MEAN 108544
#define SMX_RSTD 109056
#define SMX_TOTAL 109568

__global__ void __launch_bounds__(128, 2) softmax_mma_kernel(const float* __restrict__ disp,
                                                             float* __restrict__ out) {
    extern __shared__ char sm[];
    const uint32_t sb = smem_u32(sm);
    const int tid = threadIdx.x;
    const int g0 = blockIdx.x * 64;

    float* nns = (float*)(sm + SMX_NN);
    float4* dsm4 = (float4*)(sm + SMX_DSM);
    for (int i = tid; i < NK; i += 128) {
        nns[i] = d_nn[i];
        float4 dv;
        dv.x = disp[i * 3]; dv.y = disp[i * 3 + 1]; dv.z = disp[i * 3 + 2]; dv.w = 0.f;
        dsm4[i] = dv;
    }
    ((float*)(sm + SMX_MEAN))[tid & 127] = d_mean[tid & 127];
    ((float*)(sm + SMX_RSTD))[tid & 127] = d_rstd[tid & 127];

    {
        const char* src = (const char*)d_fkb;
        for (int i = tid; i < 1536; i += 128) cp16(sb + SMX_B + i * 16, src + (size_t)i * 16);
        cp_commit();
    }
    __syncthreads();

    {
        const float* mean = (const float*)(sm + SMX_MEAN);
        const float* rstd = (const float*)(sm + SMX_RSTD);
        const int g = tid & 63, half = tid >> 6;
#pragma unroll
        for (int oct = 0; oct < 8; ++oct) {
            const int c0 = half * 64 + oct * 8;
            const float* srcp = d_y2 + (size_t)(g0 + g) * 128 + c0;
            float4 fa = *(const float4*)srcp;
            float4 fb4 = *(const float4*)(srcp + 4);
            float vv[8] = {fa.x, fa.y, fa.z, fa.w, fb4.x, fb4.y, fb4.z, fb4.w};
            union { __nv_bfloat16 h[8]; float4 v; } H, L;
#pragma unroll
            for (int j = 0; j < 8; ++j) {
                float a = (vv[j] - mean[c0 + j]) * rstd[c0 + j];
                __nv_bfloat16 hh = __float2bfloat16(a);
                H.h[j] = hh;
                L.h[j] = __float2bfloat16(a - __bfloat162float(hh));
            }
            const uint32_t sw = (uint32_t)((oct ^ (g & 7)) << 4);
            char* basep = sm + SMX_A + g * 128 + sw;
            *(float4*)(basep + (0 + half) * 8192) = H.v;
            *(float4*)(basep + (4 + half) * 8192) = H.v;
            *(float4*)(basep + (2 + half) * 8192) = L.v;
        }
    }
    __syncthreads();

    const int wid = tid >> 5, lane = tid & 31;
    const int rA = wid * 16 + (lane & 15);
    const int uA = lane >> 4;
    const int rB0 = ((lane >> 4) << 3) + (lane & 7);
    const int uBb = (lane >> 3) & 1;

    float mlo = -1e30f, mhi = -1e30f;
    float Slo = 0.f, Shi = 0.f;
    float Wlo0 = 0.f, Wlo1 = 0.f, Wlo2 = 0.f;
    float Whi0 = 0.f, Whi1 = 0.f, Whi2 = 0.f;

    for (int ci = 0; ci < 16; ++ci) {
        asm volatile("cp.async.wait_group 0;");
        __syncthreads();
        if (ci < 15) {
            const char* src = (const char*)d_fkb + (size_t)(ci + 1) * 24576;
            const uint32_t dst = sb + SMX_B + ((ci + 1) & 1) * 24576;
            for (int i = tid; i < 1536; i += 128) cp16(dst + i * 16, src + (size_t)i * 16);
            cp_commit();
        }
        const uint32_t Bb = sb + SMX_B + (ci & 1) * 24576;
        const int nbase = ci * 32;

        float acc[4][4];
#pragma unroll
        for (int nt = 0; nt < 4; ++nt) {
            float i0 = -nns[nbase + nt * 8 + (lane & 3) * 2];
            float i1 = -nns[nbase + nt * 8 + (lane & 3) * 2 + 1];
            acc[nt][0] = i0; acc[nt][1] = i1; acc[nt][2] = i0; acc[nt][3] = i1;
        }
#pragma unroll
        for (int s = 0; s < 24; ++s) {
            const int pan = s >> 2, inner = s & 3;
            uint32_t a[4];
            ldsm4(sb + SMX_A + pan * 8192 + rA * 128 + (((inner * 2 + uA) ^ (rA & 7)) << 4),
                  a[0], a[1], a[2], a[3]);
            uint32_t b4[2][4];
#pragma unroll
            for (int bt = 0; bt < 2; ++bt) {
                const int row = bt * 16 + rB0;
                ldsm4(Bb + pan * 4096 + row * 128 + (((inner * 2 + uBb) ^ (row & 7)) << 4),
                      b4[bt][0], b4[bt][1], b4[bt][2], b4[bt][3]);
            }
#pragma unroll
            for (int nt = 0; nt < 4; ++nt)
                mma16816(acc[nt], a, b4[nt >> 1][(nt & 1) * 2], b4[nt >> 1][(nt & 1) * 2 + 1]);
        }

        float cmlo = fmaxf(fmaxf(fmaxf(acc[0][0], acc[0][1]), fmaxf(acc[1][0], acc[1][1])),
                           fmaxf(fmaxf(acc[2][0], acc[2][1]), fmaxf(acc[3][0], acc[3][1])));
        float cmhi = fmaxf(fmaxf(fmaxf(acc[0][2], acc[0][3]), fmaxf(acc[1][2], acc[1][3])),
                           fmaxf(fmaxf(acc[2][2], acc[2][3]), fmaxf(acc[3][2], acc[3][3])));
        cmlo = fmaxf(cmlo, __shfl_xor_sync(0xffffffffu, cmlo, 1));
        cmlo = fmaxf(cmlo, __shfl_xor_sync(0xffffffffu, cmlo, 2));
        cmhi = fmaxf(cmhi, __shfl_xor_sync(0xffffffffu, cmhi, 1));
        cmhi = fmaxf(cmhi, __shfl_xor_sync(0xffffffffu, cmhi, 2));
        if (cmlo > mlo) {
            float cs = exp2a(mlo - cmlo);
            Slo *= cs; Wlo0 *= cs; Wlo1 *= cs; Wlo2 *= cs;
            mlo = cmlo;
        }
        if (cmhi > mhi) {
            float cs = exp2a(mhi - cmhi);
            Shi *= cs; Whi0 *= cs; Whi1 *= cs; Whi2 *= cs;
            mhi = cmhi;
        }
#pragma unroll
        for (int nt = 0; nt < 4; ++nt) {
#pragma unroll
            for (int j = 0; j < 2; ++j) {
                const float4 dv = dsm4[nbase + nt * 8 + (lane & 3) * 2 + j];
                float elo = exp2a(acc[nt][j] - mlo);
                float ehi = exp2a(acc[nt][2 + j] - mhi);
                Slo += elo; Shi += ehi;
                Wlo0 = fmaf(elo, dv.x, Wlo0); Wlo1 = fmaf(elo, dv.y, Wlo1); Wlo2 = fmaf(elo, dv.z, Wlo2);
                Whi0 = fmaf(ehi, dv.x, Whi0); Whi1 = fmaf(ehi, dv.y, Whi1); Whi2 = fmaf(ehi, dv.z, Whi2);
            }
        }
    }

#pragma unroll
    for (int d = 1; d <= 2; d <<= 1) {
        Slo += __shfl_xor_sync(0xffffffffu, Slo, d);
        Shi += __shfl_xor_sync(0xffffffffu, Shi, d);
        Wlo0 += __shfl_xor_sync(0xffffffffu, Wlo0, d);
        Wlo1 += __shfl_xor_sync(0xffffffffu, Wlo1, d);
        Wlo2 += __shfl_xor_sync(0xffffffffu, Wlo2, d);
        Whi0 += __shfl_xor_sync(0xffffffffu, Whi0, d);
        Whi1 += __shfl_xor_sync(0xffffffffu, Whi1, d);
        Whi2 += __shfl_xor_sync(0xffffffffu, Whi2, d);
    }
    if ((lane & 3) == 0) {
        const int rlo = g0 + wid * 16 + (lane >> 2);
        const int rhi = rlo + 8;
        const float ilo = 1.0f / Slo, ihi = 1.0f / Shi;
        out[0 * DHW + rlo] = Wlo0 * ilo;
        out[1 * DHW + rlo] = Wlo1 * ilo;
        out[2 * DHW + rlo] = Wlo2 * ilo;
        out[0 * DHW + rhi] = Whi0 * ihi;
        out[1 * DHW + rhi] = Whi1 * ihi;
        out[2 * DHW + rhi] = Whi2 * ihi;
    }
}

// ---------------- launch ----------------
extern "C" void kernel_launch(void* const* d_in, const int* in_sizes, int n_in,
                              void* d_out, int out_size) {
    const float* kpts  = (const float*)d_in[0];
    const float* disp  = (const float*)d_in[1];
    const float* feats = (const float*)d_in[2];
    const float* W0    = (const float*)d_in[3];
    const float* b0    = (const float*)d_in[4];
    float* out = (float*)d_out;

    static int attr_done = 0;
    if (!attr_done) {
        cudaFuncSetAttribute(wino_gemm_kernel, cudaFuncAttributeMaxDynamicSharedMemorySize, CONV_SMEM);
        cudaFuncSetAttribute(softmax_mma_kernel, cudaFuncAttributeMaxDynamicSharedMemorySize, SMX_TOTAL);
        attr_done = 1;
    }

    pad_kernel<<<2500, 256>>>(feats);
    wino_w_kernel<<<8192, 128>>>(W0);
    wino_in_kernel<<<3456, 128>>>();
    wino_gemm_kernel<<<dim3(216, 16), 128, CONV_SMEM>>>();
    wino_out_kernel<<<NT, 128>>>(b0);
    stats_part_kernel<<<432, 128>>>();
    stats_fin_kernel<<<1, 128>>>();
    sample_kernel<<<NK, 128>>>(kpts);
    softmax_mma_kernel<<<DHW / 64, 128, SMX_TOTAL>>>(disp, out);
}

// round 15
// speedup vs baseline: 1.1145x; 1.0036x over previous
#include <cuda_runtime.h>
#include <cuda_bf16.h>
#include <cstdint>

#define DD   48
#define HW   2304
#define DHW  110592
#define NK   512
#define LOG2E 1.4426950408889634f
#define NT   13824            // 24^3 Winograd tiles
#define NMU  64

// ---------------- device scratch ----------------
__device__ float d_xp[50 * 50 * 50 * 128];                          // padded input, voxel-major
__device__ __align__(16) __nv_bfloat16 d_wA[(size_t)NMU * NT * 256]; // transformed input [mu][tile][hi128|lo128]
__device__ __align__(16) __nv_bfloat16 d_wu[NMU * 128 * 256];        // transformed weights [mu][co][bhi128|blo128]
__device__ float d_V[(size_t)32 * NT * 128];                         // x-folded GEMM out [mzmy*2+xs][tile][co]
__device__ float d_y2[(size_t)DHW * 128];                            // conv out voxel-major [voxel][c]
__device__ __align__(16) __nv_bfloat16 d_fkb[16 * 12288];            // keypoint feats, pre-swizzled
__device__ float d_sp[432 * 256];
__device__ float d_mean[128];
__device__ float d_rstd[128];
__device__ float d_nn[NK];

__device__ __forceinline__ float exp2a(float x) {
    float r; asm("ex2.approx.ftz.f32 %0, %1;" : "=f"(r) : "f"(x)); return r;
}
__device__ __forceinline__ uint32_t smem_u32(const void* p) {
    uint32_t a;
    asm("{ .reg .u64 t; cvta.to.shared.u64 t, %1; cvt.u32.u64 %0, t; }" : "=r"(a) : "l"(p));
    return a;
}
__device__ __forceinline__ void cp16(uint32_t dst, const void* src) {
    asm volatile("cp.async.cg.shared.global [%0], [%1], 16;" :: "r"(dst), "l"(src));
}
__device__ __forceinline__ void cp_commit() { asm volatile("cp.async.commit_group;"); }
__device__ __forceinline__ void ldsm4(uint32_t addr, uint32_t& r0, uint32_t& r1, uint32_t& r2, uint32_t& r3) {
    asm volatile("ldmatrix.sync.aligned.m8n8.x4.shared.b16 {%0,%1,%2,%3}, [%4];"
                 : "=r"(r0), "=r"(r1), "=r"(r2), "=r"(r3) : "r"(addr));
}
__device__ __forceinline__ void mma16816(float* c, const uint32_t* a, uint32_t b0, uint32_t b1) {
    asm volatile("mma.sync.aligned.m16n8k16.row.col.f32.bf16.bf16.f32 "
                 "{%0,%1,%2,%3}, {%4,%5,%6,%7}, {%8,%9}, {%0,%1,%2,%3};"
                 : "+f"(c[0]), "+f"(c[1]), "+f"(c[2]), "+f"(c[3])
                 : "r"(a[0]), "r"(a[1]), "r"(a[2]), "r"(a[3]), "r"(b0), "r"(b1));
}

// ---------------- pad input to [zp50][yp50][xp50][c128] fp32, voxel-major ----------------
__global__ void __launch_bounds__(256) pad_kernel(const float* __restrict__ feats) {
    __shared__ float tb[50][129];
    const int r = blockIdx.x;               // 2500 (zp,yp) rows
    const int zp = r / 50, yp = r % 50;
    const int zi = zp - 1, yi = yp - 1;
    const int tid = threadIdx.x;
    const int x = tid & 63, cq = tid >> 6;
    const int xi = x - 1;
    const bool rowok = (zi >= 0 && zi < 48 && yi >= 0 && yi < 48);
    const bool xok = rowok && (xi >= 0 && xi < 48);
#pragma unroll 4
    for (int i = 0; i < 32; ++i) {
        int c = cq * 32 + i;
        float v = 0.f;
        if (xok) {
            if (c < 125)       v = feats[(size_t)c * DHW + zi * HW + yi * 48 + xi];
            else if (c == 125) v = (2.0f / 47.0f) * (float)xi - 1.0f;
            else if (c == 126) v = (2.0f / 47.0f) * (float)yi - 1.0f;
            else               v = (2.0f / 47.0f) * (float)zi - 1.0f;
        }
        if (x < 50) tb[x][c] = v;
    }
    __syncthreads();
    float* dst = d_xp + (size_t)r * 50 * 128;
    for (int i = tid; i < 1600; i += 256) {
        int xr = i >> 5, c4 = (i & 31) * 4;
        float4 val = make_float4(tb[xr][c4], tb[xr][c4 + 1], tb[xr][c4 + 2], tb[xr][c4 + 3]);
        *(float4*)(dst + xr * 128 + c4) = val;
    }
}

// ---------------- Winograd weight transform -> [mu][co][bhi128|blo128] ----------------
__device__ __forceinline__ void grow(int m, float* g) {
    if (m == 0)      { g[0] = 1.f;  g[1] = 0.f;   g[2] = 0.f; }
    else if (m == 1) { g[0] = 0.5f; g[1] = 0.5f;  g[2] = 0.5f; }
    else if (m == 2) { g[0] = 0.5f; g[1] = -0.5f; g[2] = 0.5f; }
    else             { g[0] = 0.f;  g[1] = 0.f;   g[2] = 1.f; }
}
__global__ void __launch_bounds__(128) wino_w_kernel(const float* __restrict__ W0) {
    const int mu = blockIdx.x >> 7, co = blockIdx.x & 127, ci = threadIdx.x;
    const int mz = mu >> 4, my = (mu >> 2) & 3, mx = mu & 3;
    float gz[3], gy[3], gx[3];
    grow(mz, gz); grow(my, gy); grow(mx, gx);
    const float* w = W0 + (size_t)(co * 128 + ci) * 27;
    float u = 0.f;
#pragma unroll
    for (int dz = 0; dz < 3; ++dz)
#pragma unroll
        for (int dy = 0; dy < 3; ++dy)
#pragma unroll
            for (int dx = 0; dx < 3; ++dx)
                u = fmaf(gz[dz] * gy[dy] * gx[dx], __ldg(w + dz * 9 + dy * 3 + dx), u);
    __nv_bfloat16 hi = __float2bfloat16(u);
    __nv_bfloat16 lo = __float2bfloat16(u - __bfloat162float(hi));
    __nv_bfloat16* rrow = d_wu + ((size_t)mu * 128 + co) * 256;
    rrow[ci] = hi; rrow[128 + ci] = lo;
}

// ---------------- Winograd input transform: 8 tiles per block (4x sliding x 2y) ----------------
__global__ void __launch_bounds__(128) wino_in_kernel() {
    __shared__ __nv_bfloat16 s[NMU * 256];   // 32 KB staging
    const int blk = blockIdx.x;              // 1728 = 24z * 12ypair * 6xg
    const int c = threadIdx.x;
    const int xg = blk % 6;
    const int yp = (blk / 6) % 12;
    const int zt = blk / 72;
    const int xt0 = xg * 4;
    const int yt0 = yp * 2;
    const float* base = d_xp + ((size_t)((zt * 2) * 50 + yt0 * 2) * 50 + xt0 * 2) * 128 + c;

    float w[4][6][4];
#pragma unroll
    for (int z = 0; z < 4; ++z)
#pragma unroll
        for (int y = 0; y < 6; ++y)
#pragma unroll
            for (int x = 0; x < 4; ++x)
                w[z][y][x] = __ldg(base + ((z * 50 + y) * 50 + x) * 128);

    for (int t = 0; t < 4; ++t) {
#pragma unroll
        for (int ty = 0; ty < 2; ++ty) {
            float d[4][4][4];
#pragma unroll
            for (int z = 0; z < 4; ++z)
#pragma unroll
                for (int y = 0; y < 4; ++y)
#pragma unroll
                    for (int x = 0; x < 4; ++x) d[z][y][x] = w[z][ty * 2 + y][x];
            // x-pass
#pragma unroll
            for (int z = 0; z < 4; ++z)
#pragma unroll
                for (int y = 0; y < 4; ++y) {
                    float a0 = d[z][y][0], a1 = d[z][y][1], a2 = d[z][y][2], a3 = d[z][y][3];
                    d[z][y][0] = a0 - a2; d[z][y][1] = a1 + a2; d[z][y][2] = a2 - a1; d[z][y][3] = a1 - a3;
                }
            // y-pass
#pragma unroll
            for (int z = 0; z < 4; ++z)
#pragma unroll
                for (int x = 0; x < 4; ++x) {
                    float a0 = d[z][0][x], a1 = d[z][1][x], a2 = d[z][2][x], a3 = d[z][3][x];
                    d[z][0][x] = a0 - a2; d[z][1][x] = a1 + a2; d[z][2][x] = a2 - a1; d[z][3][x] = a1 - a3;
                }
            // z-pass
#pragma unroll
            for (int y = 0; y < 4; ++y)
#pragma unroll
                for (int x = 0; x < 4; ++x) {
                    float a0 = d[0][y][x], a1 = d[1][y][x], a2 = d[2][y][x], a3 = d[3][y][x];
                    d[0][y][x] = a0 - a2; d[1][y][x] = a1 + a2; d[2][y][x] = a2 - a1; d[3][y][x] = a1 - a3;
                }
            // split to smem
#pragma unroll
            for (int mz = 0; mz < 4; ++mz)
#pragma unroll
                for (int my = 0; my < 4; ++my)
#pragma unroll
                    for (int mx = 0; mx < 4; ++mx) {
                        int mu = mz * 16 + my * 4 + mx;
                        float v = d[mz][my][mx];
                        __nv_bfloat16 hi = __float2bfloat16(v);
                        s[mu * 256 + c] = hi;
                        s[mu * 256 + 128 + c] = __float2bfloat16(v - __bfloat162float(hi));
                    }
            __syncthreads();
            {
                const int tile = zt * 576 + (yt0 + ty) * 24 + xt0 + t;
                const float4* s4 = (const float4*)s;
                float4* dstA = (float4*)d_wA;
#pragma unroll
                for (int i = 0; i < 16; ++i) {
                    int idx = i * 128 + c;
                    int mu = idx >> 5, ch = idx & 31;
                    dstA[((size_t)mu * NT + tile) * 32 + ch] = s4[idx];
                }
            }
            __syncthreads();
        }
        if (t < 3) {
#pragma unroll
            for (int z = 0; z < 4; ++z)
#pragma unroll
                for (int y = 0; y < 6; ++y) {
                    w[z][y][0] = w[z][y][2];
                    w[z][y][1] = w[z][y][3];
                    w[z][y][2] = __ldg(base + ((z * 50 + y) * 50 + 2 * t + 4) * 128);
                    w[z][y][3] = __ldg(base + ((z * 50 + y) * 50 + 2 * t + 5) * 128);
                }
        }
    }
}

// ---------------- Winograd GEMM + x-direction output fold ----------------
#define STG 49152               // A 16KB + B 32KB
#define CONV_SMEM (2 * STG)     // 96 KB

__global__ void __launch_bounds__(128, 2) wino_gemm_kernel() {
    extern __shared__ char smem[];
    const uint32_t sb = smem_u32(smem);
    const int tid = threadIdx.x;
    const int tile0 = blockIdx.x * 64;     // 216 blocks
    const int mzmy = blockIdx.y;           // 16
    const int mu0 = mzmy * 4;

    auto load_stage = [&](int h) {
        const int mu = h >> 1, p = h & 1;
        const uint32_t ab = sb + (h & 1) * STG;
        const __nv_bfloat16* Abase = d_wA + ((size_t)(mu0 + mu) * NT + tile0) * 256;
        const __nv_bfloat16* Bbase = d_wu + (size_t)(mu0 + mu) * 32768;
#pragma unroll
        for (int i = 0; i < 8; ++i) {
            const int idx = i * 128 + tid;
            const int chunk = idx >> 9;
            const int row = (idx >> 3) & 63;
            const int u = idx & 7;
            cp16(ab + chunk * 8192 + row * 128 + ((u ^ (row & 7)) << 4),
                 Abase + (size_t)row * 256 + (p + 2 * chunk) * 64 + u * 8);
        }
#pragma unroll
        for (int i = 0; i < 16; ++i) {
            const int idx = i * 128 + tid;
            const int half = idx >> 10;
            const int row = (idx >> 3) & 127;
            const int u = idx & 7;
            cp16(ab + 16384 + half * 16384 + row * 128 + ((u ^ (row & 7)) << 4),
                 Bbase + (size_t)row * 256 + half * 128 + p * 64 + u * 8);
        }
        cp_commit();
    };

    load_stage(0);
    load_stage(1);

    const int wid = tid >> 5, lane = tid & 31;
    const int wm = wid >> 1, wn = wid & 1;
    const int rA = wm * 32 + (lane & 15);
    const int uA = lane >> 4;
    const int rB = wn * 64 + ((lane >> 4) << 3) + (lane & 7);
    const int uB = (lane >> 3) & 1;

    float acc[2][8][4], out0[2][8][4], out1[2][8][4];
#pragma unroll
    for (int i = 0; i < 2; ++i)
#pragma unroll
        for (int j = 0; j < 8; ++j)
#pragma unroll
            for (int k = 0; k < 4; ++k) { out0[i][j][k] = 0.f; out1[i][j][k] = 0.f; }

    auto compute = [&](float (&tgt)[2][8][4], int h) {
        const uint32_t Ahi = sb + (h & 1) * STG;
        const uint32_t Alo = Ahi + 8192;
        const uint32_t Bh  = Ahi + 16384;
        const uint32_t Bl  = Ahi + 32768;
#pragma unroll
        for (int k16 = 0; k16 < 4; ++k16) {
            uint32_t ah[2][4], al[2][4], bh[4][4], bl[4][4];
#pragma unroll
            for (int mt = 0; mt < 2; ++mt) {
                const int row = rA + mt * 16;
                const uint32_t off = row * 128 + (((k16 * 2 + uA) ^ (row & 7)) << 4);
                ldsm4(Ahi + off, ah[mt][0], ah[mt][1], ah[mt][2], ah[mt][3]);
                ldsm4(Alo + off, al[mt][0], al[mt][1], al[mt][2], al[mt][3]);
            }
#pragma unroll
            for (int bt = 0; bt < 4; ++bt) {
                const int row = rB + bt * 16;
                const uint32_t off = row * 128 + (((k16 * 2 + uB) ^ (row & 7)) << 4);
                ldsm4(Bh + off, bh[bt][0], bh[bt][1], bh[bt][2], bh[bt][3]);
                ldsm4(Bl + off, bl[bt][0], bl[bt][1], bl[bt][2], bl[bt][3]);
            }
#pragma unroll
            for (int mt = 0; mt < 2; ++mt)
#pragma unroll
                for (int nt = 0; nt < 8; ++nt) {
                    uint32_t h0 = bh[nt >> 1][(nt & 1) * 2], h1 = bh[nt >> 1][(nt & 1) * 2 + 1];
                    mma16816(tgt[mt][nt], ah[mt], h0, h1);
                    mma16816(tgt[mt][nt], al[mt], h0, h1);
                    mma16816(tgt[mt][nt], ah[mt], bl[nt >> 1][(nt & 1) * 2], bl[nt >> 1][(nt & 1) * 2 + 1]);
                }
        }
    };

#pragma unroll
    for (int mx = 0; mx < 4; ++mx) {
        if (mx > 0) {
#pragma unroll
            for (int i = 0; i < 2; ++i)
#pragma unroll
                for (int j = 0; j < 8; ++j)
#pragma unroll
                    for (int k = 0; k < 4; ++k) acc[i][j][k] = 0.f;
        }
#pragma unroll
        for (int ph = 0; ph < 2; ++ph) {
            const int h = mx * 2 + ph;
            if (h < 7) asm volatile("cp.async.wait_group 1;");
            else       asm volatile("cp.async.wait_group 0;");
            __syncthreads();
            if (mx == 0) compute(out0, h);
            else         compute(acc, h);
            __syncthreads();
            if (h + 2 < 8) load_stage(h + 2);
        }
        if (mx == 1) {
#pragma unroll
            for (int i = 0; i < 2; ++i)
#pragma unroll
                for (int j = 0; j < 8; ++j)
#pragma unroll
                    for (int k = 0; k < 4; ++k) { out0[i][j][k] += acc[i][j][k]; out1[i][j][k] += acc[i][j][k]; }
        } else if (mx == 2) {
#pragma unroll
            for (int i = 0; i < 2; ++i)
#pragma unroll
                for (int j = 0; j < 8; ++j)
#pragma unroll
                    for (int k = 0; k < 4; ++k) { out0[i][j][k] += acc[i][j][k]; out1[i][j][k] -= acc[i][j][k]; }
        } else if (mx == 3) {
#pragma unroll
            for (int i = 0; i < 2; ++i)
#pragma unroll
                for (int j = 0; j < 8; ++j)
#pragma unroll
                    for (int k = 0; k < 4; ++k) { out1[i][j][k] -= acc[i][j][k]; }
        }
    }

#pragma unroll
    for (int mt = 0; mt < 2; ++mt) {
#pragma unroll
        for (int half = 0; half < 2; ++half) {
            const int r = wm * 32 + mt * 16 + (lane >> 2) + half * 8;
            float* dst0 = d_V + ((size_t)(mzmy * 2 + 0) * NT + tile0 + r) * 128;
            float* dst1 = d_V + ((size_t)(mzmy * 2 + 1) * NT + tile0 + r) * 128;
#pragma unroll
            for (int nt = 0; nt < 8; ++nt) {
                const int n0 = wn * 64 + nt * 8 + (lane & 3) * 2;
                *(float2*)(dst0 + n0) = make_float2(out0[mt][nt][half * 2 + 0], out0[mt][nt][half * 2 + 1]);
                *(float2*)(dst1 + n0) = make_float2(out1[mt][nt][half * 2 + 0], out1[mt][nt][half * 2 + 1]);
            }
        }
    }
}

// ---------------- Winograd y,z output transform + bias + relu -> d_y2 ----------------
__global__ void __launch_bounds__(128) wino_out_kernel(const float* __restrict__ b0) {
    const int t = blockIdx.x;
    const int c = threadIdx.x;
    const int zt = t / 576, yt = (t / 24) % 24, xt = t % 24;
    const float* src = d_V + (size_t)t * 128 + c;
    float v[4][4][2];
#pragma unroll
    for (int mz = 0; mz < 4; ++mz)
#pragma unroll
        for (int my = 0; my < 4; ++my)
#pragma unroll
            for (int xs = 0; xs < 2; ++xs)
                v[mz][my][xs] = __ldg(src + (size_t)((mz * 4 + my) * 2 + xs) * NT * 128);
    float w[4][2][2];
#pragma unroll
    for (int mz = 0; mz < 4; ++mz)
#pragma unroll
        for (int xs = 0; xs < 2; ++xs) {
            w[mz][0][xs] = v[mz][0][xs] + v[mz][1][xs] + v[mz][2][xs];
            w[mz][1][xs] = v[mz][1][xs] - v[mz][2][xs] - v[mz][3][xs];
        }
    const float bias = __ldg(b0 + c);
#pragma unroll
    for (int py = 0; py < 2; ++py)
#pragma unroll
        for (int xs = 0; xs < 2; ++xs) {
            float o0 = w[0][py][xs] + w[1][py][xs] + w[2][py][xs];
            float o1 = w[1][py][xs] - w[2][py][xs] - w[3][py][xs];
            const int vz0 = (zt * 2) * HW + (yt * 2 + py) * 48 + xt * 2 + xs;
            d_y2[(size_t)vz0 * 128 + c] = fmaxf(o0 + bias, 0.f);
            d_y2[(size_t)(vz0 + HW) * 128 + c] = fmaxf(o1 + bias, 0.f);
        }
}

// ---------------- InstanceNorm stats (voxel-major) ----------------
__global__ void __launch_bounds__(128) stats_part_kernel() {
    const int blk = blockIdx.x;       // 432
    const int c = threadIdx.x;
    const float* p = d_y2 + (size_t)blk * 256 * 128 + c;
    float s = 0.f, s2 = 0.f;
#pragma unroll 4
    for (int i = 0; i < 256; ++i) {
        float v = p[(size_t)i * 128];
        s += v; s2 += v * v;
    }
    d_sp[blk * 256 + c] = s;
    d_sp[blk * 256 + 128 + c] = s2;
}
__global__ void __launch_bounds__(128) stats_fin_kernel() {
    const int c = threadIdx.x;
    float S = 0.f, S2 = 0.f;
    for (int b = 0; b < 432; ++b) {
        S  += d_sp[b * 256 + c];
        S2 += d_sp[b * 256 + 128 + c];
    }
    float mean = S * (1.0f / (float)DHW);
    float var  = S2 * (1.0f / (float)DHW) - mean * mean;
    d_mean[c] = mean;
    d_rstd[c] = rsqrtf(var + 1e-5f);
}

// ---------------- keypoint sampling: pre-swizzled split-bf16 B + norms ----------------
__global__ void __launch_bounds__(128) sample_kernel(const float* __restrict__ kpts) {
    const int n = blockIdx.x;
    const int c = threadIdx.x;
    __shared__ float pt[3];
    if (c < 3) pt[c] = kpts[n * 3 + c];
    __syncthreads();
    const float ix = (pt[0] + 1.0f) * 0.5f * 47.0f;
    const float iy = (pt[1] + 1.0f) * 0.5f * 47.0f;
    const float iz = (pt[2] + 1.0f) * 0.5f * 47.0f;
    const float x0f = floorf(ix), y0f = floorf(iy), z0f = floorf(iz);
    const float wx = ix - x0f, wy = iy - y0f, wz = iz - z0f;
    int x0 = min(max((int)x0f, 0), 47);
    int y0 = min(max((int)y0f, 0), 47);
    int z0 = min(max((int)z0f, 0), 47);
    int x1 = min(x0 + 1, 47), y1 = min(y0 + 1, 47), z1 = min(z0 + 1, 47);
    const float* vol = d_y2 + c;
    float c000 = vol[(size_t)(z0*HW + y0*48 + x0) * 128], c001 = vol[(size_t)(z0*HW + y0*48 + x1) * 128];
    float c010 = vol[(size_t)(z0*HW + y1*48 + x0) * 128], c011 = vol[(size_t)(z0*HW + y1*48 + x1) * 128];
    float c100 = vol[(size_t)(z1*HW + y0*48 + x0) * 128], c101 = vol[(size_t)(z1*HW + y0*48 + x1) * 128];
    float c110 = vol[(size_t)(z1*HW + y1*48 + x0) * 128], c111 = vol[(size_t)(z1*HW + y1*48 + x1) * 128];
    float v = c000*((1-wz)*(1-wy)*(1-wx)) + c001*((1-wz)*(1-wy)*wx)
            + c010*((1-wz)*wy*(1-wx))     + c011*((1-wz)*wy*wx)
            + c100*(wz*(1-wy)*(1-wx))     + c101*(wz*(1-wy)*wx)
            + c110*(wz*wy*(1-wx))         + c111*(wz*wy*wx);
    float f = (v - d_mean[c]) * d_rstd[c];

    float b = 2.0f * LOG2E * f;
    __nv_bfloat16 bh = __float2bfloat16(b);
    __nv_bfloat16 bl = __float2bfloat16(b - __bfloat162float(bh));
    const int chunk = n >> 5, row = n & 31;
    const int u = (c & 63) >> 3, j = c & 7, ph = c >> 6;
    char* fb = (char*)d_fkb;
    size_t base = (size_t)chunk * 24576 + (size_t)row * 128 + ((u ^ (row & 7)) << 4) + j * 2;
    *(__nv_bfloat16*)(fb + base + (0 + ph) * 4096) = bh;
    *(__nv_bfloat16*)(fb + base + (2 + ph) * 4096) = bh;
    *(__nv_bfloat16*)(fb + base + (4 + ph) * 4096) = bl;

    __shared__ float red[128];
    red[c] = f * f;
    __syncthreads();
    for (int o = 64; o > 0; o >>= 1) {
        if (c < o) red[c] += red[c + o];
        __syncthreads();
    }
    if (c == 0) d_nn[n] = LOG2E * red[0];
}

// ---------------- softmax interpolation via mma.sync: 128 voxels/CTA, 256 thr ----------------
#define SMX_A    0
#define SMX_B    98304
#define SMX_NN   147456
#define SMX_DSM  149504
#define SMX_MEAN 157696
#define SMX_RSTD 158208
#define SMX_TOTAL 158720

__global__ void __launch_bounds__(256, 1) softmax_mma_kernel(const float* __restrict__ disp,
                                                             float* __restrict__ out) {
    extern __shared__ char sm[];
    const uint32_t sb = smem_u32(sm);
    const int tid = threadIdx.x;
    const int g0 = blockIdx.x * 128;

    float* nns = (float*)(sm + SMX_NN);
    float4* dsm4 = (float4*)(sm + SMX_DSM);
    for (int i = tid; i < NK; i += 256) {
        nns[i] = d_nn[i];
        float4 dv;
        dv.x = disp[i * 3]; dv.y = disp[i * 3 + 1]; dv.z = disp[i * 3 + 2]; dv.w = 0.f;
        dsm4[i] = dv;
    }
    ((float*)(sm + SMX_MEAN))[tid & 127] = d_mean[tid & 127];
    ((float*)(sm + SMX_RSTD))[tid & 127] = d_rstd[tid & 127];

    {
        const char* src = (const char*)d_fkb;
        for (int i = tid; i < 1536; i += 256) cp16(sb + SMX_B + i * 16, src + (size_t)i * 16);
        cp_commit();
    }
    __syncthreads();

    {
        const float* mean = (const float*)(sm + SMX_MEAN);
        const float* rstd = (const float*)(sm + SMX_RSTD);
        const int g = tid & 127, half = tid >> 7;
#pragma unroll
        for (int oct = 0; oct < 8; ++oct) {
            const int c0 = half * 64 + oct * 8;
            const float* srcp = d_y2 + (size_t)(g0 + g) * 128 + c0;
            float4 fa = *(const float4*)srcp;
            float4 fb4 = *(const float4*)(srcp + 4);
            float vv[8] = {fa.x, fa.y, fa.z, fa.w, fb4.x, fb4.y, fb4.z, fb4.w};
            union { __nv_bfloat16 h[8]; float4 v; } H, L;
#pragma unroll
            for (int j = 0; j < 8; ++j) {
                float a = (vv[j] - mean[c0 + j]) * rstd[c0 + j];
                __nv_bfloat16 hh = __float2bfloat16(a);
                H.h[j] = hh;
                L.h[j] = __float2bfloat16(a - __bfloat162float(hh));
            }
            const uint32_t sw = (uint32_t)((oct ^ (g & 7)) << 4);
            char* basep = sm + SMX_A + g * 128 + sw;
            *(float4*)(basep + (0 + half) * 16384) = H.v;
            *(float4*)(basep + (4 + half) * 16384) = H.v;
            *(float4*)(basep + (2 + half) * 16384) = L.v;
        }
    }
    __syncthreads();

    const int wid = tid >> 5, lane = tid & 31;
    const int rA = wid * 16 + (lane & 15);
    const int uA = lane >> 4;
    const int rB0 = ((lane >> 4) << 3) + (lane & 7);
    const int uBb = (lane >> 3) & 1;

    float mlo = -1e30f, mhi = -1e30f;
    float Slo = 0.f, Shi = 0.f;
    float Wlo0 = 0.f, Wlo1 = 0.f, Wlo2 = 0.f;
    float Whi0 = 0.f, Whi1 = 0.f, Whi2 = 0.f;

    for (int ci = 0; ci < 16; ++ci) {
        asm volatile("cp.async.wait_group 0;");
        __syncthreads();
        if (ci < 15) {
            const char* src = (const char*)d_fkb + (size_t)(ci + 1) * 24576;
            const uint32_t dst = sb + SMX_B + ((ci + 1) & 1) * 24576;
            for (int i = tid; i < 1536; i += 256) cp16(dst + i * 16, src + (size_t)i * 16);
            cp_commit();
        }
        const uint32_t Bb = sb + SMX_B + (ci & 1) * 24576;
        const int nbase = ci * 32;

        float acc[4][4];
#pragma unroll
        for (int nt = 0; nt < 4; ++nt) {
            float i0 = -nns[nbase + nt * 8 + (lane & 3) * 2];
            float i1 = -nns[nbase + nt * 8 + (lane & 3) * 2 + 1];
            acc[nt][0] = i0; acc[nt][1] = i1; acc[nt][2] = i0; acc[nt][3] = i1;
        }
#pragma unroll
        for (int s = 0; s < 24; ++s) {
            const int pan = s >> 2, inner = s & 3;
            uint32_t a[4];
            ldsm4(sb + SMX_A + pan * 16384 + rA * 128 + (((inner * 2 + uA) ^ (rA & 7)) << 4),
                  a[0], a[1], a[2], a[3]);
            uint32_t b4[2][4];
#pragma unroll
            for (int bt = 0; bt < 2; ++bt) {
                const int row = bt * 16 + rB0;
                ldsm4(Bb + pan * 4096 + row * 128 + (((inner * 2 + uBb) ^ (row & 7)) << 4),
                      b4[bt][0], b4[bt][1], b4[bt][2], b4[bt][3]);
            }
#pragma unroll
            for (int nt = 0; nt < 4; ++nt)
                mma16816(acc[nt], a, b4[nt >> 1][(nt & 1) * 2], b4[nt >> 1][(nt & 1) * 2 + 1]);
        }

        float cmlo = fmaxf(fmaxf(fmaxf(acc[0][0], acc[0][1]), fmaxf(acc[1][0], acc[1][1])),
                           fmaxf(fmaxf(acc[2][0], acc[2][1]), fmaxf(acc[3][0], acc[3][1])));
        float cmhi = fmaxf(fmaxf(fmaxf(acc[0][2], acc[0][3]), fmaxf(acc[1][2], acc[1][3])),
                           fmaxf(fmaxf(acc[2][2], acc[2][3]), fmaxf(acc[3][2], acc[3][3])));
        cmlo = fmaxf(cmlo, __shfl_xor_sync(0xffffffffu, cmlo, 1));
        cmlo = fmaxf(cmlo, __shfl_xor_sync(0xffffffffu, cmlo, 2));
        cmhi = fmaxf(cmhi, __shfl_xor_sync(0xffffffffu, cmhi, 1));
        cmhi = fmaxf(cmhi, __shfl_xor_sync(0xffffffffu, cmhi, 2));
        if (cmlo > mlo) {
            float cs = exp2a(mlo - cmlo);
            Slo *= cs; Wlo0 *= cs; Wlo1 *= cs; Wlo2 *= cs;
            mlo = cmlo;
        }
        if (cmhi > mhi) {
            float cs = exp2a(mhi - cmhi);
            Shi *= cs; Whi0 *= cs; Whi1 *= cs; Whi2 *= cs;
            mhi = cmhi;
        }
#pragma unroll
        for (int nt = 0; nt < 4; ++nt) {
#pragma unroll
            for (int j = 0; j < 2; ++j) {
                const float4 dv = dsm4[nbase + nt * 8 + (lane & 3) * 2 + j];
                float elo = exp2a(acc[nt][j] - mlo);
                float ehi = exp2a(acc[nt][2 + j] - mhi);
                Slo += elo; Shi += ehi;
                Wlo0 = fmaf(elo, dv.x, Wlo0); Wlo1 = fmaf(elo, dv.y, Wlo1); Wlo2 = fmaf(elo, dv.z, Wlo2);
                Whi0 = fmaf(ehi, dv.x, Whi0); Whi1 = fmaf(ehi, dv.y, Whi1); Whi2 = fmaf(ehi, dv.z, Whi2);
            }
        }
    }

#pragma unroll
    for (int d = 1; d <= 2; d <<= 1) {
        Slo += __shfl_xor_sync(0xffffffffu, Slo, d);
        Shi += __shfl_xor_sync(0xffffffffu, Shi, d);
        Wlo0 += __shfl_xor_sync(0xffffffffu, Wlo0, d);
        Wlo1 += __shfl_xor_sync(0xffffffffu, Wlo1, d);
        Wlo2 += __shfl_xor_sync(0xffffffffu, Wlo2, d);
        Whi0 += __shfl_xor_sync(0xffffffffu, Whi0, d);
        Whi1 += __shfl_xor_sync(0xffffffffu, Whi1, d);
        Whi2 += __shfl_xor_sync(0xffffffffu, Whi2, d);
    }
    if ((lane & 3) == 0) {
        const int rlo = g0 + wid * 16 + (lane >> 2);
        const int rhi = rlo + 8;
        const float ilo = 1.0f / Slo, ihi = 1.0f / Shi;
        out[0 * DHW + rlo] = Wlo0 * ilo;
        out[1 * DHW + rlo] = Wlo1 * ilo;
        out[2 * DHW + rlo] = Wlo2 * ilo;
        out[0 * DHW + rhi] = Whi0 * ihi;
        out[1 * DHW + rhi] = Whi1 * ihi;
        out[2 * DHW + rhi] = Whi2 * ihi;
    }
}

// ---------------- launch ----------------
extern "C" void kernel_launch(void* const* d_in, const int* in_sizes, int n_in,
                              void* d_out, int out_size) {
    const float* kpts  = (const float*)d_in[0];
    const float* disp  = (const float*)d_in[1];
    const float* feats = (const float*)d_in[2];
    const float* W0    = (const float*)d_in[3];
    const float* b0    = (const float*)d_in[4];
    float* out = (float*)d_out;

    static int attr_done = 0;
    if (!attr_done) {
        cudaFuncSetAttribute(wino_gemm_kernel, cudaFuncAttributeMaxDynamicSharedMemorySize, CONV_SMEM);
        cudaFuncSetAttribute(softmax_mma_kernel, cudaFuncAttributeMaxDynamicSharedMemorySize, SMX_TOTAL);
        attr_done = 1;
    }

    pad_kernel<<<2500, 256>>>(feats);
    wino_w_kernel<<<8192, 128>>>(W0);
    wino_in_kernel<<<1728, 128>>>();
    wino_gemm_kernel<<<dim3(216, 16), 128, CONV_SMEM>>>();
    wino_out_kernel<<<NT, 128>>>(b0);
    stats_part_kernel<<<432, 128>>>();
    stats_fin_kernel<<<1, 128>>>();
    sample_kernel<<<NK, 128>>>(kpts);
    softmax_mma_kernel<<<DHW / 128, 256, SMX_TOTAL>>>(disp, out);
}

// round 16
// speedup vs baseline: 1.1419x; 1.0246x over previous
#include <cuda_runtime.h>
#include <cuda_bf16.h>
#include <cstdint>

#define DD   48
#define HW   2304
#define DHW  110592
#define NK   512
#define LOG2E 1.4426950408889634f
#define NT   13824            // 24^3 Winograd tiles
#define NMU  64

// ---------------- device scratch ----------------
__device__ float d_xp[50 * 50 * 50 * 128];                          // padded input, voxel-major
__device__ __align__(16) __nv_bfloat16 d_wA[(size_t)NMU * NT * 256]; // transformed input [mu][tile][hi128|lo128]
__device__ __align__(16) __nv_bfloat16 d_wu[NMU * 128 * 256];        // transformed weights [mu][co][bhi128|blo128]
__device__ float d_V[(size_t)32 * NT * 128];                         // x-folded GEMM out [mzmy*2+xs][tile][co]
__device__ float d_y2[(size_t)DHW * 128];                            // conv out voxel-major [voxel][c]
__device__ __align__(16) __nv_bfloat16 d_fkb[16 * 12288];            // keypoint feats, pre-swizzled
__device__ float d_sp[128 * 432 * 2];                                // stats partials [c][blk] (sum | sumsq)
__device__ float d_mean[128];
__device__ float d_rstd[128];
__device__ float d_nn[NK];

__device__ __forceinline__ float exp2a(float x) {
    float r; asm("ex2.approx.ftz.f32 %0, %1;" : "=f"(r) : "f"(x)); return r;
}
__device__ __forceinline__ uint32_t smem_u32(const void* p) {
    uint32_t a;
    asm("{ .reg .u64 t; cvta.to.shared.u64 t, %1; cvt.u32.u64 %0, t; }" : "=r"(a) : "l"(p));
    return a;
}
__device__ __forceinline__ void cp16(uint32_t dst, const void* src) {
    asm volatile("cp.async.cg.shared.global [%0], [%1], 16;" :: "r"(dst), "l"(src));
}
__device__ __forceinline__ void cp_commit() { asm volatile("cp.async.commit_group;"); }
__device__ __forceinline__ void ldsm4(uint32_t addr, uint32_t& r0, uint32_t& r1, uint32_t& r2, uint32_t& r3) {
    asm volatile("ldmatrix.sync.aligned.m8n8.x4.shared.b16 {%0,%1,%2,%3}, [%4];"
                 : "=r"(r0), "=r"(r1), "=r"(r2), "=r"(r3) : "r"(addr));
}
__device__ __forceinline__ void mma16816(float* c, const uint32_t* a, uint32_t b0, uint32_t b1) {
    asm volatile("mma.sync.aligned.m16n8k16.row.col.f32.bf16.bf16.f32 "
                 "{%0,%1,%2,%3}, {%4,%5,%6,%7}, {%8,%9}, {%0,%1,%2,%3};"
                 : "+f"(c[0]), "+f"(c[1]), "+f"(c[2]), "+f"(c[3])
                 : "r"(a[0]), "r"(a[1]), "r"(a[2]), "r"(a[3]), "r"(b0), "r"(b1));
}

// ---------------- pad input to [zp50][yp50][xp50][c128] fp32, voxel-major ----------------
__global__ void __launch_bounds__(256) pad_kernel(const float* __restrict__ feats) {
    __shared__ float tb[50][129];
    const int r = blockIdx.x;               // 2500 (zp,yp) rows
    const int zp = r / 50, yp = r % 50;
    const int zi = zp - 1, yi = yp - 1;
    const int tid = threadIdx.x;
    const int x = tid & 63, cq = tid >> 6;
    const int xi = x - 1;
    const bool rowok = (zi >= 0 && zi < 48 && yi >= 0 && yi < 48);
    const bool xok = rowok && (xi >= 0 && xi < 48);
#pragma unroll 4
    for (int i = 0; i < 32; ++i) {
        int c = cq * 32 + i;
        float v = 0.f;
        if (xok) {
            if (c < 125)       v = feats[(size_t)c * DHW + zi * HW + yi * 48 + xi];
            else if (c == 125) v = (2.0f / 47.0f) * (float)xi - 1.0f;
            else if (c == 126) v = (2.0f / 47.0f) * (float)yi - 1.0f;
            else               v = (2.0f / 47.0f) * (float)zi - 1.0f;
        }
        if (x < 50) tb[x][c] = v;
    }
    __syncthreads();
    float* dst = d_xp + (size_t)r * 50 * 128;
    for (int i = tid; i < 1600; i += 256) {
        int xr = i >> 5, c4 = (i & 31) * 4;
        float4 val = make_float4(tb[xr][c4], tb[xr][c4 + 1], tb[xr][c4 + 2], tb[xr][c4 + 3]);
        *(float4*)(dst + xr * 128 + c4) = val;
    }
}

// ---------------- Winograd weight transform -> [mu][co][bhi128|blo128] ----------------
__device__ __forceinline__ void grow(int m, float* g) {
    if (m == 0)      { g[0] = 1.f;  g[1] = 0.f;   g[2] = 0.f; }
    else if (m == 1) { g[0] = 0.5f; g[1] = 0.5f;  g[2] = 0.5f; }
    else if (m == 2) { g[0] = 0.5f; g[1] = -0.5f; g[2] = 0.5f; }
    else             { g[0] = 0.f;  g[1] = 0.f;   g[2] = 1.f; }
}
__global__ void __launch_bounds__(128) wino_w_kernel(const float* __restrict__ W0) {
    const int mu = blockIdx.x >> 7, co = blockIdx.x & 127, ci = threadIdx.x;
    const int mz = mu >> 4, my = (mu >> 2) & 3, mx = mu & 3;
    float gz[3], gy[3], gx[3];
    grow(mz, gz); grow(my, gy); grow(mx, gx);
    const float* w = W0 + (size_t)(co * 128 + ci) * 27;
    float u = 0.f;
#pragma unroll
    for (int dz = 0; dz < 3; ++dz)
#pragma unroll
        for (int dy = 0; dy < 3; ++dy)
#pragma unroll
            for (int dx = 0; dx < 3; ++dx)
                u = fmaf(gz[dz] * gy[dy] * gx[dx], __ldg(w + dz * 9 + dy * 3 + dx), u);
    __nv_bfloat16 hi = __float2bfloat16(u);
    __nv_bfloat16 lo = __float2bfloat16(u - __bfloat162float(hi));
    __nv_bfloat16* rrow = d_wu + ((size_t)mu * 128 + co) * 256;
    rrow[ci] = hi; rrow[128 + ci] = lo;
}

// ---------------- Winograd input transform: 8 tiles per block, DIRECT coalesced stores ----------------
__global__ void __launch_bounds__(128) wino_in_kernel() {
    const int blk = blockIdx.x;              // 1728 = 24z * 12ypair * 6xg
    const int c = threadIdx.x;
    const int xg = blk % 6;
    const int yp = (blk / 6) % 12;
    const int zt = blk / 72;
    const int xt0 = xg * 4;
    const int yt0 = yp * 2;
    const float* base = d_xp + ((size_t)((zt * 2) * 50 + yt0 * 2) * 50 + xt0 * 2) * 128 + c;

    float w[4][6][4];
#pragma unroll
    for (int z = 0; z < 4; ++z)
#pragma unroll
        for (int y = 0; y < 6; ++y)
#pragma unroll
            for (int x = 0; x < 4; ++x)
                w[z][y][x] = __ldg(base + ((z * 50 + y) * 50 + x) * 128);

    for (int t = 0; t < 4; ++t) {
#pragma unroll
        for (int ty = 0; ty < 2; ++ty) {
            float d[4][4][4];
#pragma unroll
            for (int z = 0; z < 4; ++z)
#pragma unroll
                for (int y = 0; y < 4; ++y)
#pragma unroll
                    for (int x = 0; x < 4; ++x) d[z][y][x] = w[z][ty * 2 + y][x];
            // x-pass
#pragma unroll
            for (int z = 0; z < 4; ++z)
#pragma unroll
                for (int y = 0; y < 4; ++y) {
                    float a0 = d[z][y][0], a1 = d[z][y][1], a2 = d[z][y][2], a3 = d[z][y][3];
                    d[z][y][0] = a0 - a2; d[z][y][1] = a1 + a2; d[z][y][2] = a2 - a1; d[z][y][3] = a1 - a3;
                }
            // y-pass
#pragma unroll
            for (int z = 0; z < 4; ++z)
#pragma unroll
                for (int x = 0; x < 4; ++x) {
                    float a0 = d[z][0][x], a1 = d[z][1][x], a2 = d[z][2][x], a3 = d[z][3][x];
                    d[z][0][x] = a0 - a2; d[z][1][x] = a1 + a2; d[z][2][x] = a2 - a1; d[z][3][x] = a1 - a3;
                }
            // z-pass
#pragma unroll
            for (int y = 0; y < 4; ++y)
#pragma unroll
                for (int x = 0; x < 4; ++x) {
                    float a0 = d[0][y][x], a1 = d[1][y][x], a2 = d[2][y][x], a3 = d[3][y][x];
                    d[0][y][x] = a0 - a2; d[1][y][x] = a1 + a2; d[2][y][x] = a2 - a1; d[3][y][x] = a1 - a3;
                }
            // direct split-bf16 stores (identical layout to staged version)
            const int tile = zt * 576 + (yt0 + ty) * 24 + xt0 + t;
            __nv_bfloat16* dptr = d_wA + (size_t)tile * 256 + c;
#pragma unroll
            for (int mz = 0; mz < 4; ++mz)
#pragma unroll
                for (int my = 0; my < 4; ++my)
#pragma unroll
                    for (int mx = 0; mx < 4; ++mx) {
                        const int mu = mz * 16 + my * 4 + mx;
                        float v = d[mz][my][mx];
                        __nv_bfloat16 hi = __float2bfloat16(v);
                        __nv_bfloat16 lo = __float2bfloat16(v - __bfloat162float(hi));
                        __nv_bfloat16* p = dptr + (size_t)mu * NT * 256;
                        p[0] = hi;
                        p[128] = lo;
                    }
        }
        if (t < 3) {
#pragma unroll
            for (int z = 0; z < 4; ++z)
#pragma unroll
                for (int y = 0; y < 6; ++y) {
                    w[z][y][0] = w[z][y][2];
                    w[z][y][1] = w[z][y][3];
                    w[z][y][2] = __ldg(base + ((z * 50 + y) * 50 + 2 * t + 4) * 128);
                    w[z][y][3] = __ldg(base + ((z * 50 + y) * 50 + 2 * t + 5) * 128);
                }
        }
    }
}

// ---------------- Winograd GEMM + x-direction output fold ----------------
#define STG 49152               // A 16KB + B 32KB
#define CONV_SMEM (2 * STG)     // 96 KB

__global__ void __launch_bounds__(128, 2) wino_gemm_kernel() {
    extern __shared__ char smem[];
    const uint32_t sb = smem_u32(smem);
    const int tid = threadIdx.x;
    const int tile0 = blockIdx.x * 64;     // 216 blocks
    const int mzmy = blockIdx.y;           // 16
    const int mu0 = mzmy * 4;

    auto load_stage = [&](int h) {
        const int mu = h >> 1, p = h & 1;
        const uint32_t ab = sb + (h & 1) * STG;
        const __nv_bfloat16* Abase = d_wA + ((size_t)(mu0 + mu) * NT + tile0) * 256;
        const __nv_bfloat16* Bbase = d_wu + (size_t)(mu0 + mu) * 32768;
#pragma unroll
        for (int i = 0; i < 8; ++i) {
            const int idx = i * 128 + tid;
            const int chunk = idx >> 9;
            const int row = (idx >> 3) & 63;
            const int u = idx & 7;
            cp16(ab + chunk * 8192 + row * 128 + ((u ^ (row & 7)) << 4),
                 Abase + (size_t)row * 256 + (p + 2 * chunk) * 64 + u * 8);
        }
#pragma unroll
        for (int i = 0; i < 16; ++i) {
            const int idx = i * 128 + tid;
            const int half = idx >> 10;
            const int row = (idx >> 3) & 127;
            const int u = idx & 7;
            cp16(ab + 16384 + half * 16384 + row * 128 + ((u ^ (row & 7)) << 4),
                 Bbase + (size_t)row * 256 + half * 128 + p * 64 + u * 8);
        }
        cp_commit();
    };

    load_stage(0);
    load_stage(1);

    const int wid = tid >> 5, lane = tid & 31;
    const int wm = wid >> 1, wn = wid & 1;
    const int rA = wm * 32 + (lane & 15);
    const int uA = lane >> 4;
    const int rB = wn * 64 + ((lane >> 4) << 3) + (lane & 7);
    const int uB = (lane >> 3) & 1;

    float acc[2][8][4], out0[2][8][4], out1[2][8][4];
#pragma unroll
    for (int i = 0; i < 2; ++i)
#pragma unroll
        for (int j = 0; j < 8; ++j)
#pragma unroll
            for (int k = 0; k < 4; ++k) { out0[i][j][k] = 0.f; out1[i][j][k] = 0.f; }

    auto compute = [&](float (&tgt)[2][8][4], int h) {
        const uint32_t Ahi = sb + (h & 1) * STG;
        const uint32_t Alo = Ahi + 8192;
        const uint32_t Bh  = Ahi + 16384;
        const uint32_t Bl  = Ahi + 32768;
#pragma unroll
        for (int k16 = 0; k16 < 4; ++k16) {
            uint32_t ah[2][4], al[2][4], bh[4][4], bl[4][4];
#pragma unroll
            for (int mt = 0; mt < 2; ++mt) {
                const int row = rA + mt * 16;
                const uint32_t off = row * 128 + (((k16 * 2 + uA) ^ (row & 7)) << 4);
                ldsm4(Ahi + off, ah[mt][0], ah[mt][1], ah[mt][2], ah[mt][3]);
                ldsm4(Alo + off, al[mt][0], al[mt][1], al[mt][2], al[mt][3]);
            }
#pragma unroll
            for (int bt = 0; bt < 4; ++bt) {
                const int row = rB + bt * 16;
                const uint32_t off = row * 128 + (((k16 * 2 + uB) ^ (row & 7)) << 4);
                ldsm4(Bh + off, bh[bt][0], bh[bt][1], bh[bt][2], bh[bt][3]);
                ldsm4(Bl + off, bl[bt][0], bl[bt][1], bl[bt][2], bl[bt][3]);
            }
#pragma unroll
            for (int mt = 0; mt < 2; ++mt)
#pragma unroll
                for (int nt = 0; nt < 8; ++nt) {
                    uint32_t h0 = bh[nt >> 1][(nt & 1) * 2], h1 = bh[nt >> 1][(nt & 1) * 2 + 1];
                    mma16816(tgt[mt][nt], ah[mt], h0, h1);
                    mma16816(tgt[mt][nt], al[mt], h0, h1);
                    mma16816(tgt[mt][nt], ah[mt], bl[nt >> 1][(nt & 1) * 2], bl[nt >> 1][(nt & 1) * 2 + 1]);
                }
        }
    };

#pragma unroll
    for (int mx = 0; mx < 4; ++mx) {
        if (mx > 0) {
#pragma unroll
            for (int i = 0; i < 2; ++i)
#pragma unroll
                for (int j = 0; j < 8; ++j)
#pragma unroll
                    for (int k = 0; k < 4; ++k) acc[i][j][k] = 0.f;
        }
#pragma unroll
        for (int ph = 0; ph < 2; ++ph) {
            const int h = mx * 2 + ph;
            if (h < 7) asm volatile("cp.async.wait_group 1;");
            else       asm volatile("cp.async.wait_group 0;");
            __syncthreads();
            if (mx == 0) compute(out0, h);
            else         compute(acc, h);
            __syncthreads();
            if (h + 2 < 8) load_stage(h + 2);
        }
        if (mx == 1) {
#pragma unroll
            for (int i = 0; i < 2; ++i)
#pragma unroll
                for (int j = 0; j < 8; ++j)
#pragma unroll
                    for (int k = 0; k < 4; ++k) { out0[i][j][k] += acc[i][j][k]; out1[i][j][k] += acc[i][j][k]; }
        } else if (mx == 2) {
#pragma unroll
            for (int i = 0; i < 2; ++i)
#pragma unroll
                for (int j = 0; j < 8; ++j)
#pragma unroll
                    for (int k = 0; k < 4; ++k) { out0[i][j][k] += acc[i][j][k]; out1[i][j][k] -= acc[i][j][k]; }
        } else if (mx == 3) {
#pragma unroll
            for (int i = 0; i < 2; ++i)
#pragma unroll
                for (int j = 0; j < 8; ++j)
#pragma unroll
                    for (int k = 0; k < 4; ++k) { out1[i][j][k] -= acc[i][j][k]; }
        }
    }

#pragma unroll
    for (int mt = 0; mt < 2; ++mt) {
#pragma unroll
        for (int half = 0; half < 2; ++half) {
            const int r = wm * 32 + mt * 16 + (lane >> 2) + half * 8;
            float* dst0 = d_V + ((size_t)(mzmy * 2 + 0) * NT + tile0 + r) * 128;
            float* dst1 = d_V + ((size_t)(mzmy * 2 + 1) * NT + tile0 + r) * 128;
#pragma unroll
            for (int nt = 0; nt < 8; ++nt) {
                const int n0 = wn * 64 + nt * 8 + (lane & 3) * 2;
                *(float2*)(dst0 + n0) = make_float2(out0[mt][nt][half * 2 + 0], out0[mt][nt][half * 2 + 1]);
                *(float2*)(dst1 + n0) = make_float2(out1[mt][nt][half * 2 + 0], out1[mt][nt][half * 2 + 1]);
            }
        }
    }
}

// ---------------- Winograd y,z output transform + bias + relu -> d_y2 ----------------
__global__ void __launch_bounds__(128) wino_out_kernel(const float* __restrict__ b0) {
    const int t = blockIdx.x;
    const int c = threadIdx.x;
    const int zt = t / 576, yt = (t / 24) % 24, xt = t % 24;
    const float* src = d_V + (size_t)t * 128 + c;
    float v[4][4][2];
#pragma unroll
    for (int mz = 0; mz < 4; ++mz)
#pragma unroll
        for (int my = 0; my < 4; ++my)
#pragma unroll
            for (int xs = 0; xs < 2; ++xs)
                v[mz][my][xs] = __ldg(src + (size_t)((mz * 4 + my) * 2 + xs) * NT * 128);
    float w[4][2][2];
#pragma unroll
    for (int mz = 0; mz < 4; ++mz)
#pragma unroll
        for (int xs = 0; xs < 2; ++xs) {
            w[mz][0][xs] = v[mz][0][xs] + v[mz][1][xs] + v[mz][2][xs];
            w[mz][1][xs] = v[mz][1][xs] - v[mz][2][xs] - v[mz][3][xs];
        }
    const float bias = __ldg(b0 + c);
#pragma unroll
    for (int py = 0; py < 2; ++py)
#pragma unroll
        for (int xs = 0; xs < 2; ++xs) {
            float o0 = w[0][py][xs] + w[1][py][xs] + w[2][py][xs];
            float o1 = w[1][py][xs] - w[2][py][xs] - w[3][py][xs];
            const int vz0 = (zt * 2) * HW + (yt * 2 + py) * 48 + xt * 2 + xs;
            d_y2[(size_t)vz0 * 128 + c] = fmaxf(o0 + bias, 0.f);
            d_y2[(size_t)(vz0 + HW) * 128 + c] = fmaxf(o1 + bias, 0.f);
        }
}

// ---------------- InstanceNorm stats: partials [c][blk], parallel finalize ----------------
__global__ void __launch_bounds__(128) stats_part_kernel() {
    const int blk = blockIdx.x;       // 432
    const int c = threadIdx.x;
    const float* p = d_y2 + (size_t)blk * 256 * 128 + c;
    float s = 0.f, s2 = 0.f;
#pragma unroll 4
    for (int i = 0; i < 256; ++i) {
        float v = p[(size_t)i * 128];
        s += v; s2 += v * v;
    }
    d_sp[c * 432 + blk] = s;
    d_sp[55296 + c * 432 + blk] = s2;
}
__global__ void __launch_bounds__(128) stats_fin_kernel() {
    const int c = blockIdx.x;         // 128
    const int tid = threadIdx.x;
    float S = 0.f, S2 = 0.f;
    for (int b = tid; b < 432; b += 128) {
        S  += d_sp[c * 432 + b];
        S2 += d_sp[55296 + c * 432 + b];
    }
    __shared__ float rs[128], rs2[128];
    rs[tid] = S; rs2[tid] = S2;
    __syncthreads();
    for (int o = 64; o > 0; o >>= 1) {
        if (tid < o) { rs[tid] += rs[tid + o]; rs2[tid] += rs2[tid + o]; }
        __syncthreads();
    }
    if (tid == 0) {
        float mean = rs[0] * (1.0f / (float)DHW);
        float var  = rs2[0] * (1.0f / (float)DHW) - mean * mean;
        d_mean[c] = mean;
        d_rstd[c] = rsqrtf(var + 1e-5f);
    }
}

// ---------------- keypoint sampling: pre-swizzled split-bf16 B + norms ----------------
__global__ void __launch_bounds__(128) sample_kernel(const float* __restrict__ kpts) {
    const int n = blockIdx.x;
    const int c = threadIdx.x;
    __shared__ float pt[3];
    if (c < 3) pt[c] = kpts[n * 3 + c];
    __syncthreads();
    const float ix = (pt[0] + 1.0f) * 0.5f * 47.0f;
    const float iy = (pt[1] + 1.0f) * 0.5f * 47.0f;
    const float iz = (pt[2] + 1.0f) * 0.5f * 47.0f;
    const float x0f = floorf(ix), y0f = floorf(iy), z0f = floorf(iz);
    const float wx = ix - x0f, wy = iy - y0f, wz = iz - z0f;
    int x0 = min(max((int)x0f, 0), 47);
    int y0 = min(max((int)y0f, 0), 47);
    int z0 = min(max((int)z0f, 0), 47);
    int x1 = min(x0 + 1, 47), y1 = min(y0 + 1, 47), z1 = min(z0 + 1, 47);
    const float* vol = d_y2 + c;
    float c000 = vol[(size_t)(z0*HW + y0*48 + x0) * 128], c001 = vol[(size_t)(z0*HW + y0*48 + x1) * 128];
    float c010 = vol[(size_t)(z0*HW + y1*48 + x0) * 128], c011 = vol[(size_t)(z0*HW + y1*48 + x1) * 128];
    float c100 = vol[(size_t)(z1*HW + y0*48 + x0) * 128], c101 = vol[(size_t)(z1*HW + y0*48 + x1) * 128];
    float c110 = vol[(size_t)(z1*HW + y1*48 + x0) * 128], c111 = vol[(size_t)(z1*HW + y1*48 + x1) * 128];
    float v = c000*((1-wz)*(1-wy)*(1-wx)) + c001*((1-wz)*(1-wy)*wx)
            + c010*((1-wz)*wy*(1-wx))     + c011*((1-wz)*wy*wx)
            + c100*(wz*(1-wy)*(1-wx))     + c101*(wz*(1-wy)*wx)
            + c110*(wz*wy*(1-wx))         + c111*(wz*wy*wx);
    float f = (v - d_mean[c]) * d_rstd[c];

    float b = 2.0f * LOG2E * f;
    __nv_bfloat16 bh = __float2bfloat16(b);
    __nv_bfloat16 bl = __float2bfloat16(b - __bfloat162float(bh));
    const int chunk = n >> 5, row = n & 31;
    const int u = (c & 63) >> 3, j = c & 7, ph = c >> 6;
    char* fb = (char*)d_fkb;
    size_t base = (size_t)chunk * 24576 + (size_t)row * 128 + ((u ^ (row & 7)) << 4) + j * 2;
    *(__nv_bfloat16*)(fb + base + (0 + ph) * 4096) = bh;
    *(__nv_bfloat16*)(fb + base + (2 + ph) * 4096) = bh;
    *(__nv_bfloat16*)(fb + base + (4 + ph) * 4096) = bl;

    __shared__ float red[128];
    red[c] = f * f;
    __syncthreads();
    for (int o = 64; o > 0; o >>= 1) {
        if (c < o) red[c] += red[c + o];
        __syncthreads();
    }
    if (c == 0) d_nn[n] = LOG2E * red[0];
}

// ---------------- softmax interpolation via mma.sync: 128 voxels/CTA, 256 thr ----------------
#define SMX_A    0
#define SMX_B    98304
#define SMX_NN   147456
#define SMX_DSM  149504
#define SMX_MEAN 157696
#define SMX_RSTD 158208
#define SMX_TOTAL 158720

__global__ void __launch_bounds__(256, 1) softmax_mma_kernel(const float* __restrict__ disp,
                                                             float* __restrict__ out) {
    extern __shared__ char sm[];
    const uint32_t sb = smem_u32(sm);
    const int tid = threadIdx.x;
    const int g0 = blockIdx.x * 128;

    float* nns = (float*)(sm + SMX_NN);
    float4* dsm4 = (float4*)(sm + SMX_DSM);
    for (int i = tid; i < NK; i += 256) {
        nns[i] = d_nn[i];
        float4 dv;
        dv.x = disp[i * 3]; dv.y = disp[i * 3 + 1]; dv.z = disp[i * 3 + 2]; dv.w = 0.f;
        dsm4[i] = dv;
    }
    ((float*)(sm + SMX_MEAN))[tid & 127] = d_mean[tid & 127];
    ((float*)(sm + SMX_RSTD))[tid & 127] = d_rstd[tid & 127];

    {
        const char* src = (const char*)d_fkb;
        for (int i = tid; i < 1536; i += 256) cp16(sb + SMX_B + i * 16, src + (size_t)i * 16);
        cp_commit();
    }
    __syncthreads();

    {
        const float* mean = (const float*)(sm + SMX_MEAN);
        const float* rstd = (const float*)(sm + SMX_RSTD);
        const int g = tid & 127, half = tid >> 7;
#pragma unroll
        for (int oct = 0; oct < 8; ++oct) {
            const int c0 = half * 64 + oct * 8;
            const float* srcp = d_y2 + (size_t)(g0 + g) * 128 + c0;
            float4 fa = *(const float4*)srcp;
            float4 fb4 = *(const float4*)(srcp + 4);
            float vv[8] = {fa.x, fa.y, fa.z, fa.w, fb4.x, fb4.y, fb4.z, fb4.w};
            union { __nv_bfloat16 h[8]; float4 v; } H, L;
#pragma unroll
            for (int j = 0; j < 8; ++j) {
                float a = (vv[j] - mean[c0 + j]) * rstd[c0 + j];
                __nv_bfloat16 hh = __float2bfloat16(a);
                H.h[j] = hh;
                L.h[j] = __float2bfloat16(a - __bfloat162float(hh));
            }
            const uint32_t sw = (uint32_t)((oct ^ (g & 7)) << 4);
            char* basep = sm + SMX_A + g * 128 + sw;
            *(float4*)(basep + (0 + half) * 16384) = H.v;
            *(float4*)(basep + (4 + half) * 16384) = H.v;
            *(float4*)(basep + (2 + half) * 16384) = L.v;
        }
    }
    __syncthreads();

    const int wid = tid >> 5, lane = tid & 31;
    const int rA = wid * 16 + (lane & 15);
    const int uA = lane >> 4;
    const int rB0 = ((lane >> 4) << 3) + (lane & 7);
    const int uBb = (lane >> 3) & 1;

    float mlo = -1e30f, mhi = -1e30f;
    float Slo = 0.f, Shi = 0.f;
    float Wlo0 = 0.f, Wlo1 = 0.f, Wlo2 = 0.f;
    float Whi0 = 0.f, Whi1 = 0.f, Whi2 = 0.f;

    for (int ci = 0; ci < 16; ++ci) {
        asm volatile("cp.async.wait_group 0;");
        __syncthreads();
        if (ci < 15) {
            const char* src = (const char*)d_fkb + (size_t)(ci + 1) * 24576;
            const uint32_t dst = sb + SMX_B + ((ci + 1) & 1) * 24576;
            for (int i = tid; i < 1536; i += 256) cp16(dst + i * 16, src + (size_t)i * 16);
            cp_commit();
        }
        const uint32_t Bb = sb + SMX_B + (ci & 1) * 24576;
        const int nbase = ci * 32;

        float acc[4][4];
#pragma unroll
        for (int nt = 0; nt < 4; ++nt) {
            float i0 = -nns[nbase + nt * 8 + (lane & 3) * 2];
            float i1 = -nns[nbase + nt * 8 + (lane & 3) * 2 + 1];
            acc[nt][0] = i0; acc[nt][1] = i1; acc[nt][2] = i0; acc[nt][3] = i1;
        }
#pragma unroll
        for (int s = 0; s < 24; ++s) {
            const int pan = s >> 2, inner = s & 3;
            uint32_t a[4];
            ldsm4(sb + SMX_A + pan * 16384 + rA * 128 + (((inner * 2 + uA) ^ (rA & 7)) << 4),
                  a[0], a[1], a[2], a[3]);
            uint32_t b4[2][4];
#pragma unroll
            for (int bt = 0; bt < 2; ++bt) {
                const int row = bt * 16 + rB0;
                ldsm4(Bb + pan * 4096 + row * 128 + (((inner * 2 + uBb) ^ (row & 7)) << 4),
                      b4[bt][0], b4[bt][1], b4[bt][2], b4[bt][3]);
            }
#pragma unroll
            for (int nt = 0; nt < 4; ++nt)
                mma16816(acc[nt], a, b4[nt >> 1][(nt & 1) * 2], b4[nt >> 1][(nt & 1) * 2 + 1]);
        }

        float cmlo = fmaxf(fmaxf(fmaxf(acc[0][0], acc[0][1]), fmaxf(acc[1][0], acc[1][1])),
                           fmaxf(fmaxf(acc[2][0], acc[2][1]), fmaxf(acc[3][0], acc[3][1])));
        float cmhi = fmaxf(fmaxf(fmaxf(acc[0][2], acc[0][3]), fmaxf(acc[1][2], acc[1][3])),
                           fmaxf(fmaxf(acc[2][2], acc[2][3]), fmaxf(acc[3][2], acc[3][3])));
        cmlo = fmaxf(cmlo, __shfl_xor_sync(0xffffffffu, cmlo, 1));
        cmlo = fmaxf(cmlo, __shfl_xor_sync(0xffffffffu, cmlo, 2));
        cmhi = fmaxf(cmhi, __shfl_xor_sync(0xffffffffu, cmhi, 1));
        cmhi = fmaxf(cmhi, __shfl_xor_sync(0xffffffffu, cmhi, 2));
        if (cmlo > mlo) {
            float cs = exp2a(mlo - cmlo);
            Slo *= cs; Wlo0 *= cs; Wlo1 *= cs; Wlo2 *= cs;
            mlo = cmlo;
        }
        if (cmhi > mhi) {
            float cs = exp2a(mhi - cmhi);
            Shi *= cs; Whi0 *= cs; Whi1 *= cs; Whi2 *= cs;
            mhi = cmhi;
        }
#pragma unroll
        for (int nt = 0; nt < 4; ++nt) {
#pragma unroll
            for (int j = 0; j < 2; ++j) {
                const float4 dv = dsm4[nbase + nt * 8 + (lane & 3) * 2 + j];
                float elo = exp2a(acc[nt][j] - mlo);
                float ehi = exp2a(acc[nt][2 + j] - mhi);
                Slo += elo; Shi += ehi;
                Wlo0 = fmaf(elo, dv.x, Wlo0); Wlo1 = fmaf(elo, dv.y, Wlo1); Wlo2 = fmaf(elo, dv.z, Wlo2);
                Whi0 = fmaf(ehi, dv.x, Whi0); Whi1 = fmaf(ehi, dv.y, Whi1); Whi2 = fmaf(ehi, dv.z, Whi2);
            }
        }
    }

#pragma unroll
    for (int d = 1; d <= 2; d <<= 1) {
        Slo += __shfl_xor_sync(0xffffffffu, Slo, d);
        Shi += __shfl_xor_sync(0xffffffffu, Shi, d);
        Wlo0 += __shfl_xor_sync(0xffffffffu, Wlo0, d);
        Wlo1 += __shfl_xor_sync(0xffffffffu, Wlo1, d);
        Wlo2 += __shfl_xor_sync(0xffffffffu, Wlo2, d);
        Whi0 += __shfl_xor_sync(0xffffffffu, Whi0, d);
        Whi1 += __shfl_xor_sync(0xffffffffu, Whi1, d);
        Whi2 += __shfl_xor_sync(0xffffffffu, Whi2, d);
    }
    if ((lane & 3) == 0) {
        const int rlo = g0 + wid * 16 + (lane >> 2);
        const int rhi = rlo + 8;
        const float ilo = 1.0f / Slo, ihi = 1.0f / Shi;
        out[0 * DHW + rlo] = Wlo0 * ilo;
        out[1 * DHW + rlo] = Wlo1 * ilo;
        out[2 * DHW + rlo] = Wlo2 * ilo;
        out[0 * DHW + rhi] = Whi0 * ihi;
        out[1 * DHW + rhi] = Whi1 * ihi;
        out[2 * DHW + rhi] = Whi2 * ihi;
    }
}

// ---------------- launch ----------------
extern "C" void kernel_launch(void* const* d_in, const int* in_sizes, int n_in,
                              void* d_out, int out_size) {
    const float* kpts  = (const float*)d_in[0];
    const float* disp  = (const float*)d_in[1];
    const float* feats = (const float*)d_in[2];
    const float* W0    = (const float*)d_in[3];
    const float* b0    = (const float*)d_in[4];
    float* out = (float*)d_out;

    static int attr_done = 0;
    if (!attr_done) {
        cudaFuncSetAttribute(wino_gemm_kernel, cudaFuncAttributeMaxDynamicSharedMemorySize, CONV_SMEM);
        cudaFuncSetAttribute(softmax_mma_kernel, cudaFuncAttributeMaxDynamicSharedMemorySize, SMX_TOTAL);
        attr_done = 1;
    }

    pad_kernel<<<2500, 256>>>(feats);
    wino_w_kernel<<<8192, 128>>>(W0);
    wino_in_kernel<<<1728, 128>>>();
    wino_gemm_kernel<<<dim3(216, 16), 128, CONV_SMEM>>>();
    wino_out_kernel<<<NT, 128>>>(b0);
    stats_part_kernel<<<432, 128>>>();
    stats_fin_kernel<<<128, 128>>>();
    sample_kernel<<<NK, 128>>>(kpts);
    softmax_mma_kernel<<<DHW / 128, 256, SMX_TOTAL>>>(disp, out);
}

// round 17
// speedup vs baseline: 1.2884x; 1.1283x over previous
#include <cuda_runtime.h>
#include <cuda_bf16.h>
#include <cstdint>

#define DD   48
#define HW   2304
#define DHW  110592
#define NK   512
#define LOG2E 1.4426950408889634f
#define NT   13824            // 24^3 Winograd tiles
#define NMU  64

// ---------------- device scratch ----------------
__device__ float d_xp[50 * 50 * 50 * 128];                          // padded input, voxel-major
__device__ __align__(16) __nv_bfloat16 d_wA[(size_t)NMU * NT * 256]; // transformed input [mu][tile][hi128|lo128]
__device__ __align__(16) __nv_bfloat16 d_wu[NMU * 128 * 256];        // transformed weights [mu][co][bhi128|blo128]
__device__ float d_V[(size_t)32 * NT * 128];                         // x-folded GEMM out [mzmy*2+xs][tile][co]
__device__ float d_y2[(size_t)DHW * 128];                            // conv out voxel-major [voxel][c]
__device__ __align__(16) __nv_bfloat16 d_fkb[16 * 8192];             // keypoint feats [chunk16][bh p0|bh p1|bl p0|bl p1]
__device__ float d_sp[128 * 432 * 2];                                // stats partials [c][blk] (sum | sumsq)
__device__ float d_mean[128];
__device__ float d_rstd[128];
__device__ float d_nn[NK];

__device__ __forceinline__ float exp2a(float x) {
    float r; asm("ex2.approx.ftz.f32 %0, %1;" : "=f"(r) : "f"(x)); return r;
}
__device__ __forceinline__ uint32_t smem_u32(const void* p) {
    uint32_t a;
    asm("{ .reg .u64 t; cvta.to.shared.u64 t, %1; cvt.u32.u64 %0, t; }" : "=r"(a) : "l"(p));
    return a;
}
__device__ __forceinline__ void cp16(uint32_t dst, const void* src) {
    asm volatile("cp.async.cg.shared.global [%0], [%1], 16;" :: "r"(dst), "l"(src));
}
__device__ __forceinline__ void cp_commit() { asm volatile("cp.async.commit_group;"); }
__device__ __forceinline__ void ldsm4(uint32_t addr, uint32_t& r0, uint32_t& r1, uint32_t& r2, uint32_t& r3) {
    asm volatile("ldmatrix.sync.aligned.m8n8.x4.shared.b16 {%0,%1,%2,%3}, [%4];"
                 : "=r"(r0), "=r"(r1), "=r"(r2), "=r"(r3) : "r"(addr));
}
__device__ __forceinline__ void mma16816(float* c, const uint32_t* a, uint32_t b0, uint32_t b1) {
    asm volatile("mma.sync.aligned.m16n8k16.row.col.f32.bf16.bf16.f32 "
                 "{%0,%1,%2,%3}, {%4,%5,%6,%7}, {%8,%9}, {%0,%1,%2,%3};"
                 : "+f"(c[0]), "+f"(c[1]), "+f"(c[2]), "+f"(c[3])
                 : "r"(a[0]), "r"(a[1]), "r"(a[2]), "r"(a[3]), "r"(b0), "r"(b1));
}

// ---------------- pad input to [zp50][yp50][xp50][c128] fp32, voxel-major ----------------
__global__ void __launch_bounds__(256) pad_kernel(const float* __restrict__ feats) {
    __shared__ float tb[50][129];
    const int r = blockIdx.x;               // 2500 (zp,yp) rows
    const int zp = r / 50, yp = r % 50;
    const int zi = zp - 1, yi = yp - 1;
    const int tid = threadIdx.x;
    const int x = tid & 63, cq = tid >> 6;
    const int xi = x - 1;
    const bool rowok = (zi >= 0 && zi < 48 && yi >= 0 && yi < 48);
    const bool xok = rowok && (xi >= 0 && xi < 48);
#pragma unroll 4
    for (int i = 0; i < 32; ++i) {
        int c = cq * 32 + i;
        float v = 0.f;
        if (xok) {
            if (c < 125)       v = feats[(size_t)c * DHW + zi * HW + yi * 48 + xi];
            else if (c == 125) v = (2.0f / 47.0f) * (float)xi - 1.0f;
            else if (c == 126) v = (2.0f / 47.0f) * (float)yi - 1.0f;
            else               v = (2.0f / 47.0f) * (float)zi - 1.0f;
        }
        if (x < 50) tb[x][c] = v;
    }
    __syncthreads();
    float* dst = d_xp + (size_t)r * 50 * 128;
    for (int i = tid; i < 1600; i += 256) {
        int xr = i >> 5, c4 = (i & 31) * 4;
        float4 val = make_float4(tb[xr][c4], tb[xr][c4 + 1], tb[xr][c4 + 2], tb[xr][c4 + 3]);
        *(float4*)(dst + xr * 128 + c4) = val;
    }
}

// ---------------- Winograd weight transform (separable, all 64 mus per thread) ----------------
__global__ void __launch_bounds__(128) wino_w_kernel(const float* __restrict__ W0) {
    const int co = blockIdx.x;       // 128
    const int ci = threadIdx.x;      // 128
    float w[27];
    const float* wp = W0 + (size_t)(co * 128 + ci) * 27;
#pragma unroll
    for (int k = 0; k < 27; ++k) w[k] = __ldg(wp + k);

    const float G[4][3] = {{1.f, 0.f, 0.f}, {0.5f, 0.5f, 0.5f}, {0.5f, -0.5f, 0.5f}, {0.f, 0.f, 1.f}};
    float t1[4][9];
#pragma unroll
    for (int mz = 0; mz < 4; ++mz)
#pragma unroll
        for (int j = 0; j < 9; ++j)
            t1[mz][j] = G[mz][0] * w[j] + G[mz][1] * w[9 + j] + G[mz][2] * w[18 + j];
    float t2[4][4][3];
#pragma unroll
    for (int mz = 0; mz < 4; ++mz)
#pragma unroll
        for (int my = 0; my < 4; ++my)
#pragma unroll
            for (int dx = 0; dx < 3; ++dx)
                t2[mz][my][dx] = G[my][0] * t1[mz][dx] + G[my][1] * t1[mz][3 + dx] + G[my][2] * t1[mz][6 + dx];
#pragma unroll
    for (int mz = 0; mz < 4; ++mz)
#pragma unroll
        for (int my = 0; my < 4; ++my)
#pragma unroll
            for (int mx = 0; mx < 4; ++mx) {
                const int mu = mz * 16 + my * 4 + mx;
                float u = G[mx][0] * t2[mz][my][0] + G[mx][1] * t2[mz][my][1] + G[mx][2] * t2[mz][my][2];
                __nv_bfloat16 hi = __float2bfloat16(u);
                __nv_bfloat16 lo = __float2bfloat16(u - __bfloat162float(hi));
                __nv_bfloat16* rrow = d_wu + ((size_t)mu * 128 + co) * 256;
                rrow[ci] = hi;
                rrow[128 + ci] = lo;
            }
}

// ---------------- Winograd input transform: 8 tiles per block, DIRECT coalesced stores ----------------
__global__ void __launch_bounds__(128) wino_in_kernel() {
    const int blk = blockIdx.x;              // 1728 = 24z * 12ypair * 6xg
    const int c = threadIdx.x;
    const int xg = blk % 6;
    const int yp = (blk / 6) % 12;
    const int zt = blk / 72;
    const int xt0 = xg * 4;
    const int yt0 = yp * 2;
    const float* base = d_xp + ((size_t)((zt * 2) * 50 + yt0 * 2) * 50 + xt0 * 2) * 128 + c;

    float w[4][6][4];
#pragma unroll
    for (int z = 0; z < 4; ++z)
#pragma unroll
        for (int y = 0; y < 6; ++y)
#pragma unroll
            for (int x = 0; x < 4; ++x)
                w[z][y][x] = __ldg(base + ((z * 50 + y) * 50 + x) * 128);

    for (int t = 0; t < 4; ++t) {
#pragma unroll
        for (int ty = 0; ty < 2; ++ty) {
            float d[4][4][4];
#pragma unroll
            for (int z = 0; z < 4; ++z)
#pragma unroll
                for (int y = 0; y < 4; ++y)
#pragma unroll
                    for (int x = 0; x < 4; ++x) d[z][y][x] = w[z][ty * 2 + y][x];
            // x-pass
#pragma unroll
            for (int z = 0; z < 4; ++z)
#pragma unroll
                for (int y = 0; y < 4; ++y) {
                    float a0 = d[z][y][0], a1 = d[z][y][1], a2 = d[z][y][2], a3 = d[z][y][3];
                    d[z][y][0] = a0 - a2; d[z][y][1] = a1 + a2; d[z][y][2] = a2 - a1; d[z][y][3] = a1 - a3;
                }
            // y-pass
#pragma unroll
            for (int z = 0; z < 4; ++z)
#pragma unroll
                for (int x = 0; x < 4; ++x) {
                    float a0 = d[z][0][x], a1 = d[z][1][x], a2 = d[z][2][x], a3 = d[z][3][x];
                    d[z][0][x] = a0 - a2; d[z][1][x] = a1 + a2; d[z][2][x] = a2 - a1; d[z][3][x] = a1 - a3;
                }
            // z-pass
#pragma unroll
            for (int y = 0; y < 4; ++y)
#pragma unroll
                for (int x = 0; x < 4; ++x) {
                    float a0 = d[0][y][x], a1 = d[1][y][x], a2 = d[2][y][x], a3 = d[3][y][x];
                    d[0][y][x] = a0 - a2; d[1][y][x] = a1 + a2; d[2][y][x] = a2 - a1; d[3][y][x] = a1 - a3;
                }
            const int tile = zt * 576 + (yt0 + ty) * 24 + xt0 + t;
            __nv_bfloat16* dptr = d_wA + (size_t)tile * 256 + c;
#pragma unroll
            for (int mz = 0; mz < 4; ++mz)
#pragma unroll
                for (int my = 0; my < 4; ++my)
#pragma unroll
                    for (int mx = 0; mx < 4; ++mx) {
                        const int mu = mz * 16 + my * 4 + mx;
                        float v = d[mz][my][mx];
                        __nv_bfloat16 hi = __float2bfloat16(v);
                        __nv_bfloat16 lo = __float2bfloat16(v - __bfloat162float(hi));
                        __nv_bfloat16* p = dptr + (size_t)mu * NT * 256;
                        p[0] = hi;
                        p[128] = lo;
                    }
        }
        if (t < 3) {
#pragma unroll
            for (int z = 0; z < 4; ++z)
#pragma unroll
                for (int y = 0; y < 6; ++y) {
                    w[z][y][0] = w[z][y][2];
                    w[z][y][1] = w[z][y][3];
                    w[z][y][2] = __ldg(base + ((z * 50 + y) * 50 + 2 * t + 4) * 128);
                    w[z][y][3] = __ldg(base + ((z * 50 + y) * 50 + 2 * t + 5) * 128);
                }
        }
    }
}

// ---------------- Winograd GEMM + x-direction output fold ----------------
#define STG 49152               // A 16KB + B 32KB
#define CONV_SMEM (2 * STG)     // 96 KB

__global__ void __launch_bounds__(128, 2) wino_gemm_kernel() {
    extern __shared__ char smem[];
    const uint32_t sb = smem_u32(smem);
    const int tid = threadIdx.x;
    const int tile0 = blockIdx.x * 64;     // 216 blocks
    const int mzmy = blockIdx.y;           // 16
    const int mu0 = mzmy * 4;

    auto load_stage = [&](int h) {
        const int mu = h >> 1, p = h & 1;
        const uint32_t ab = sb + (h & 1) * STG;
        const __nv_bfloat16* Abase = d_wA + ((size_t)(mu0 + mu) * NT + tile0) * 256;
        const __nv_bfloat16* Bbase = d_wu + (size_t)(mu0 + mu) * 32768;
#pragma unroll
        for (int i = 0; i < 8; ++i) {
            const int idx = i * 128 + tid;
            const int chunk = idx >> 9;
            const int row = (idx >> 3) & 63;
            const int u = idx & 7;
            cp16(ab + chunk * 8192 + row * 128 + ((u ^ (row & 7)) << 4),
                 Abase + (size_t)row * 256 + (p + 2 * chunk) * 64 + u * 8);
        }
#pragma unroll
        for (int i = 0; i < 16; ++i) {
            const int idx = i * 128 + tid;
            const int half = idx >> 10;
            const int row = (idx >> 3) & 127;
            const int u = idx & 7;
            cp16(ab + 16384 + half * 16384 + row * 128 + ((u ^ (row & 7)) << 4),
                 Bbase + (size_t)row * 256 + half * 128 + p * 64 + u * 8);
        }
        cp_commit();
    };

    load_stage(0);
    load_stage(1);

    const int wid = tid >> 5, lane = tid & 31;
    const int wm = wid >> 1, wn = wid & 1;
    const int rA = wm * 32 + (lane & 15);
    const int uA = lane >> 4;
    const int rB = wn * 64 + ((lane >> 4) << 3) + (lane & 7);
    const int uB = (lane >> 3) & 1;

    float acc[2][8][4], out0[2][8][4], out1[2][8][4];
#pragma unroll
    for (int i = 0; i < 2; ++i)
#pragma unroll
        for (int j = 0; j < 8; ++j)
#pragma unroll
            for (int k = 0; k < 4; ++k) { out0[i][j][k] = 0.f; out1[i][j][k] = 0.f; }

    auto compute = [&](float (&tgt)[2][8][4], int h) {
        const uint32_t Ahi = sb + (h & 1) * STG;
        const uint32_t Alo = Ahi + 8192;
        const uint32_t Bh  = Ahi + 16384;
        const uint32_t Bl  = Ahi + 32768;
#pragma unroll
        for (int k16 = 0; k16 < 4; ++k16) {
            uint32_t ah[2][4], al[2][4], bh[4][4], bl[4][4];
#pragma unroll
            for (int mt = 0; mt < 2; ++mt) {
                const int row = rA + mt * 16;
                const uint32_t off = row * 128 + (((k16 * 2 + uA) ^ (row & 7)) << 4);
                ldsm4(Ahi + off, ah[mt][0], ah[mt][1], ah[mt][2], ah[mt][3]);
                ldsm4(Alo + off, al[mt][0], al[mt][1], al[mt][2], al[mt][3]);
            }
#pragma unroll
            for (int bt = 0; bt < 4; ++bt) {
                const int row = rB + bt * 16;
                const uint32_t off = row * 128 + (((k16 * 2 + uB) ^ (row & 7)) << 4);
                ldsm4(Bh + off, bh[bt][0], bh[bt][1], bh[bt][2], bh[bt][3]);
                ldsm4(Bl + off, bl[bt][0], bl[bt][1], bl[bt][2], bl[bt][3]);
            }
#pragma unroll
            for (int mt = 0; mt < 2; ++mt)
#pragma unroll
                for (int nt = 0; nt < 8; ++nt) {
                    uint32_t h0 = bh[nt >> 1][(nt & 1) * 2], h1 = bh[nt >> 1][(nt & 1) * 2 + 1];
                    mma16816(tgt[mt][nt], ah[mt], h0, h1);
                    mma16816(tgt[mt][nt], al[mt], h0, h1);
                    mma16816(tgt[mt][nt], ah[mt], bl[nt >> 1][(nt & 1) * 2], bl[nt >> 1][(nt & 1) * 2 + 1]);
                }
        }
    };

#pragma unroll
    for (int mx = 0; mx < 4; ++mx) {
        if (mx > 0) {
#pragma unroll
            for (int i = 0; i < 2; ++i)
#pragma unroll
                for (int j = 0; j < 8; ++j)
#pragma unroll
                    for (int k = 0; k < 4; ++k) acc[i][j][k] = 0.f;
        }
#pragma unroll
        for (int ph = 0; ph < 2; ++ph) {
            const int h = mx * 2 + ph;
            if (h < 7) asm volatile("cp.async.wait_group 1;");
            else       asm volatile("cp.async.wait_group 0;");
            __syncthreads();
            if (mx == 0) compute(out0, h);
            else         compute(acc, h);
            __syncthreads();
            if (h + 2 < 8) load_stage(h + 2);
        }
        if (mx == 1) {
#pragma unroll
            for (int i = 0; i < 2; ++i)
#pragma unroll
                for (int j = 0; j < 8; ++j)
#pragma unroll
                    for (int k = 0; k < 4; ++k) { out0[i][j][k] += acc[i][j][k]; out1[i][j][k] += acc[i][j][k]; }
        } else if (mx == 2) {
#pragma unroll
            for (int i = 0; i < 2; ++i)
#pragma unroll
                for (int j = 0; j < 8; ++j)
#pragma unroll
                    for (int k = 0; k < 4; ++k) { out0[i][j][k] += acc[i][j][k]; out1[i][j][k] -= acc[i][j][k]; }
        } else if (mx == 3) {
#pragma unroll
            for (int i = 0; i < 2; ++i)
#pragma unroll
                for (int j = 0; j < 8; ++j)
#pragma unroll
                    for (int k = 0; k < 4; ++k) { out1[i][j][k] -= acc[i][j][k]; }
        }
    }

#pragma unroll
    for (int mt = 0; mt < 2; ++mt) {
#pragma unroll
        for (int half = 0; half < 2; ++half) {
            const int r = wm * 32 + mt * 16 + (lane >> 2) + half * 8;
            float* dst0 = d_V + ((size_t)(mzmy * 2 + 0) * NT + tile0 + r) * 128;
            float* dst1 = d_V + ((size_t)(mzmy * 2 + 1) * NT + tile0 + r) * 128;
#pragma unroll
            for (int nt = 0; nt < 8; ++nt) {
                const int n0 = wn * 64 + nt * 8 + (lane & 3) * 2;
                *(float2*)(dst0 + n0) = make_float2(out0[mt][nt][half * 2 + 0], out0[mt][nt][half * 2 + 1]);
                *(float2*)(dst1 + n0) = make_float2(out1[mt][nt][half * 2 + 0], out1[mt][nt][half * 2 + 1]);
            }
        }
    }
}

// ---------------- Winograd y,z output transform + bias + relu -> d_y2 ----------------
__global__ void __launch_bounds__(128) wino_out_kernel(const float* __restrict__ b0) {
    const int t = blockIdx.x;
    const int c = threadIdx.x;
    const int zt = t / 576, yt = (t / 24) % 24, xt = t % 24;
    const float* src = d_V + (size_t)t * 128 + c;
    float v[4][4][2];
#pragma unroll
    for (int mz = 0; mz < 4; ++mz)
#pragma unroll
        for (int my = 0; my < 4; ++my)
#pragma unroll
            for (int xs = 0; xs < 2; ++xs)
                v[mz][my][xs] = __ldg(src + (size_t)((mz * 4 + my) * 2 + xs) * NT * 128);
    float w[4][2][2];
#pragma unroll
    for (int mz = 0; mz < 4; ++mz)
#pragma unroll
        for (int xs = 0; xs < 2; ++xs) {
            w[mz][0][xs] = v[mz][0][xs] + v[mz][1][xs] + v[mz][2][xs];
            w[mz][1][xs] = v[mz][1][xs] - v[mz][2][xs] - v[mz][3][xs];
        }
    const float bias = __ldg(b0 + c);
#pragma unroll
    for (int py = 0; py < 2; ++py)
#pragma unroll
        for (int xs = 0; xs < 2; ++xs) {
            float o0 = w[0][py][xs] + w[1][py][xs] + w[2][py][xs];
            float o1 = w[1][py][xs] - w[2][py][xs] - w[3][py][xs];
            const int vz0 = (zt * 2) * HW + (yt * 2 + py) * 48 + xt * 2 + xs;
            d_y2[(size_t)vz0 * 128 + c] = fmaxf(o0 + bias, 0.f);
            d_y2[(size_t)(vz0 + HW) * 128 + c] = fmaxf(o1 + bias, 0.f);
        }
}

// ---------------- InstanceNorm stats: partials [c][blk], parallel finalize ----------------
__global__ void __launch_bounds__(128) stats_part_kernel() {
    const int blk = blockIdx.x;       // 432
    const int c = threadIdx.x;
    const float* p = d_y2 + (size_t)blk * 256 * 128 + c;
    float s = 0.f, s2 = 0.f;
#pragma unroll 4
    for (int i = 0; i < 256; ++i) {
        float v = p[(size_t)i * 128];
        s += v; s2 += v * v;
    }
    d_sp[c * 432 + blk] = s;
    d_sp[55296 + c * 432 + blk] = s2;
}
__global__ void __launch_bounds__(128) stats_fin_kernel() {
    const int c = blockIdx.x;         // 128
    const int tid = threadIdx.x;
    float S = 0.f, S2 = 0.f;
    for (int b = tid; b < 432; b += 128) {
        S  += d_sp[c * 432 + b];
        S2 += d_sp[55296 + c * 432 + b];
    }
    __shared__ float rs[128], rs2[128];
    rs[tid] = S; rs2[tid] = S2;
    __syncthreads();
    for (int o = 64; o > 0; o >>= 1) {
        if (tid < o) { rs[tid] += rs[tid + o]; rs2[tid] += rs2[tid + o]; }
        __syncthreads();
    }
    if (tid == 0) {
        float mean = rs[0] * (1.0f / (float)DHW);
        float var  = rs2[0] * (1.0f / (float)DHW) - mean * mean;
        d_mean[c] = mean;
        d_rstd[c] = rsqrtf(var + 1e-5f);
    }
}

// ---------------- keypoint sampling: split-bf16 B [bh p0|bh p1|bl p0|bl p1] + norms ----------------
__global__ void __launch_bounds__(128) sample_kernel(const float* __restrict__ kpts) {
    const int n = blockIdx.x;
    const int c = threadIdx.x;
    __shared__ float pt[3];
    if (c < 3) pt[c] = kpts[n * 3 + c];
    __syncthreads();
    const float ix = (pt[0] + 1.0f) * 0.5f * 47.0f;
    const float iy = (pt[1] + 1.0f) * 0.5f * 47.0f;
    const float iz = (pt[2] + 1.0f) * 0.5f * 47.0f;
    const float x0f = floorf(ix), y0f = floorf(iy), z0f = floorf(iz);
    const float wx = ix - x0f, wy = iy - y0f, wz = iz - z0f;
    int x0 = min(max((int)x0f, 0), 47);
    int y0 = min(max((int)y0f, 0), 47);
    int z0 = min(max((int)z0f, 0), 47);
    int x1 = min(x0 + 1, 47), y1 = min(y0 + 1, 47), z1 = min(z0 + 1, 47);
    const float* vol = d_y2 + c;
    float c000 = vol[(size_t)(z0*HW + y0*48 + x0) * 128], c001 = vol[(size_t)(z0*HW + y0*48 + x1) * 128];
    float c010 = vol[(size_t)(z0*HW + y1*48 + x0) * 128], c011 = vol[(size_t)(z0*HW + y1*48 + x1) * 128];
    float c100 = vol[(size_t)(z1*HW + y0*48 + x0) * 128], c101 = vol[(size_t)(z1*HW + y0*48 + x1) * 128];
    float c110 = vol[(size_t)(z1*HW + y1*48 + x0) * 128], c111 = vol[(size_t)(z1*HW + y1*48 + x1) * 128];
    float v = c000*((1-wz)*(1-wy)*(1-wx)) + c001*((1-wz)*(1-wy)*wx)
            + c010*((1-wz)*wy*(1-wx))     + c011*((1-wz)*wy*wx)
            + c100*(wz*(1-wy)*(1-wx))     + c101*(wz*(1-wy)*wx)
            + c110*(wz*wy*(1-wx))         + c111*(wz*wy*wx);
    float f = (v - d_mean[c]) * d_rstd[c];

    float b = 2.0f * LOG2E * f;
    __nv_bfloat16 bh = __float2bfloat16(b);
    __nv_bfloat16 bl = __float2bfloat16(b - __bfloat162float(bh));
    const int chunk = n >> 5, row = n & 31;
    const int u = (c & 63) >> 3, j = c & 7, ph = c >> 6;
    char* fb = (char*)d_fkb;
    size_t base = (size_t)chunk * 16384 + (size_t)row * 128 + ((u ^ (row & 7)) << 4) + j * 2;
    *(__nv_bfloat16*)(fb + base + (0 + ph) * 4096) = bh;
    *(__nv_bfloat16*)(fb + base + (2 + ph) * 4096) = bl;

    __shared__ float red[128];
    red[c] = f * f;
    __syncthreads();
    for (int o = 64; o > 0; o >>= 1) {
        if (c < o) red[c] += red[c + o];
        __syncthreads();
    }
    if (c == 0) d_nn[n] = LOG2E * red[0];
}

// ---------------- softmax via mma.sync: 128 voxels/CTA, fused-split, 2 CTA/SM ----------------
#define SMX_A    0              // 4 panels x 16384: [H p0][H p1][L p0][L p1]
#define SMX_B    65536          // 2 x 16384
#define SMX_NN   98304
#define SMX_DSM  100352
#define SMX_MEAN 108544
#define SMX_RSTD 109056
#define SMX_TOTAL 109568

__global__ void __launch_bounds__(256, 2) softmax_mma_kernel(const float* __restrict__ disp,
                                                             float* __restrict__ out) {
    extern __shared__ char sm[];
    const uint32_t sb = smem_u32(sm);
    const int tid = threadIdx.x;
    const int g0 = blockIdx.x * 128;

    float* nns = (float*)(sm + SMX_NN);
    float4* dsm4 = (float4*)(sm + SMX_DSM);
    for (int i = tid; i < NK; i += 256) {
        nns[i] = d_nn[i];
        float4 dv;
        dv.x = disp[i * 3]; dv.y = disp[i * 3 + 1]; dv.z = disp[i * 3 + 2]; dv.w = 0.f;
        dsm4[i] = dv;
    }
    ((float*)(sm + SMX_MEAN))[tid & 127] = d_mean[tid & 127];
    ((float*)(sm + SMX_RSTD))[tid & 127] = d_rstd[tid & 127];

    {
        const char* src = (const char*)d_fkb;
        for (int i = tid; i < 1024; i += 256) cp16(sb + SMX_B + i * 16, src + (size_t)i * 16);
        cp_commit();
    }
    __syncthreads();

    {
        const float* mean = (const float*)(sm + SMX_MEAN);
        const float* rstd = (const float*)(sm + SMX_RSTD);
        const int g = tid & 127, half = tid >> 7;
#pragma unroll
        for (int oct = 0; oct < 8; ++oct) {
            const int c0 = half * 64 + oct * 8;
            const float* srcp = d_y2 + (size_t)(g0 + g) * 128 + c0;
            float4 fa = *(const float4*)srcp;
            float4 fb4 = *(const float4*)(srcp + 4);
            float vv[8] = {fa.x, fa.y, fa.z, fa.w, fb4.x, fb4.y, fb4.z, fb4.w};
            union { __nv_bfloat16 h[8]; float4 v; } H, L;
#pragma unroll
            for (int j = 0; j < 8; ++j) {
                float a = (vv[j] - mean[c0 + j]) * rstd[c0 + j];
                __nv_bfloat16 hh = __float2bfloat16(a);
                H.h[j] = hh;
                L.h[j] = __float2bfloat16(a - __bfloat162float(hh));
            }
            const uint32_t sw = (uint32_t)((oct ^ (g & 7)) << 4);
            char* basep = sm + SMX_A + g * 128 + sw;
            *(float4*)(basep + (0 + half) * 16384) = H.v;
            *(float4*)(basep + (2 + half) * 16384) = L.v;
        }
    }
    __syncthreads();

    const int wid = tid >> 5, lane = tid & 31;
    const int rA = wid * 16 + (lane & 15);
    const int uA = lane >> 4;
    const int rB0 = ((lane >> 4) << 3) + (lane & 7);
    const int uBb = (lane >> 3) & 1;

    float mlo = -1e30f, mhi = -1e30f;
    float Slo = 0.f, Shi = 0.f;
    float Wlo0 = 0.f, Wlo1 = 0.f, Wlo2 = 0.f;
    float Whi0 = 0.f, Whi1 = 0.f, Whi2 = 0.f;

    for (int ci = 0; ci < 16; ++ci) {
        asm volatile("cp.async.wait_group 0;");
        __syncthreads();
        if (ci < 15) {
            const char* src = (const char*)d_fkb + (size_t)(ci + 1) * 16384;
            const uint32_t dst = sb + SMX_B + ((ci + 1) & 1) * 16384;
            for (int i = tid; i < 1024; i += 256) cp16(dst + i * 16, src + (size_t)i * 16);
            cp_commit();
        }
        const uint32_t Bb = sb + SMX_B + (ci & 1) * 16384;
        const int nbase = ci * 32;

        float acc[4][4];
#pragma unroll
        for (int nt = 0; nt < 4; ++nt) {
            float i0 = -nns[nbase + nt * 8 + (lane & 3) * 2];
            float i1 = -nns[nbase + nt * 8 + (lane & 3) * 2 + 1];
            acc[nt][0] = i0; acc[nt][1] = i1; acc[nt][2] = i0; acc[nt][3] = i1;
        }
#pragma unroll
        for (int p = 0; p < 2; ++p) {
#pragma unroll
            for (int inner = 0; inner < 4; ++inner) {
                uint32_t a_h[4], a_l[4], b_h[2][4], b_l[2][4];
                const uint32_t Aoff = rA * 128 + (((inner * 2 + uA) ^ (rA & 7)) << 4);
                ldsm4(sb + SMX_A + p * 16384 + Aoff, a_h[0], a_h[1], a_h[2], a_h[3]);
                ldsm4(sb + SMX_A + (2 + p) * 16384 + Aoff, a_l[0], a_l[1], a_l[2], a_l[3]);
#pragma unroll
                for (int bt = 0; bt < 2; ++bt) {
                    const int row = bt * 16 + rB0;
                    const uint32_t Boff = row * 128 + (((inner * 2 + uBb) ^ (row & 7)) << 4);
                    ldsm4(Bb + p * 4096 + Boff, b_h[bt][0], b_h[bt][1], b_h[bt][2], b_h[bt][3]);
                    ldsm4(Bb + (2 + p) * 4096 + Boff, b_l[bt][0], b_l[bt][1], b_l[bt][2], b_l[bt][3]);
                }
#pragma unroll
                for (int nt = 0; nt < 4; ++nt) {
                    uint32_t h0 = b_h[nt >> 1][(nt & 1) * 2], h1 = b_h[nt >> 1][(nt & 1) * 2 + 1];
                    mma16816(acc[nt], a_h, h0, h1);
                    mma16816(acc[nt], a_l, h0, h1);
                    mma16816(acc[nt], a_h, b_l[nt >> 1][(nt & 1) * 2], b_l[nt >> 1][(nt & 1) * 2 + 1]);
                }
            }
        }

        float cmlo = fmaxf(fmaxf(fmaxf(acc[0][0], acc[0][1]), fmaxf(acc[1][0], acc[1][1])),
                           fmaxf(fmaxf(acc[2][0], acc[2][1]), fmaxf(acc[3][0], acc[3][1])));
        float cmhi = fmaxf(fmaxf(fmaxf(acc[0][2], acc[0][3]), fmaxf(acc[1][2], acc[1][3])),
                           fmaxf(fmaxf(acc[2][2], acc[2][3]), fmaxf(acc[3][2], acc[3][3])));
        cmlo = fmaxf(cmlo, __shfl_xor_sync(0xffffffffu, cmlo, 1));
        cmlo = fmaxf(cmlo, __shfl_xor_sync(0xffffffffu, cmlo, 2));
        cmhi = fmaxf(cmhi, __shfl_xor_sync(0xffffffffu, cmhi, 1));
        cmhi = fmaxf(cmhi, __shfl_xor_sync(0xffffffffu, cmhi, 2));
        if (cmlo > mlo) {
            float cs = exp2a(mlo - cmlo);
            Slo *= cs; Wlo0 *= cs; Wlo1 *= cs; Wlo2 *= cs;
            mlo = cmlo;
        }
        if (cmhi > mhi) {
            float cs = exp2a(mhi - cmhi);
            Shi *= cs; Whi0 *= cs; Whi1 *= cs; Whi2 *= cs;
            mhi = cmhi;
        }
#pragma unroll
        for (int nt = 0; nt < 4; ++nt) {
#pragma unroll
            for (int j = 0; j < 2; ++j) {
                const float4 dv = dsm4[nbase + nt * 8 + (lane & 3) * 2 + j];
                float elo = exp2a(acc[nt][j] - mlo);
                float ehi = exp2a(acc[nt][2 + j] - mhi);
                Slo += elo; Shi += ehi;
                Wlo0 = fmaf(elo, dv.x, Wlo0); Wlo1 = fmaf(elo, dv.y, Wlo1); Wlo2 = fmaf(elo, dv.z, Wlo2);
                Whi0 = fmaf(ehi, dv.x, Whi0); Whi1 = fmaf(ehi, dv.y, Whi1); Whi2 = fmaf(ehi, dv.z, Whi2);
            }
        }
    }

#pragma unroll
    for (int d = 1; d <= 2; d <<= 1) {
        Slo += __shfl_xor_sync(0xffffffffu, Slo, d);
        Shi += __shfl_xor_sync(0xffffffffu, Shi, d);
        Wlo0 += __shfl_xor_sync(0xffffffffu, Wlo0, d);
        Wlo1 += __shfl_xor_sync(0xffffffffu, Wlo1, d);
        Wlo2 += __shfl_xor_sync(0xffffffffu, Wlo2, d);
        Whi0 += __shfl_xor_sync(0xffffffffu, Whi0, d);
        Whi1 += __shfl_xor_sync(0xffffffffu, Whi1, d);
        Whi2 += __shfl_xor_sync(0xffffffffu, Whi2, d);
    }
    if ((lane & 3) == 0) {
        const int rlo = g0 + wid * 16 + (lane >> 2);
        const int rhi = rlo + 8;
        const float ilo = 1.0f / Slo, ihi = 1.0f / Shi;
        out[0 * DHW + rlo] = Wlo0 * ilo;
        out[1 * DHW + rlo] = Wlo1 * ilo;
        out[2 * DHW + rlo] = Wlo2 * ilo;
        out[0 * DHW + rhi] = Whi0 * ihi;
        out[1 * DHW + rhi] = Whi1 * ihi;
        out[2 * DHW + rhi] = Whi2 * ihi;
    }
}

// ---------------- launch ----------------
extern "C" void kernel_launch(void* const* d_in, const int* in_sizes, int n_in,
                              void* d_out, int out_size) {
    const float* kpts  = (const float*)d_in[0];
    const float* disp  = (const float*)d_in[1];
    const float* feats = (const float*)d_in[2];
    const float* W0    = (const float*)d_in[3];
    const float* b0    = (const float*)d_in[4];
    float* out = (float*)d_out;

    static int attr_done = 0;
    if (!attr_done) {
        cudaFuncSetAttribute(wino_gemm_kernel, cudaFuncAttributeMaxDynamicSharedMemorySize, CONV_SMEM);
        cudaFuncSetAttribute(softmax_mma_kernel, cudaFuncAttributeMaxDynamicSharedMemorySize, SMX_TOTAL);
        attr_done = 1;
    }

    pad_kernel<<<2500, 256>>>(feats);
    wino_w_kernel<<<128, 128>>>(W0);
    wino_in_kernel<<<1728, 128>>>();
    wino_gemm_kernel<<<dim3(216, 16), 128, CONV_SMEM>>>();
    wino_out_kernel<<<NT, 128>>>(b0);
    stats_part_kernel<<<432, 128>>>();
    stats_fin_kernel<<<128, 128>>>();
    sample_kernel<<<NK, 128>>>(kpts);
    softmax_mma_kernel<<<DHW / 128, 256, SMX_TOTAL>>>(disp, out);
}